// round 1
// baseline (speedup 1.0000x reference)
#include <cuda_runtime.h>
#include <math.h>

// ---------------- problem constants ----------------
#define BB      64
#define TT      20
#define SS      10
#define LL      20
#define HH      128
#define H3      384
#define NITEMS  50000
#define CURROWS (BB*TT)          // 1280
#define FRDROWS (BB*SS*LL)       // 12800
#define NROWS   (CURROWS+FRDROWS) // 14080
#define NSEQ    (BB + BB*SS)     // 704 sequences, each length 20
#define SEQPB   5                // sequences per GRU block -> 141 blocks (1 wave)

// ---------------- scratch (static device memory; no allocations) ----------------
__device__ float g_x[NROWS*HH];        // gathered embeddings (cur rows 0..1279, frd rows 1280..)
__device__ float g_gi[NROWS*H3];       // x @ W_ih^T + b_ih
__device__ float g_hs[NROWS*HH];       // GRU outputs for all (seq,t)
__device__ float g_simraw[BB*SS*TT];
__device__ float g_sim1[BB*SS*TT];
__device__ int   g_pres[BB*SS];
__device__ float g_sess[BB*SS*HH];
__device__ float g_acat[CURROWS*256];  // [hs | hf] per (b,t) row

// ---------------- 1. gather v_emb[indices] ----------------
__global__ void k_gather(const int* __restrict__ cur, const int* __restrict__ frd,
                         const float* __restrict__ vemb) {
    int t = blockIdx.x * blockDim.x + threadIdx.x;
    if (t >= NROWS*HH) return;
    int row = t >> 7, col = t & 127;
    int item = (row < CURROWS) ? cur[row] : frd[row - CURROWS];
    g_x[t] = vemb[(size_t)item * HH + col];
}

// ---------------- 2. GI GEMM: [14080,128] @ W_ih^T -> [14080,384] (+b_ih) ----------------
// BM=64 BN=128 BK=32, 256 threads, 4x8 strided micro-tiles
__global__ void k_gi_gemm(const float* __restrict__ Wih, const float* __restrict__ bih) {
    __shared__ float As[64][33];
    __shared__ float Bs[32][128];
    int tid = threadIdx.x, tx = tid & 15, ty = tid >> 4;
    int m0 = blockIdx.y << 6, n0 = blockIdx.x << 7;
    float acc[4][8];
#pragma unroll
    for (int u = 0; u < 4; u++)
#pragma unroll
        for (int v = 0; v < 8; v++) acc[u][v] = 0.f;

    for (int kt = 0; kt < 4; kt++) {
        int k0 = kt << 5;
        // A tile: 64x32 = 512 float4
#pragma unroll
        for (int q = 0; q < 2; q++) {
            int i4 = tid * 2 + q;
            int m = i4 >> 3, kq = i4 & 7;
            float4 v = *(const float4*)(&g_x[(size_t)(m0+m)*HH + k0 + kq*4]);
            As[m][kq*4+0] = v.x; As[m][kq*4+1] = v.y; As[m][kq*4+2] = v.z; As[m][kq*4+3] = v.w;
        }
        // B tile: 128x32 = 1024 float4 ; B[k][n] = Wih[n*128 + k]
#pragma unroll
        for (int q = 0; q < 4; q++) {
            int i4 = tid * 4 + q;
            int n = i4 >> 3, kq = i4 & 7;
            float4 v = *(const float4*)(&Wih[(size_t)(n0+n)*HH + k0 + kq*4]);
            Bs[kq*4+0][n] = v.x; Bs[kq*4+1][n] = v.y; Bs[kq*4+2][n] = v.z; Bs[kq*4+3][n] = v.w;
        }
        __syncthreads();
#pragma unroll
        for (int k = 0; k < 32; k++) {
            float a[4], bb[8];
#pragma unroll
            for (int u = 0; u < 4; u++) a[u] = As[u*16+ty][k];
#pragma unroll
            for (int v = 0; v < 8; v++) bb[v] = Bs[k][v*16+tx];
#pragma unroll
            for (int u = 0; u < 4; u++)
#pragma unroll
                for (int v = 0; v < 8; v++) acc[u][v] += a[u]*bb[v];
        }
        __syncthreads();
    }
#pragma unroll
    for (int u = 0; u < 4; u++) {
        int m = m0 + u*16 + ty;
#pragma unroll
        for (int v = 0; v < 8; v++) {
            int n = n0 + v*16 + tx;
            g_gi[(size_t)m*H3 + n] = acc[u][v] + bih[n];
        }
    }
}

// ---------------- 3. GRU recurrence (704 seqs x 20 steps), W_hh in shared ----------------
__global__ void k_gru(const float* __restrict__ Whh, const float* __restrict__ bhh) {
    extern __shared__ float sm[];
    float* Wsh  = sm;                    // [384][132]
    float* hsh  = sm + 384*132;          // [5][128]
    float* ghsh = hsh + SEQPB*128;       // [5][384]
    int tid = threadIdx.x;               // 384 threads
    for (int idx = tid; idx < 384*128; idx += 384) {
        int j = idx >> 7, k = idx & 127;
        Wsh[j*132 + k] = Whh[idx];
    }
    int seq0 = blockIdx.x * SEQPB;
    int nseq = NSEQ - seq0; if (nseq > SEQPB) nseq = SEQPB;
    for (int idx = tid; idx < SEQPB*128; idx += 384) hsh[idx] = 0.f;
    __syncthreads();

    int j = tid;
    float bh = bhh[j];
    const float4* w4 = (const float4*)(Wsh + j*132);

    for (int t = 0; t < 20; t++) {
        // phase 1: gh[i][j] = b_hh[j] + h[i,:] . W_hh[j,:]
        float acc[SEQPB];
#pragma unroll
        for (int i = 0; i < SEQPB; i++) acc[i] = bh;
#pragma unroll 8
        for (int kq = 0; kq < 32; kq++) {
            float4 w = w4[kq];
#pragma unroll
            for (int i = 0; i < SEQPB; i++) {
                float4 h = *(const float4*)(&hsh[i*128 + kq*4]);
                acc[i] += w.x*h.x + w.y*h.y + w.z*h.z + w.w*h.w;
            }
        }
#pragma unroll
        for (int i = 0; i < SEQPB; i++) ghsh[i*H3 + j] = acc[i];
        __syncthreads();
        // phase 2: gates + h update
        for (int idx = tid; idx < nseq*128; idx += 384) {
            int i = idx >> 7, jj = idx & 127;
            size_t row = (size_t)(seq0 + i) * 20 + t;
            const float* gir = g_gi + row * H3;
            float r = 1.f / (1.f + expf(-(gir[jj]       + ghsh[i*H3 + jj])));
            float z = 1.f / (1.f + expf(-(gir[128 + jj] + ghsh[i*H3 + 128 + jj])));
            float n = tanhf(gir[256 + jj] + r * ghsh[i*H3 + 256 + jj]);
            float hprev = hsh[i*128 + jj];
            float h = (1.f - z) * n + z * hprev;
            hsh[i*128 + jj] = h;
            g_hs[row*HH + jj] = h;
        }
        __syncthreads();
    }
}

// ---------------- 4. scores + max_l + preserve-init ----------------
__global__ void k_scores() {
    __shared__ float Qt[HH*TT];  // [k][t]
    __shared__ float Et[HH*LL];  // [k][l]
    __shared__ float Sc[TT*LL];
    int bs = blockIdx.x;                 // b*10+s
    int b  = bs / SS;
    int tid = threadIdx.x;               // 256
    const float* qsrc = g_hs + (size_t)(b*TT) * HH;
    const float* esrc = g_hs + (size_t)(CURROWS + bs*LL) * HH;
    for (int i = tid; i < TT*HH; i += 256) {
        int tt = i >> 7, k = i & 127;
        Qt[k*TT + tt] = qsrc[i];
        Et[k*LL + tt] = esrc[i];
    }
    __syncthreads();
    for (int p = tid; p < TT*LL; p += 256) {
        int t = p / LL, l = p % LL;
        float acc = 0.f;
#pragma unroll 8
        for (int k = 0; k < HH; k++) acc += Qt[k*TT + t] * Et[k*LL + l];
        Sc[t*LL + l] = acc;
    }
    __syncthreads();
    if (tid < TT) {
        float mx = -INFINITY;
        for (int l = 0; l < LL; l++) mx = fmaxf(mx, Sc[tid*LL + l]);
        g_simraw[(size_t)bs*TT + tid] = mx;
    }
    if (tid == 0) g_pres[bs] = 0;
}

// ---------------- 5. softmax over s + top-2 -> preserve ----------------
__global__ void k_smax_topk() {
    int gid = blockIdx.x * 256 + threadIdx.x;
    if (gid >= BB*TT) return;
    int b = gid / TT, t = gid % TT;
    float v[SS];
    float mx = -INFINITY;
#pragma unroll
    for (int s = 0; s < SS; s++) { v[s] = g_simraw[(b*SS+s)*TT + t]; mx = fmaxf(mx, v[s]); }
    float sum = 0.f;
#pragma unroll
    for (int s = 0; s < SS; s++) { v[s] = expf(v[s]-mx); sum += v[s]; }
    float inv = 1.f / sum;
#pragma unroll
    for (int s = 0; s < SS; s++) { v[s] *= inv; g_sim1[(b*SS+s)*TT + t] = v[s]; }
    int i1 = 0; float b1 = v[0];
#pragma unroll
    for (int s = 1; s < SS; s++) if (v[s] > b1) { b1 = v[s]; i1 = s; }
    int i2 = -1; float b2 = -INFINITY;
#pragma unroll
    for (int s = 0; s < SS; s++) if (s != i1 && v[s] > b2) { b2 = v[s]; i2 = s; }
    atomicOr(&g_pres[b*SS + i1], 1);
    atomicOr(&g_pres[b*SS + i2], 1);
}

// ---------------- 6. friend-session attention: w + sess_emb ----------------
__global__ void k_wsess(const int* __restrict__ users, const float* __restrict__ uemb) {
    __shared__ float ue[HH];
    __shared__ float d[LL];
    __shared__ float wsm[LL];
    int bs = blockIdx.x;         // b*10+s
    int b = bs / SS;
    int tid = threadIdx.x;       // 128
    ue[tid] = uemb[(size_t)users[b]*HH + tid];
    __syncthreads();
    const float* F = g_x + (size_t)(CURROWS + bs*LL) * HH;
    int lane = tid & 31, w = tid >> 5;
    for (int l = w*5; l < w*5 + 5; l++) {
        float p = 0.f;
#pragma unroll
        for (int k = lane; k < HH; k += 32) p += ue[k] * F[(size_t)l*HH + k];
#pragma unroll
        for (int off = 16; off > 0; off >>= 1) p += __shfl_down_sync(0xffffffff, p, off);
        if (lane == 0) d[l] = p;
    }
    __syncthreads();
    if (tid == 0) {
        float mx = -INFINITY;
        for (int l = 0; l < LL; l++) mx = fmaxf(mx, d[l]);
        float sum = 0.f;
        for (int l = 0; l < LL; l++) { wsm[l] = expf(d[l]-mx); sum += wsm[l]; }
        float inv = 1.f / sum;
        for (int l = 0; l < LL; l++) wsm[l] *= inv;
    }
    __syncthreads();
    float acc = 0.f;
#pragma unroll
    for (int l = 0; l < LL; l++) acc += wsm[l] * F[(size_t)l*HH + tid];
    g_sess[(size_t)bs*HH + tid] = acc;
}

// ---------------- 7. double masked softmax + hf + build [hs|hf] ----------------
__global__ void k_hf_acat() {
    __shared__ float sfin[SS];
    int row = blockIdx.x;        // b*20+t
    int b = row / TT, t = row % TT;
    int tid = threadIdx.x;       // 128
    if (tid == 0) {
        float v[SS], p[SS]; int m[SS];
        for (int s = 0; s < SS; s++) { m[s] = g_pres[b*SS+s]; v[s] = g_sim1[(b*SS+s)*TT + t]; }
        float mx = -INFINITY;
        for (int s = 0; s < SS; s++) if (m[s]) mx = fmaxf(mx, v[s]);
        float sum = 0.f;
        for (int s = 0; s < SS; s++) { p[s] = m[s] ? expf(v[s]-mx) : 0.f; sum += p[s]; }
        float inv = 1.f / sum;
        for (int s = 0; s < SS; s++) p[s] *= inv;
        mx = -INFINITY;
        for (int s = 0; s < SS; s++) if (m[s]) mx = fmaxf(mx, p[s]);
        sum = 0.f;
        float q[SS];
        for (int s = 0; s < SS; s++) { q[s] = m[s] ? expf(p[s]-mx) : 0.f; sum += q[s]; }
        inv = 1.f / sum;
        for (int s = 0; s < SS; s++) sfin[s] = m[s] ? q[s]*inv : 0.f;
    }
    __syncthreads();
    float acc = 0.f;
#pragma unroll
    for (int s = 0; s < SS; s++) acc += sfin[s] * g_sess[(size_t)(b*SS+s)*HH + tid];
    g_acat[(size_t)row*256 + tid]       = g_hs[(size_t)row*HH + tid]; // cur rows == row
    g_acat[(size_t)row*256 + 128 + tid] = acc;
}

// ---------------- 8. logits GEMM: [1280,256] @ Wp^T + b -> [1280,50000] ----------------
// Wp[n][k] = out1_w[n][k] for k<128, out1_w[n][128+k] for k>=128 (hu block skipped)
__global__ void k_out_gemm(const float* __restrict__ Wo, const float* __restrict__ bo,
                           float* __restrict__ out) {
    __shared__ float As[64][33];
    __shared__ float Bs[32][128];
    int tid = threadIdx.x, tx = tid & 15, ty = tid >> 4;
    int m0 = blockIdx.y << 6, n0 = blockIdx.x << 7;
    float acc[4][8];
#pragma unroll
    for (int u = 0; u < 4; u++)
#pragma unroll
        for (int v = 0; v < 8; v++) acc[u][v] = 0.f;

    for (int kt = 0; kt < 8; kt++) {
        int k0 = kt << 5;
        int ks = (k0 < 128) ? k0 : (k0 + 128);
#pragma unroll
        for (int q = 0; q < 2; q++) {
            int i4 = tid * 2 + q;
            int m = i4 >> 3, kq = i4 & 7;
            float4 v = *(const float4*)(&g_acat[(size_t)(m0+m)*256 + k0 + kq*4]);
            As[m][kq*4+0] = v.x; As[m][kq*4+1] = v.y; As[m][kq*4+2] = v.z; As[m][kq*4+3] = v.w;
        }
#pragma unroll
        for (int q = 0; q < 4; q++) {
            int i4 = tid * 4 + q;
            int n = i4 >> 3, kq = i4 & 7;
            float4 v = make_float4(0.f, 0.f, 0.f, 0.f);
            if (n0 + n < NITEMS)
                v = *(const float4*)(&Wo[(size_t)(n0+n)*H3 + ks + kq*4]);
            Bs[kq*4+0][n] = v.x; Bs[kq*4+1][n] = v.y; Bs[kq*4+2][n] = v.z; Bs[kq*4+3][n] = v.w;
        }
        __syncthreads();
#pragma unroll
        for (int k = 0; k < 32; k++) {
            float a[4], bb[8];
#pragma unroll
            for (int u = 0; u < 4; u++) a[u] = As[u*16+ty][k];
#pragma unroll
            for (int v = 0; v < 8; v++) bb[v] = Bs[k][v*16+tx];
#pragma unroll
            for (int u = 0; u < 4; u++)
#pragma unroll
                for (int v = 0; v < 8; v++) acc[u][v] += a[u]*bb[v];
        }
        __syncthreads();
    }
#pragma unroll
    for (int u = 0; u < 4; u++) {
        int m = m0 + u*16 + ty;
#pragma unroll
        for (int v = 0; v < 8; v++) {
            int n = n0 + v*16 + tx;
            if (n < NITEMS)
                out[(size_t)m*NITEMS + n] = acc[u][v] + bo[n];
        }
    }
}

// ---------------- launch ----------------
extern "C" void kernel_launch(void* const* d_in, const int* in_sizes, int n_in,
                              void* d_out, int out_size) {
    (void)in_sizes; (void)n_in; (void)out_size;
    const int*   users = (const int*)d_in[0];
    const int*   cur   = (const int*)d_in[1];
    // d_in[2] = hist_sess (unused by reference)
    const int*   frds  = (const int*)d_in[3];
    // d_in[4] = cur_sess_len (always T)
    const float* vemb  = (const float*)d_in[5];
    const float* uemb  = (const float*)d_in[6];
    const float* Wih   = (const float*)d_in[7];
    const float* Whh   = (const float*)d_in[8];
    const float* bih   = (const float*)d_in[9];
    const float* bhh   = (const float*)d_in[10];
    const float* Wo    = (const float*)d_in[11];
    const float* bo    = (const float*)d_in[12];
    float* out = (float*)d_out;

    k_gather<<<(NROWS*HH)/256, 256>>>(cur, frds, vemb);

    dim3 ggi(H3/128, NROWS/64);
    k_gi_gemm<<<ggi, 256>>>(Wih, bih);

    const int gru_smem = (384*132 + SEQPB*128 + SEQPB*H3) * (int)sizeof(float); // 212992
    cudaFuncSetAttribute(k_gru, cudaFuncAttributeMaxDynamicSharedMemorySize, gru_smem);
    k_gru<<<(NSEQ + SEQPB - 1)/SEQPB, 384, gru_smem>>>(Whh, bhh);

    k_scores<<<BB*SS, 256>>>();
    k_smax_topk<<<(BB*TT + 255)/256, 256>>>();
    k_wsess<<<BB*SS, 128>>>(users, uemb);
    k_hf_acat<<<BB*TT, 128>>>();

    dim3 go((NITEMS + 127)/128, CURROWS/64);
    k_out_gemm<<<go, 256>>>(Wo, bo, out);
}

// round 4
// speedup vs baseline: 1.9522x; 1.9522x over previous
#include <cuda_runtime.h>
#include <cuda_bf16.h>
#include <math.h>
#include <stdint.h>

// ---------------- problem constants ----------------
#define BB      64
#define TT      20
#define SS      10
#define LL      20
#define HH      128
#define H3      384
#define NITEMS  50000
#define CURROWS (BB*TT)          // 1280
#define FRDROWS (BB*SS*LL)       // 12800
#define NROWS   (CURROWS+FRDROWS) // 14080
#define NSEQ    (BB + BB*SS)     // 704 sequences, each length 20
#define SEQPB   5                // sequences per GRU block -> 141 blocks (1 wave)

// ---------------- scratch (static device memory; no allocations) ----------------
__device__ float g_x[NROWS*HH];
__device__ float g_gi[NROWS*H3];
__device__ float g_hs[NROWS*HH];
__device__ float g_simraw[BB*SS*TT];
__device__ float g_sim1[BB*SS*TT];
__device__ int   g_pres[BB*SS];
__device__ float g_sess[BB*SS*HH];
__device__ float g_acat[CURROWS*256];
// bf16 split planes for tensor-core logit GEMM
__device__ __align__(16) __nv_bfloat16 g_ahi[CURROWS*256];
__device__ __align__(16) __nv_bfloat16 g_alo[CURROWS*256];
__device__ __align__(16) __nv_bfloat16 g_whi[(size_t)NITEMS*256];
__device__ __align__(16) __nv_bfloat16 g_wlo[(size_t)NITEMS*256];

// ---------------- helpers ----------------
__device__ __forceinline__ uint32_t smem_u32(const void* p) {
    uint32_t a;
    asm("{ .reg .u64 t; cvta.to.shared.u64 t, %1; cvt.u32.u64 %0, t; }" : "=r"(a) : "l"(p));
    return a;
}
#define SWZ(off) ((off) ^ (((off) >> 3) & 0x70))

__device__ __forceinline__ void ldsm4(uint32_t& r0, uint32_t& r1, uint32_t& r2, uint32_t& r3,
                                      uint32_t addr) {
    asm volatile("ldmatrix.sync.aligned.m8n8.x4.shared.b16 {%0,%1,%2,%3}, [%4];"
                 : "=r"(r0), "=r"(r1), "=r"(r2), "=r"(r3) : "r"(addr));
}
__device__ __forceinline__ void mma16816(float* c, const uint32_t* a, uint32_t b0, uint32_t b1) {
    asm volatile("mma.sync.aligned.m16n8k16.row.col.f32.bf16.bf16.f32 "
                 "{%0,%1,%2,%3}, {%4,%5,%6,%7}, {%8,%9}, {%0,%1,%2,%3};"
                 : "+f"(c[0]), "+f"(c[1]), "+f"(c[2]), "+f"(c[3])
                 : "r"(a[0]), "r"(a[1]), "r"(a[2]), "r"(a[3]), "r"(b0), "r"(b1));
}
__device__ __forceinline__ void cpasync16(uint32_t dst, const void* src) {
    asm volatile("cp.async.cg.shared.global [%0], [%1], 16;" :: "r"(dst), "l"(src));
}
#define CP_COMMIT() asm volatile("cp.async.commit_group;" ::: "memory")
#define CP_WAIT1()  asm volatile("cp.async.wait_group 1;" ::: "memory")
#define CP_WAIT0()  asm volatile("cp.async.wait_group 0;" ::: "memory")

// ---------------- 1. gather v_emb[indices] ----------------
__global__ void k_gather(const int* __restrict__ cur, const int* __restrict__ frd,
                         const float* __restrict__ vemb) {
    int t = blockIdx.x * blockDim.x + threadIdx.x;
    if (t >= NROWS*HH) return;
    int row = t >> 7, col = t & 127;
    int item = (row < CURROWS) ? cur[row] : frd[row - CURROWS];
    g_x[t] = vemb[(size_t)item * HH + col];
}

// ---------------- 2. GI GEMM: [14080,128] @ W_ih^T -> [14080,384] (+b_ih) ----------------
__global__ void k_gi_gemm(const float* __restrict__ Wih, const float* __restrict__ bih) {
    __shared__ float As[64][33];
    __shared__ float Bs[32][128];
    int tid = threadIdx.x, tx = tid & 15, ty = tid >> 4;
    int m0 = blockIdx.y << 6, n0 = blockIdx.x << 7;
    float acc[4][8];
#pragma unroll
    for (int u = 0; u < 4; u++)
#pragma unroll
        for (int v = 0; v < 8; v++) acc[u][v] = 0.f;

    for (int kt = 0; kt < 4; kt++) {
        int k0 = kt << 5;
#pragma unroll
        for (int q = 0; q < 2; q++) {
            int i4 = tid * 2 + q;
            int m = i4 >> 3, kq = i4 & 7;
            float4 v = *(const float4*)(&g_x[(size_t)(m0+m)*HH + k0 + kq*4]);
            As[m][kq*4+0] = v.x; As[m][kq*4+1] = v.y; As[m][kq*4+2] = v.z; As[m][kq*4+3] = v.w;
        }
#pragma unroll
        for (int q = 0; q < 4; q++) {
            int i4 = tid * 4 + q;
            int n = i4 >> 3, kq = i4 & 7;
            float4 v = *(const float4*)(&Wih[(size_t)(n0+n)*HH + k0 + kq*4]);
            Bs[kq*4+0][n] = v.x; Bs[kq*4+1][n] = v.y; Bs[kq*4+2][n] = v.z; Bs[kq*4+3][n] = v.w;
        }
        __syncthreads();
#pragma unroll
        for (int k = 0; k < 32; k++) {
            float a[4], bb[8];
#pragma unroll
            for (int u = 0; u < 4; u++) a[u] = As[u*16+ty][k];
#pragma unroll
            for (int v = 0; v < 8; v++) bb[v] = Bs[k][v*16+tx];
#pragma unroll
            for (int u = 0; u < 4; u++)
#pragma unroll
                for (int v = 0; v < 8; v++) acc[u][v] += a[u]*bb[v];
        }
        __syncthreads();
    }
#pragma unroll
    for (int u = 0; u < 4; u++) {
        int m = m0 + u*16 + ty;
#pragma unroll
        for (int v = 0; v < 8; v++) {
            int n = n0 + v*16 + tx;
            g_gi[(size_t)m*H3 + n] = acc[u][v] + bih[n];
        }
    }
}

// ---------------- 3. GRU recurrence ----------------
__global__ void k_gru(const float* __restrict__ Whh, const float* __restrict__ bhh) {
    extern __shared__ float sm[];
    float* Wsh  = sm;                    // [384][132]
    float* hsh  = sm + 384*132;          // [5][128]
    float* ghsh = hsh + SEQPB*128;       // [5][384]
    int tid = threadIdx.x;               // 384 threads
    for (int idx = tid; idx < 384*128; idx += 384) {
        int j = idx >> 7, k = idx & 127;
        Wsh[j*132 + k] = Whh[idx];
    }
    int seq0 = blockIdx.x * SEQPB;
    int nseq = NSEQ - seq0; if (nseq > SEQPB) nseq = SEQPB;
    for (int idx = tid; idx < SEQPB*128; idx += 384) hsh[idx] = 0.f;
    __syncthreads();

    int j = tid;
    float bh = bhh[j];
    const float4* w4 = (const float4*)(Wsh + j*132);

    for (int t = 0; t < 20; t++) {
        float acc[SEQPB];
#pragma unroll
        for (int i = 0; i < SEQPB; i++) acc[i] = bh;
#pragma unroll 8
        for (int kq = 0; kq < 32; kq++) {
            float4 w = w4[kq];
#pragma unroll
            for (int i = 0; i < SEQPB; i++) {
                float4 h = *(const float4*)(&hsh[i*128 + kq*4]);
                acc[i] += w.x*h.x + w.y*h.y + w.z*h.z + w.w*h.w;
            }
        }
#pragma unroll
        for (int i = 0; i < SEQPB; i++) ghsh[i*H3 + j] = acc[i];
        __syncthreads();
        for (int idx = tid; idx < nseq*128; idx += 384) {
            int i = idx >> 7, jj = idx & 127;
            size_t row = (size_t)(seq0 + i) * 20 + t;
            const float* gir = g_gi + row * H3;
            float r = 1.f / (1.f + expf(-(gir[jj]       + ghsh[i*H3 + jj])));
            float z = 1.f / (1.f + expf(-(gir[128 + jj] + ghsh[i*H3 + 128 + jj])));
            float n = tanhf(gir[256 + jj] + r * ghsh[i*H3 + 256 + jj]);
            float hprev = hsh[i*128 + jj];
            float h = (1.f - z) * n + z * hprev;
            hsh[i*128 + jj] = h;
            g_hs[row*HH + jj] = h;
        }
        __syncthreads();
    }
}

// ---------------- 4. scores + max_l ----------------
__global__ void k_scores() {
    __shared__ float Qt[HH*TT];
    __shared__ float Et[HH*LL];
    __shared__ float Sc[TT*LL];
    int bs = blockIdx.x;
    int b  = bs / SS;
    int tid = threadIdx.x;
    const float* qsrc = g_hs + (size_t)(b*TT) * HH;
    const float* esrc = g_hs + (size_t)(CURROWS + bs*LL) * HH;
    for (int i = tid; i < TT*HH; i += 256) {
        int tt = i >> 7, k = i & 127;
        Qt[k*TT + tt] = qsrc[i];
        Et[k*LL + tt] = esrc[i];
    }
    __syncthreads();
    for (int p = tid; p < TT*LL; p += 256) {
        int t = p / LL, l = p % LL;
        float acc = 0.f;
#pragma unroll 8
        for (int k = 0; k < HH; k++) acc += Qt[k*TT + t] * Et[k*LL + l];
        Sc[t*LL + l] = acc;
    }
    __syncthreads();
    if (tid < TT) {
        float mx = -INFINITY;
        for (int l = 0; l < LL; l++) mx = fmaxf(mx, Sc[tid*LL + l]);
        g_simraw[(size_t)bs*TT + tid] = mx;
    }
    if (tid == 0) g_pres[bs] = 0;
}

// ---------------- 5. softmax over s + top-2 ----------------
__global__ void k_smax_topk() {
    int gid = blockIdx.x * 256 + threadIdx.x;
    if (gid >= BB*TT) return;
    int b = gid / TT, t = gid % TT;
    float v[SS];
    float mx = -INFINITY;
#pragma unroll
    for (int s = 0; s < SS; s++) { v[s] = g_simraw[(b*SS+s)*TT + t]; mx = fmaxf(mx, v[s]); }
    float sum = 0.f;
#pragma unroll
    for (int s = 0; s < SS; s++) { v[s] = expf(v[s]-mx); sum += v[s]; }
    float inv = 1.f / sum;
#pragma unroll
    for (int s = 0; s < SS; s++) { v[s] *= inv; g_sim1[(b*SS+s)*TT + t] = v[s]; }
    int i1 = 0; float b1 = v[0];
#pragma unroll
    for (int s = 1; s < SS; s++) if (v[s] > b1) { b1 = v[s]; i1 = s; }
    int i2 = -1; float b2 = -INFINITY;
#pragma unroll
    for (int s = 0; s < SS; s++) if (s != i1 && v[s] > b2) { b2 = v[s]; i2 = s; }
    atomicOr(&g_pres[b*SS + i1], 1);
    atomicOr(&g_pres[b*SS + i2], 1);
}

// ---------------- 6. friend-session attention ----------------
__global__ void k_wsess(const int* __restrict__ users, const float* __restrict__ uemb) {
    __shared__ float ue[HH];
    __shared__ float d[LL];
    __shared__ float wsm[LL];
    int bs = blockIdx.x;
    int b = bs / SS;
    int tid = threadIdx.x;
    ue[tid] = uemb[(size_t)users[b]*HH + tid];
    __syncthreads();
    const float* F = g_x + (size_t)(CURROWS + bs*LL) * HH;
    int lane = tid & 31, w = tid >> 5;
    for (int l = w*5; l < w*5 + 5; l++) {
        float p = 0.f;
#pragma unroll
        for (int k = lane; k < HH; k += 32) p += ue[k] * F[(size_t)l*HH + k];
#pragma unroll
        for (int off = 16; off > 0; off >>= 1) p += __shfl_down_sync(0xffffffff, p, off);
        if (lane == 0) d[l] = p;
    }
    __syncthreads();
    if (tid == 0) {
        float mx = -INFINITY;
        for (int l = 0; l < LL; l++) mx = fmaxf(mx, d[l]);
        float sum = 0.f;
        for (int l = 0; l < LL; l++) { wsm[l] = expf(d[l]-mx); sum += wsm[l]; }
        float inv = 1.f / sum;
        for (int l = 0; l < LL; l++) wsm[l] *= inv;
    }
    __syncthreads();
    float acc = 0.f;
#pragma unroll
    for (int l = 0; l < LL; l++) acc += wsm[l] * F[(size_t)l*HH + tid];
    g_sess[(size_t)bs*HH + tid] = acc;
}

// ---------------- 7. double masked softmax + hf + build [hs|hf] ----------------
__global__ void k_hf_acat() {
    __shared__ float sfin[SS];
    int row = blockIdx.x;
    int b = row / TT, t = row % TT;
    int tid = threadIdx.x;
    if (tid == 0) {
        float v[SS], p[SS]; int m[SS];
        for (int s = 0; s < SS; s++) { m[s] = g_pres[b*SS+s]; v[s] = g_sim1[(b*SS+s)*TT + t]; }
        float mx = -INFINITY;
        for (int s = 0; s < SS; s++) if (m[s]) mx = fmaxf(mx, v[s]);
        float sum = 0.f;
        for (int s = 0; s < SS; s++) { p[s] = m[s] ? expf(v[s]-mx) : 0.f; sum += p[s]; }
        float inv = 1.f / sum;
        for (int s = 0; s < SS; s++) p[s] *= inv;
        mx = -INFINITY;
        for (int s = 0; s < SS; s++) if (m[s]) mx = fmaxf(mx, p[s]);
        sum = 0.f;
        float q[SS];
        for (int s = 0; s < SS; s++) { q[s] = m[s] ? expf(p[s]-mx) : 0.f; sum += q[s]; }
        inv = 1.f / sum;
        for (int s = 0; s < SS; s++) sfin[s] = m[s] ? q[s]*inv : 0.f;
    }
    __syncthreads();
    float acc = 0.f;
#pragma unroll
    for (int s = 0; s < SS; s++) acc += sfin[s] * g_sess[(size_t)(b*SS+s)*HH + tid];
    g_acat[(size_t)row*256 + tid]       = g_hs[(size_t)row*HH + tid];
    g_acat[(size_t)row*256 + 128 + tid] = acc;
}

// ---------------- 8a. split conversions fp32 -> bf16 hi/lo ----------------
__device__ __forceinline__ uint32_t pack_bf2(float a, float b) {
    __nv_bfloat162 t = __floats2bfloat162_rn(a, b);
    return *(uint32_t*)&t;
}
__global__ void k_conv_a() {
    int idx = blockIdx.x * 256 + threadIdx.x;        // over 1280*64 float4s
    if (idx >= CURROWS*64) return;
    int r = idx >> 6, k4 = idx & 63;
    float4 v = *(const float4*)(g_acat + (size_t)r*256 + k4*4);
    float h0 = __bfloat162float(__float2bfloat16_rn(v.x));
    float h1 = __bfloat162float(__float2bfloat16_rn(v.y));
    float h2 = __bfloat162float(__float2bfloat16_rn(v.z));
    float h3 = __bfloat162float(__float2bfloat16_rn(v.w));
    uint2 hi = make_uint2(pack_bf2(h0, h1), pack_bf2(h2, h3));
    uint2 lo = make_uint2(pack_bf2(v.x-h0, v.y-h1), pack_bf2(v.z-h2, v.w-h3));
    *(uint2*)(g_ahi + (size_t)r*256 + k4*4) = hi;
    *(uint2*)(g_alo + (size_t)r*256 + k4*4) = lo;
}
__global__ void k_conv_w(const float* __restrict__ Wo) {
    int idx = blockIdx.x * 256 + threadIdx.x;        // over 50000*64 float4s
    if (idx >= NITEMS*64) return;
    int n = idx >> 6, k4 = idx & 63;
    int ks = (k4*4 < 128) ? k4*4 : k4*4 + 128;       // skip hu block
    float4 v = *(const float4*)(Wo + (size_t)n*H3 + ks);
    float h0 = __bfloat162float(__float2bfloat16_rn(v.x));
    float h1 = __bfloat162float(__float2bfloat16_rn(v.y));
    float h2 = __bfloat162float(__float2bfloat16_rn(v.z));
    float h3 = __bfloat162float(__float2bfloat16_rn(v.w));
    uint2 hi = make_uint2(pack_bf2(h0, h1), pack_bf2(h2, h3));
    uint2 lo = make_uint2(pack_bf2(v.x-h0, v.y-h1), pack_bf2(v.z-h2, v.w-h3));
    *(uint2*)(g_whi + (size_t)n*256 + k4*4) = hi;
    *(uint2*)(g_wlo + (size_t)n*256 + k4*4) = lo;
}

// ---------------- 8b. mma.sync (HMMA) logits GEMM ----------------
// Per CTA: one N-tile (128 cols), persistent over 10 M-tiles of 128 rows.
// 3 passes (hi*hi, lo*hi, hi*lo), K chunks of 64 bf16 double-buffered via cp.async.
#define SM_BIAS    0          // 128 floats
#define SM_A       1024       // 2 x 16KB A chunk buffers
#define SM_BHI     33792      // 4 blocks x 16KB
#define SM_BLO     99328      // 4 blocks x 16KB  (ends at 164864)
#define SM_TOTAL   164864

__device__ __forceinline__ void prefetch_a(int mt, int c, uint32_t dst, int tid) {
    int pass = c >> 2, kc = c & 3;
    const __nv_bfloat16* plane = (pass == 1) ? g_alo : g_ahi;
    const char* src = (const char*)plane + (size_t)(mt*128)*512 + kc*128;
#pragma unroll
    for (int q = 0; q < 4; q++) {
        int i = tid + q*256;          // uint4 index 0..1023
        int row = i >> 3, j = i & 7;
        cpasync16(dst + SWZ((uint32_t)(row*128 + j*16)), src + (size_t)row*512 + j*16);
    }
}

__global__ void __launch_bounds__(256, 1) k_out_mma(const float* __restrict__ bo,
                                                    float* __restrict__ out) {
    extern __shared__ char smem[];
    uint32_t sbase = smem_u32(smem);
    int tid = threadIdx.x, lane = tid & 31, wid = tid >> 5;
    int wm = wid & 3, wn = wid >> 2;     // warp tile: rows wm*32.., cols wn*64..
    int n0 = blockIdx.x * 128;
    float* bsh = (float*)smem;

    if (tid < 128) bsh[tid] = (n0 + tid < NITEMS) ? bo[n0 + tid] : 0.f;

    // resident B tiles: 128 n-rows x 256 bf16 (hi + lo), 4 K-blocks of 64 each
    for (int i = tid; i < 128*32; i += 256) {
        int n = i >> 5, j = i & 31;
        int ng = n0 + n;
        uint4 hv = make_uint4(0,0,0,0), lv = make_uint4(0,0,0,0);
        if (ng < NITEMS) {
            hv = *(const uint4*)(g_whi + (size_t)ng*256 + j*8);
            lv = *(const uint4*)(g_wlo + (size_t)ng*256 + j*8);
        }
        int kc = j >> 3, jj = j & 7;
        uint32_t off = SWZ((uint32_t)(n*128 + jj*16));
        *(uint4*)(smem + SM_BHI + kc*16384 + off) = hv;
        *(uint4*)(smem + SM_BLO + kc*16384 + off) = lv;
    }
    __syncthreads();

    uint32_t abuf0 = sbase + SM_A;
    // per-lane fragment address components
    int arow = wm*32 + (lane & 15);
    uint32_t asel = (uint32_t)((lane >> 4) * 16);
    int bg = lane >> 3, br = lane & 7;
    int bnrow = wn*64 + ((bg >> 1) << 3) + br;
    uint32_t bkb = (uint32_t)((bg & 1) * 16);

    for (int mt = 0; mt < 10; mt++) {
        float acc[2][8][4];
#pragma unroll
        for (int u = 0; u < 2; u++)
#pragma unroll
            for (int v = 0; v < 8; v++)
#pragma unroll
                for (int q = 0; q < 4; q++) acc[u][v][q] = 0.f;

        prefetch_a(mt, 0, abuf0, tid);
        CP_COMMIT();

        for (int c = 0; c < 12; c++) {
            if (c + 1 < 12) {
                prefetch_a(mt, c + 1, abuf0 + ((c + 1) & 1) * 16384, tid);
                CP_COMMIT();
                CP_WAIT1();
            } else {
                CP_WAIT0();
            }
            __syncthreads();

            int pass = c >> 2, kc = c & 3;
            uint32_t ab = abuf0 + (c & 1) * 16384;
            uint32_t bb = sbase + ((pass == 2) ? SM_BLO : SM_BHI) + kc*16384;
#pragma unroll
            for (int s = 0; s < 4; s++) {
                uint32_t A0[4], A1[4];
                ldsm4(A0[0], A0[1], A0[2], A0[3], ab + SWZ((uint32_t)(arow*128      + s*32) + asel));
                ldsm4(A1[0], A1[1], A1[2], A1[3], ab + SWZ((uint32_t)((arow+16)*128 + s*32) + asel));
                uint32_t Bf[8][2];
#pragma unroll
                for (int nfp = 0; nfp < 4; nfp++) {
                    uint32_t b0, b1, b2, b3;
                    ldsm4(b0, b1, b2, b3,
                          bb + SWZ((uint32_t)((bnrow + nfp*16)*128 + s*32) + bkb));
                    Bf[2*nfp][0] = b0;   Bf[2*nfp][1] = b1;
                    Bf[2*nfp+1][0] = b2; Bf[2*nfp+1][1] = b3;
                }
#pragma unroll
                for (int nf = 0; nf < 8; nf++) {
                    mma16816(acc[0][nf], A0, Bf[nf][0], Bf[nf][1]);
                    mma16816(acc[1][nf], A1, Bf[nf][0], Bf[nf][1]);
                }
            }
            __syncthreads();
        }

        // epilogue: acc + bias -> out
        int rbase = mt*128 + wm*32 + (lane >> 2);
        int cq = (lane & 3) * 2;
#pragma unroll
        for (int mf = 0; mf < 2; mf++) {
            int rr = rbase + mf*16;
#pragma unroll
            for (int nf = 0; nf < 8; nf++) {
                int cl = wn*64 + nf*8 + cq;
                int cc = n0 + cl;
                if (cc < NITEMS) {
                    float2 v0, v1;
                    v0.x = acc[mf][nf][0] + bsh[cl];
                    v0.y = acc[mf][nf][1] + bsh[cl+1];
                    v1.x = acc[mf][nf][2] + bsh[cl];
                    v1.y = acc[mf][nf][3] + bsh[cl+1];
                    *(float2*)(out + (size_t)rr*NITEMS + cc)     = v0;
                    *(float2*)(out + (size_t)(rr+8)*NITEMS + cc) = v1;
                }
            }
        }
    }
}

// ---------------- launch ----------------
extern "C" void kernel_launch(void* const* d_in, const int* in_sizes, int n_in,
                              void* d_out, int out_size) {
    (void)in_sizes; (void)n_in; (void)out_size;
    const int*   users = (const int*)d_in[0];
    const int*   cur   = (const int*)d_in[1];
    const int*   frds  = (const int*)d_in[3];
    const float* vemb  = (const float*)d_in[5];
    const float* uemb  = (const float*)d_in[6];
    const float* Wih   = (const float*)d_in[7];
    const float* Whh   = (const float*)d_in[8];
    const float* bih   = (const float*)d_in[9];
    const float* bhh   = (const float*)d_in[10];
    const float* Wo    = (const float*)d_in[11];
    const float* bo    = (const float*)d_in[12];
    float* out = (float*)d_out;

    // weight-plane conversion first (no deps on activations)
    k_conv_w<<<(NITEMS*64 + 255)/256, 256>>>(Wo);

    k_gather<<<(NROWS*HH)/256, 256>>>(cur, frds, vemb);

    dim3 ggi(H3/128, NROWS/64);
    k_gi_gemm<<<ggi, 256>>>(Wih, bih);

    const int gru_smem = (384*132 + SEQPB*128 + SEQPB*H3) * (int)sizeof(float);
    cudaFuncSetAttribute(k_gru, cudaFuncAttributeMaxDynamicSharedMemorySize, gru_smem);
    k_gru<<<(NSEQ + SEQPB - 1)/SEQPB, 384, gru_smem>>>(Whh, bhh);

    k_scores<<<BB*SS, 256>>>();
    k_smax_topk<<<(BB*TT + 255)/256, 256>>>();
    k_wsess<<<BB*SS, 128>>>(users, uemb);
    k_hf_acat<<<BB*TT, 128>>>();
    k_conv_a<<<(CURROWS*64 + 255)/256, 256>>>();

    cudaFuncSetAttribute(k_out_mma, cudaFuncAttributeMaxDynamicSharedMemorySize, SM_TOTAL);
    k_out_mma<<<(NITEMS + 127)/128, 256, SM_TOTAL>>>(bo, out);
}

// round 6
// speedup vs baseline: 2.4738x; 1.2672x over previous
#include <cuda_runtime.h>
#include <cuda_bf16.h>
#include <math.h>
#include <stdint.h>

// ---------------- problem constants ----------------
#define BB      64
#define TT      20
#define SS      10
#define LL      20
#define HH      128
#define H3      384
#define NITEMS  50000
#define CURROWS (BB*TT)          // 1280
#define FRDROWS (BB*SS*LL)       // 12800
#define NROWS   (CURROWS+FRDROWS) // 14080
#define NSEQ    (BB + BB*SS)     // 704 sequences, each length 20
#define SEQPB   5                // sequences per GRU block -> 141 blocks (1 wave)

// ---------------- scratch (static device memory; no allocations) ----------------
__device__ float g_x[NROWS*HH];
__device__ float g_gi[NROWS*H3];
__device__ float g_hs[NROWS*HH];
__device__ float g_simraw[BB*SS*TT];
__device__ float g_sim1[BB*SS*TT];
__device__ int   g_pres[BB*SS];
__device__ float g_sess[BB*SS*HH];
__device__ float g_acat[CURROWS*256];
// bf16 split planes
__device__ __align__(16) __nv_bfloat16 g_ahi[CURROWS*256];
__device__ __align__(16) __nv_bfloat16 g_alo[CURROWS*256];
__device__ __align__(16) __nv_bfloat16 g_xhi[NROWS*HH];
__device__ __align__(16) __nv_bfloat16 g_xlo[NROWS*HH];

// ---------------- helpers ----------------
__device__ __forceinline__ uint32_t smem_u32(const void* p) {
    uint32_t a;
    asm("{ .reg .u64 t; cvta.to.shared.u64 t, %1; cvt.u32.u64 %0, t; }" : "=r"(a) : "l"(p));
    return a;
}
#define SWZ(off) ((off) ^ (((off) >> 3) & 0x70))

__device__ __forceinline__ void ldsm4(uint32_t& r0, uint32_t& r1, uint32_t& r2, uint32_t& r3,
                                      uint32_t addr) {
    asm volatile("ldmatrix.sync.aligned.m8n8.x4.shared.b16 {%0,%1,%2,%3}, [%4];"
                 : "=r"(r0), "=r"(r1), "=r"(r2), "=r"(r3) : "r"(addr));
}
__device__ __forceinline__ void mma16816(float* c, const uint32_t* a, uint32_t b0, uint32_t b1) {
    asm volatile("mma.sync.aligned.m16n8k16.row.col.f32.bf16.bf16.f32 "
                 "{%0,%1,%2,%3}, {%4,%5,%6,%7}, {%8,%9}, {%0,%1,%2,%3};"
                 : "+f"(c[0]), "+f"(c[1]), "+f"(c[2]), "+f"(c[3])
                 : "r"(a[0]), "r"(a[1]), "r"(a[2]), "r"(a[3]), "r"(b0), "r"(b1));
}
__device__ __forceinline__ void cpasync16(uint32_t dst, const void* src) {
    asm volatile("cp.async.cg.shared.global [%0], [%1], 16;" :: "r"(dst), "l"(src));
}
#define CP_COMMIT() asm volatile("cp.async.commit_group;" ::: "memory")
#define CP_WAIT1()  asm volatile("cp.async.wait_group 1;" ::: "memory")
#define CP_WAIT0()  asm volatile("cp.async.wait_group 0;" ::: "memory")

__device__ __forceinline__ uint32_t pack_bf2(float a, float b) {
    __nv_bfloat162 t = __floats2bfloat162_rn(a, b);
    return *(uint32_t*)&t;
}
__device__ __forceinline__ void split8(const float* s, uint4& hi, uint4& lo) {
    float4 v0 = *(const float4*)s, v1 = *(const float4*)(s + 4);
    float a[8] = {v0.x, v0.y, v0.z, v0.w, v1.x, v1.y, v1.z, v1.w};
    float h[8];
#pragma unroll
    for (int q = 0; q < 8; q++) h[q] = __bfloat162float(__float2bfloat16_rn(a[q]));
    hi = make_uint4(pack_bf2(h[0],h[1]), pack_bf2(h[2],h[3]),
                    pack_bf2(h[4],h[5]), pack_bf2(h[6],h[7]));
    lo = make_uint4(pack_bf2(a[0]-h[0],a[1]-h[1]), pack_bf2(a[2]-h[2],a[3]-h[3]),
                    pack_bf2(a[4]-h[4],a[5]-h[5]), pack_bf2(a[6]-h[6],a[7]-h[7]));
}
// fast, overflow-robust sigmoid/tanh (err ~1e-6, well inside 1e-3)
__device__ __forceinline__ float fsig(float x) {
    return __fdividef(1.f, 1.f + __expf(-x));
}
__device__ __forceinline__ float ftanh(float x) {
    return __fdividef(2.f, 1.f + __expf(-2.f*x)) - 1.f;
}

// ---------------- 1. gather v_emb[indices] (+ write x bf16 hi/lo planes) ----------------
__global__ void k_gather(const int* __restrict__ cur, const int* __restrict__ frd,
                         const float* __restrict__ vemb) {
    int t = blockIdx.x * blockDim.x + threadIdx.x;
    if (t >= NROWS*HH) return;
    int row = t >> 7, col = t & 127;
    int item = (row < CURROWS) ? cur[row] : frd[row - CURROWS];
    float v = vemb[(size_t)item * HH + col];
    g_x[t] = v;
    float h = __bfloat162float(__float2bfloat16_rn(v));
    g_xhi[t] = __float2bfloat16_rn(h);
    g_xlo[t] = __float2bfloat16_rn(v - h);
}

// ---------------- 2. GI GEMM (mma.sync, split-bf16 3-pass): x @ W_ih^T + b_ih ----------------
#define GI_A     1024       // 2 x 16KB A chunk buffers
#define GI_BHI   33792      // 2 blocks x 16KB
#define GI_BLO   66560      // 2 blocks x 16KB
#define GI_TOTAL 99328

__device__ __forceinline__ void gi_prefetch_a(int m0, int c, uint32_t dst, int tid) {
    const __nv_bfloat16* plane = (c & 1) ? g_xlo : g_xhi;
    int kc = c >> 1;
    const char* src = (const char*)plane + (size_t)m0*256 + kc*128;
#pragma unroll
    for (int q = 0; q < 4; q++) {
        int i = tid + q*256;
        int row = i >> 3, j = i & 7;
        cpasync16(dst + SWZ((uint32_t)(row*128 + j*16)), src + (size_t)row*256 + j*16);
    }
}

__global__ void __launch_bounds__(256, 1) k_gi_mma(const float* __restrict__ Wih,
                                                   const float* __restrict__ bih) {
    extern __shared__ char smem[];
    uint32_t sbase = smem_u32(smem);
    int tid = threadIdx.x, lane = tid & 31, wid = tid >> 5;
    int wm = wid & 3, wn = wid >> 2;
    int n0 = blockIdx.x * 128, m0 = blockIdx.y * 128;
    float* bsh = (float*)smem;
    if (tid < 128) bsh[tid] = bih[n0 + tid];

    // first A chunk in flight while we split B
    gi_prefetch_a(m0, 0, sbase + GI_A, tid);
    CP_COMMIT();

    // B = W_ih rows n0..n0+127 (128 k fp32), split to bf16 hi/lo in smem
    for (int i = tid; i < 128*16; i += 256) {
        int n = i >> 4, j = i & 15;
        uint4 hi, lo;
        split8(Wih + (size_t)(n0+n)*HH + j*8, hi, lo);
        int kc = j >> 3, jj = j & 7;
        uint32_t off = SWZ((uint32_t)(n*128 + jj*16));
        *(uint4*)(smem + GI_BHI + kc*16384 + off) = hi;
        *(uint4*)(smem + GI_BLO + kc*16384 + off) = lo;
    }
    __syncthreads();

    uint32_t abuf0 = sbase + GI_A;
    int arow = wm*32 + (lane & 15);
    uint32_t asel = (uint32_t)((lane >> 4) * 16);
    int bg = lane >> 3, br = lane & 7;
    int bnrow = wn*64 + ((bg >> 1) << 3) + br;
    uint32_t bkb = (uint32_t)((bg & 1) * 16);

    float acc[2][8][4];
#pragma unroll
    for (int u = 0; u < 2; u++)
#pragma unroll
        for (int v = 0; v < 8; v++)
#pragma unroll
            for (int q = 0; q < 4; q++) acc[u][v][q] = 0.f;

    for (int c = 0; c < 4; c++) {
        if (c + 1 < 4) {
            gi_prefetch_a(m0, c + 1, abuf0 + ((c + 1) & 1) * 16384, tid);
            CP_COMMIT();
            CP_WAIT1();
        } else {
            CP_WAIT0();
        }
        __syncthreads();
        int kc = c >> 1;
        uint32_t ab = abuf0 + (c & 1) * 16384;
        uint32_t bhi_b = sbase + GI_BHI + kc*16384;
        uint32_t blo_b = sbase + GI_BLO + kc*16384;
        bool hiA = !(c & 1);
#pragma unroll
        for (int s = 0; s < 4; s++) {
            uint32_t A0[4], A1[4];
            ldsm4(A0[0], A0[1], A0[2], A0[3], ab + SWZ((uint32_t)(arow*128      + s*32) + asel));
            ldsm4(A1[0], A1[1], A1[2], A1[3], ab + SWZ((uint32_t)((arow+16)*128 + s*32) + asel));
            uint32_t Bf[8][2];
#pragma unroll
            for (int nfp = 0; nfp < 4; nfp++) {
                uint32_t b0, b1, b2, b3;
                ldsm4(b0, b1, b2, b3, bhi_b + SWZ((uint32_t)((bnrow + nfp*16)*128 + s*32) + bkb));
                Bf[2*nfp][0] = b0;   Bf[2*nfp][1] = b1;
                Bf[2*nfp+1][0] = b2; Bf[2*nfp+1][1] = b3;
            }
#pragma unroll
            for (int nf = 0; nf < 8; nf++) {
                mma16816(acc[0][nf], A0, Bf[nf][0], Bf[nf][1]);
                mma16816(acc[1][nf], A1, Bf[nf][0], Bf[nf][1]);
            }
            if (hiA) {
#pragma unroll
                for (int nfp = 0; nfp < 4; nfp++) {
                    uint32_t b0, b1, b2, b3;
                    ldsm4(b0, b1, b2, b3, blo_b + SWZ((uint32_t)((bnrow + nfp*16)*128 + s*32) + bkb));
                    Bf[2*nfp][0] = b0;   Bf[2*nfp][1] = b1;
                    Bf[2*nfp+1][0] = b2; Bf[2*nfp+1][1] = b3;
                }
#pragma unroll
                for (int nf = 0; nf < 8; nf++) {
                    mma16816(acc[0][nf], A0, Bf[nf][0], Bf[nf][1]);
                    mma16816(acc[1][nf], A1, Bf[nf][0], Bf[nf][1]);
                }
            }
        }
        __syncthreads();
    }

    int rbase = m0 + wm*32 + (lane >> 2);
    int cq = (lane & 3) * 2;
#pragma unroll
    for (int mf = 0; mf < 2; mf++) {
        int rr = rbase + mf*16;
#pragma unroll
        for (int nf = 0; nf < 8; nf++) {
            int cl = wn*64 + nf*8 + cq;
            float2 v0, v1;
            v0.x = acc[mf][nf][0] + bsh[cl];
            v0.y = acc[mf][nf][1] + bsh[cl+1];
            v1.x = acc[mf][nf][2] + bsh[cl];
            v1.y = acc[mf][nf][3] + bsh[cl+1];
            *(float2*)(g_gi + (size_t)rr*H3 + n0 + cl)     = v0;
            *(float2*)(g_gi + (size_t)(rr+8)*H3 + n0 + cl) = v1;
        }
    }
}

// ---------------- 3. GRU recurrence (g_gi prefetch + fast transcendentals) ----------------
__global__ void k_gru(const float* __restrict__ Whh, const float* __restrict__ bhh) {
    extern __shared__ float sm[];
    float* Wsh  = sm;                    // [384][132]
    float* hsh  = sm + 384*132;          // [5][128]
    float* ghsh = hsh + SEQPB*128;       // [5][384]
    int tid = threadIdx.x;               // 384 threads
    for (int idx = tid; idx < 384*128; idx += 384) {
        int j = idx >> 7, k = idx & 127;
        Wsh[j*132 + k] = Whh[idx];
    }
    int seq0 = blockIdx.x * SEQPB;
    int nseq = NSEQ - seq0; if (nseq > SEQPB) nseq = SEQPB;
    for (int idx = tid; idx < SEQPB*128; idx += 384) hsh[idx] = 0.f;
    __syncthreads();

    int j = tid;
    float bh = bhh[j];
    const float4* w4 = (const float4*)(Wsh + j*132);
    int nel = nseq * 128;

    for (int t = 0; t < 20; t++) {
        // prefetch this step's gate pre-activations from global (hidden under phase 1)
        float pg[2][3];
#pragma unroll
        for (int e = 0; e < 2; e++) {
            int idx = tid + e*384;
            pg[e][0] = pg[e][1] = pg[e][2] = 0.f;
            if (idx < nel) {
                int i = idx >> 7, jj = idx & 127;
                const float* gir = g_gi + ((size_t)(seq0 + i) * 20 + t) * H3;
                pg[e][0] = gir[jj];
                pg[e][1] = gir[128 + jj];
                pg[e][2] = gir[256 + jj];
            }
        }
        // phase 1: gh[i][j] = b_hh[j] + h[i,:] . W_hh[j,:]
        float acc[SEQPB];
#pragma unroll
        for (int i = 0; i < SEQPB; i++) acc[i] = bh;
#pragma unroll 8
        for (int kq = 0; kq < 32; kq++) {
            float4 w = w4[kq];
#pragma unroll
            for (int i = 0; i < SEQPB; i++) {
                float4 h = *(const float4*)(&hsh[i*128 + kq*4]);
                acc[i] += w.x*h.x + w.y*h.y + w.z*h.z + w.w*h.w;
            }
        }
#pragma unroll
        for (int i = 0; i < SEQPB; i++) ghsh[i*H3 + j] = acc[i];
        __syncthreads();
        // phase 2: gates + h update (fast sigmoid/tanh)
#pragma unroll
        for (int e = 0; e < 2; e++) {
            int idx = tid + e*384;
            if (idx < nel) {
                int i = idx >> 7, jj = idx & 127;
                float r = fsig(pg[e][0] + ghsh[i*H3 + jj]);
                float z = fsig(pg[e][1] + ghsh[i*H3 + 128 + jj]);
                float n = ftanh(pg[e][2] + r * ghsh[i*H3 + 256 + jj]);
                float hprev = hsh[i*128 + jj];
                float h = (1.f - z) * n + z * hprev;
                hsh[i*128 + jj] = h;
                g_hs[((size_t)(seq0 + i) * 20 + t) * HH + jj] = h;
            }
        }
        __syncthreads();
    }
}

// ---------------- 4. scores + max_l ----------------
__global__ void k_scores() {
    __shared__ float Qt[HH*TT];
    __shared__ float Et[HH*LL];
    __shared__ float Sc[TT*LL];
    int bs = blockIdx.x;
    int b  = bs / SS;
    int tid = threadIdx.x;
    const float* qsrc = g_hs + (size_t)(b*TT) * HH;
    const float* esrc = g_hs + (size_t)(CURROWS + bs*LL) * HH;
    for (int i = tid; i < TT*HH; i += 256) {
        int tt = i >> 7, k = i & 127;
        Qt[k*TT + tt] = qsrc[i];
        Et[k*LL + tt] = esrc[i];
    }
    __syncthreads();
    for (int p = tid; p < TT*LL; p += 256) {
        int t = p / LL, l = p % LL;
        float acc = 0.f;
#pragma unroll 8
        for (int k = 0; k < HH; k++) acc += Qt[k*TT + t] * Et[k*LL + l];
        Sc[t*LL + l] = acc;
    }
    __syncthreads();
    if (tid < TT) {
        float mx = -INFINITY;
        for (int l = 0; l < LL; l++) mx = fmaxf(mx, Sc[tid*LL + l]);
        g_simraw[(size_t)bs*TT + tid] = mx;
    }
    if (tid == 0) g_pres[bs] = 0;
}

// ---------------- 5. softmax over s + top-2 ----------------
__global__ void k_smax_topk() {
    int gid = blockIdx.x * 256 + threadIdx.x;
    if (gid >= BB*TT) return;
    int b = gid / TT, t = gid % TT;
    float v[SS];
    float mx = -INFINITY;
#pragma unroll
    for (int s = 0; s < SS; s++) { v[s] = g_simraw[(b*SS+s)*TT + t]; mx = fmaxf(mx, v[s]); }
    float sum = 0.f;
#pragma unroll
    for (int s = 0; s < SS; s++) { v[s] = expf(v[s]-mx); sum += v[s]; }
    float inv = 1.f / sum;
#pragma unroll
    for (int s = 0; s < SS; s++) { v[s] *= inv; g_sim1[(b*SS+s)*TT + t] = v[s]; }
    int i1 = 0; float b1 = v[0];
#pragma unroll
    for (int s = 1; s < SS; s++) if (v[s] > b1) { b1 = v[s]; i1 = s; }
    int i2 = -1; float b2 = -INFINITY;
#pragma unroll
    for (int s = 0; s < SS; s++) if (s != i1 && v[s] > b2) { b2 = v[s]; i2 = s; }
    atomicOr(&g_pres[b*SS + i1], 1);
    atomicOr(&g_pres[b*SS + i2], 1);
}

// ---------------- 6. friend-session attention ----------------
__global__ void k_wsess(const int* __restrict__ users, const float* __restrict__ uemb) {
    __shared__ float ue[HH];
    __shared__ float d[LL];
    __shared__ float wsm[LL];
    int bs = blockIdx.x;
    int b = bs / SS;
    int tid = threadIdx.x;
    ue[tid] = uemb[(size_t)users[b]*HH + tid];
    __syncthreads();
    const float* F = g_x + (size_t)(CURROWS + bs*LL) * HH;
    int lane = tid & 31, w = tid >> 5;
    for (int l = w*5; l < w*5 + 5; l++) {
        float p = 0.f;
#pragma unroll
        for (int k = lane; k < HH; k += 32) p += ue[k] * F[(size_t)l*HH + k];
#pragma unroll
        for (int off = 16; off > 0; off >>= 1) p += __shfl_down_sync(0xffffffff, p, off);
        if (lane == 0) d[l] = p;
    }
    __syncthreads();
    if (tid == 0) {
        float mx = -INFINITY;
        for (int l = 0; l < LL; l++) mx = fmaxf(mx, d[l]);
        float sum = 0.f;
        for (int l = 0; l < LL; l++) { wsm[l] = expf(d[l]-mx); sum += wsm[l]; }
        float inv = 1.f / sum;
        for (int l = 0; l < LL; l++) wsm[l] *= inv;
    }
    __syncthreads();
    float acc = 0.f;
#pragma unroll
    for (int l = 0; l < LL; l++) acc += wsm[l] * F[(size_t)l*HH + tid];
    g_sess[(size_t)bs*HH + tid] = acc;
}

// ---------------- 7. double masked softmax + hf + build [hs|hf] ----------------
__global__ void k_hf_acat() {
    __shared__ float sfin[SS];
    int row = blockIdx.x;
    int b = row / TT, t = row % TT;
    int tid = threadIdx.x;
    if (tid == 0) {
        float v[SS], p[SS]; int m[SS];
        for (int s = 0; s < SS; s++) { m[s] = g_pres[b*SS+s]; v[s] = g_sim1[(b*SS+s)*TT + t]; }
        float mx = -INFINITY;
        for (int s = 0; s < SS; s++) if (m[s]) mx = fmaxf(mx, v[s]);
        float sum = 0.f;
        for (int s = 0; s < SS; s++) { p[s] = m[s] ? expf(v[s]-mx) : 0.f; sum += p[s]; }
        float inv = 1.f / sum;
        for (int s = 0; s < SS; s++) p[s] *= inv;
        mx = -INFINITY;
        for (int s = 0; s < SS; s++) if (m[s]) mx = fmaxf(mx, p[s]);
        sum = 0.f;
        float q[SS];
        for (int s = 0; s < SS; s++) { q[s] = m[s] ? expf(p[s]-mx) : 0.f; sum += q[s]; }
        inv = 1.f / sum;
        for (int s = 0; s < SS; s++) sfin[s] = m[s] ? q[s]*inv : 0.f;
    }
    __syncthreads();
    float acc = 0.f;
#pragma unroll
    for (int s = 0; s < SS; s++) acc += sfin[s] * g_sess[(size_t)(b*SS+s)*HH + tid];
    g_acat[(size_t)row*256 + tid]       = g_hs[(size_t)row*HH + tid];
    g_acat[(size_t)row*256 + 128 + tid] = acc;
}

// ---------------- 8a. split conversion for A (activations) ----------------
__global__ void k_conv_a() {
    int idx = blockIdx.x * 256 + threadIdx.x;        // over 1280*64 float4s
    if (idx >= CURROWS*64) return;
    int r = idx >> 6, k4 = idx & 63;
    float4 v = *(const float4*)(g_acat + (size_t)r*256 + k4*4);
    float h0 = __bfloat162float(__float2bfloat16_rn(v.x));
    float h1 = __bfloat162float(__float2bfloat16_rn(v.y));
    float h2 = __bfloat162float(__float2bfloat16_rn(v.z));
    float h3 = __bfloat162float(__float2bfloat16_rn(v.w));
    uint2 hi = make_uint2(pack_bf2(h0, h1), pack_bf2(h2, h3));
    uint2 lo = make_uint2(pack_bf2(v.x-h0, v.y-h1), pack_bf2(v.z-h2, v.w-h3));
    *(uint2*)(g_ahi + (size_t)r*256 + k4*4) = hi;
    *(uint2*)(g_alo + (size_t)r*256 + k4*4) = lo;
}

// ---------------- 8b. mma.sync logits GEMM (Wo split in-kernel, A-reuse chunk order) ----------------
#define SM_A       1024       // 2 x 16KB A chunk buffers
#define SM_BHI     33792      // 4 blocks x 16KB
#define SM_BLO     99328      // 4 blocks x 16KB  (ends at 164864)
#define SM_TOTAL   164864

__device__ __forceinline__ void prefetch_a(int mt, int c, uint32_t dst, int tid) {
    const __nv_bfloat16* plane = (c & 1) ? g_alo : g_ahi;
    int kc = c >> 1;
    const char* src = (const char*)plane + (size_t)(mt*128)*512 + kc*128;
#pragma unroll
    for (int q = 0; q < 4; q++) {
        int i = tid + q*256;          // uint4 index 0..1023
        int row = i >> 3, j = i & 7;
        cpasync16(dst + SWZ((uint32_t)(row*128 + j*16)), src + (size_t)row*512 + j*16);
    }
}

__global__ void __launch_bounds__(256, 1) k_out_mma(const float* __restrict__ Wo,
                                                    const float* __restrict__ bo,
                                                    float* __restrict__ out) {
    extern __shared__ char smem[];
    uint32_t sbase = smem_u32(smem);
    int tid = threadIdx.x, lane = tid & 31, wid = tid >> 5;
    int wm = wid & 3, wn = wid >> 2;     // warp tile: rows wm*32.., cols wn*64..
    int n0 = blockIdx.x * 128;
    float* bsh = (float*)smem;

    if (tid < 128) bsh[tid] = (n0 + tid < NITEMS) ? bo[n0 + tid] : 0.f;

    // first A chunk in flight while we split B
    prefetch_a(0, 0, sbase + SM_A, tid);
    CP_COMMIT();

    // resident B: 128 n-rows x 256 k (skipping hu block), fp32 -> bf16 hi/lo split in-kernel
    for (int i = tid; i < 128*32; i += 256) {
        int n = i >> 5, j = i & 31;       // j = group of 8 k-values
        int ng = n0 + n;
        uint4 hi = make_uint4(0,0,0,0), lo = make_uint4(0,0,0,0);
        if (ng < NITEMS) {
            int k0 = j * 8;
            int ks = (k0 < 128) ? k0 : k0 + 128;   // skip hu block
            split8(Wo + (size_t)ng*H3 + ks, hi, lo);
        }
        int kc = j >> 3, jj = j & 7;
        uint32_t off = SWZ((uint32_t)(n*128 + jj*16));
        *(uint4*)(smem + SM_BHI + kc*16384 + off) = hi;
        *(uint4*)(smem + SM_BLO + kc*16384 + off) = lo;
    }
    __syncthreads();

    uint32_t abuf0 = sbase + SM_A;
    int arow = wm*32 + (lane & 15);
    uint32_t asel = (uint32_t)((lane >> 4) * 16);
    int bg = lane >> 3, br = lane & 7;
    int bnrow = wn*64 + ((bg >> 1) << 3) + br;
    uint32_t bkb = (uint32_t)((bg & 1) * 16);

    for (int mt = 0; mt < 10; mt++) {
        float acc[2][8][4];
#pragma unroll
        for (int u = 0; u < 2; u++)
#pragma unroll
            for (int v = 0; v < 8; v++)
#pragma unroll
                for (int q = 0; q < 4; q++) acc[u][v][q] = 0.f;

        if (mt > 0) {
            prefetch_a(mt, 0, abuf0, tid);
            CP_COMMIT();
        }
        // chunk order (A-reuse): c even -> a_hi[kc] vs {b_hi, b_lo}; c odd -> a_lo[kc] vs b_hi
        for (int c = 0; c < 8; c++) {
            if (c + 1 < 8) {
                prefetch_a(mt, c + 1, abuf0 + ((c + 1) & 1) * 16384, tid);
                CP_COMMIT();
                CP_WAIT1();
            } else {
                CP_WAIT0();
            }
            __syncthreads();

            int kc = c >> 1;
            uint32_t ab = abuf0 + (c & 1) * 16384;
            uint32_t bhi_b = sbase + SM_BHI + kc*16384;
            uint32_t blo_b = sbase + SM_BLO + kc*16384;
            bool hiA = !(c & 1);
#pragma unroll
            for (int s = 0; s < 4; s++) {
                uint32_t A0[4], A1[4];
                ldsm4(A0[0], A0[1], A0[2], A0[3], ab + SWZ((uint32_t)(arow*128      + s*32) + asel));
                ldsm4(A1[0], A1[1], A1[2], A1[3], ab + SWZ((uint32_t)((arow+16)*128 + s*32) + asel));
                uint32_t Bf[8][2];
#pragma unroll
                for (int nfp = 0; nfp < 4; nfp++) {
                    uint32_t b0, b1, b2, b3;
                    ldsm4(b0, b1, b2, b3, bhi_b + SWZ((uint32_t)((bnrow + nfp*16)*128 + s*32) + bkb));
                    Bf[2*nfp][0] = b0;   Bf[2*nfp][1] = b1;
                    Bf[2*nfp+1][0] = b2; Bf[2*nfp+1][1] = b3;
                }
#pragma unroll
                for (int nf = 0; nf < 8; nf++) {
                    mma16816(acc[0][nf], A0, Bf[nf][0], Bf[nf][1]);
                    mma16816(acc[1][nf], A1, Bf[nf][0], Bf[nf][1]);
                }
                if (hiA) {
#pragma unroll
                    for (int nfp = 0; nfp < 4; nfp++) {
                        uint32_t b0, b1, b2, b3;
                        ldsm4(b0, b1, b2, b3, blo_b + SWZ((uint32_t)((bnrow + nfp*16)*128 + s*32) + bkb));
                        Bf[2*nfp][0] = b0;   Bf[2*nfp][1] = b1;
                        Bf[2*nfp+1][0] = b2; Bf[2*nfp+1][1] = b3;
                    }
#pragma unroll
                    for (int nf = 0; nf < 8; nf++) {
                        mma16816(acc[0][nf], A0, Bf[nf][0], Bf[nf][1]);
                        mma16816(acc[1][nf], A1, Bf[nf][0], Bf[nf][1]);
                    }
                }
            }
            __syncthreads();
        }

        // epilogue: acc + bias -> out
        int rbase = mt*128 + wm*32 + (lane >> 2);
        int cq = (lane & 3) * 2;
#pragma unroll
        for (int mf = 0; mf < 2; mf++) {
            int rr = rbase + mf*16;
#pragma unroll
            for (int nf = 0; nf < 8; nf++) {
                int cl = wn*64 + nf*8 + cq;
                int cc = n0 + cl;
                if (cc < NITEMS) {
                    float2 v0, v1;
                    v0.x = acc[mf][nf][0] + bsh[cl];
                    v0.y = acc[mf][nf][1] + bsh[cl+1];
                    v1.x = acc[mf][nf][2] + bsh[cl];
                    v1.y = acc[mf][nf][3] + bsh[cl+1];
                    *(float2*)(out + (size_t)rr*NITEMS + cc)     = v0;
                    *(float2*)(out + (size_t)(rr+8)*NITEMS + cc) = v1;
                }
            }
        }
    }
}

// ---------------- launch ----------------
extern "C" void kernel_launch(void* const* d_in, const int* in_sizes, int n_in,
                              void* d_out, int out_size) {
    (void)in_sizes; (void)n_in; (void)out_size;
    const int*   users = (const int*)d_in[0];
    const int*   cur   = (const int*)d_in[1];
    const int*   frds  = (const int*)d_in[3];
    const float* vemb  = (const float*)d_in[5];
    const float* uemb  = (const float*)d_in[6];
    const float* Wih   = (const float*)d_in[7];
    const float* Whh   = (const float*)d_in[8];
    const float* bih   = (const float*)d_in[9];
    const float* bhh   = (const float*)d_in[10];
    const float* Wo    = (const float*)d_in[11];
    const float* bo    = (const float*)d_in[12];
    float* out = (float*)d_out;

    k_gather<<<(NROWS*HH)/256, 256>>>(cur, frds, vemb);

    cudaFuncSetAttribute(k_gi_mma, cudaFuncAttributeMaxDynamicSharedMemorySize, GI_TOTAL);
    k_gi_mma<<<dim3(3, NROWS/128), 256, GI_TOTAL>>>(Wih, bih);

    const int gru_smem = (384*132 + SEQPB*128 + SEQPB*H3) * (int)sizeof(float);
    cudaFuncSetAttribute(k_gru, cudaFuncAttributeMaxDynamicSharedMemorySize, gru_smem);
    k_gru<<<(NSEQ + SEQPB - 1)/SEQPB, 384, gru_smem>>>(Whh, bhh);

    k_scores<<<BB*SS, 256>>>();
    k_smax_topk<<<(BB*TT + 255)/256, 256>>>();
    k_wsess<<<BB*SS, 128>>>(users, uemb);
    k_hf_acat<<<BB*TT, 128>>>();
    k_conv_a<<<(CURROWS*64 + 255)/256, 256>>>();

    cudaFuncSetAttribute(k_out_mma, cudaFuncAttributeMaxDynamicSharedMemorySize, SM_TOTAL);
    k_out_mma<<<(NITEMS + 127)/128, 256, SM_TOTAL>>>(Wo, bo, out);
}

// round 8
// speedup vs baseline: 2.5063x; 1.0131x over previous
#include <cuda_runtime.h>
#include <cuda_bf16.h>
#include <math.h>
#include <stdint.h>

// ---------------- problem constants ----------------
#define BB      64
#define TT      20
#define SS      10
#define LL      20
#define HH      128
#define H3      384
#define NITEMS  50000
#define CURROWS (BB*TT)          // 1280
#define FRDROWS (BB*SS*LL)       // 12800
#define NROWS   (CURROWS+FRDROWS) // 14080
#define NSEQ    (BB + BB*SS)     // 704 sequences, each length 20
#define SEQPB   5

// ---------------- scratch (static device memory; no allocations) ----------------
__device__ float g_x[NROWS*HH];
__device__ float g_gi[NROWS*H3];
__device__ float g_hs[NROWS*HH];
// bf16 split planes
__device__ __align__(16) __nv_bfloat16 g_ahi[CURROWS*256];
__device__ __align__(16) __nv_bfloat16 g_alo[CURROWS*256];
__device__ __align__(16) __nv_bfloat16 g_xhi[NROWS*HH];
__device__ __align__(16) __nv_bfloat16 g_xlo[NROWS*HH];

// ---------------- helpers ----------------
__device__ __forceinline__ uint32_t smem_u32(const void* p) {
    uint32_t a;
    asm("{ .reg .u64 t; cvta.to.shared.u64 t, %1; cvt.u32.u64 %0, t; }" : "=r"(a) : "l"(p));
    return a;
}
#define SWZ(off) ((off) ^ (((off) >> 3) & 0x70))

__device__ __forceinline__ void ldsm4(uint32_t& r0, uint32_t& r1, uint32_t& r2, uint32_t& r3,
                                      uint32_t addr) {
    asm volatile("ldmatrix.sync.aligned.m8n8.x4.shared.b16 {%0,%1,%2,%3}, [%4];"
                 : "=r"(r0), "=r"(r1), "=r"(r2), "=r"(r3) : "r"(addr));
}
__device__ __forceinline__ void mma16816(float* c, const uint32_t* a, uint32_t b0, uint32_t b1) {
    asm volatile("mma.sync.aligned.m16n8k16.row.col.f32.bf16.bf16.f32 "
                 "{%0,%1,%2,%3}, {%4,%5,%6,%7}, {%8,%9}, {%0,%1,%2,%3};"
                 : "+f"(c[0]), "+f"(c[1]), "+f"(c[2]), "+f"(c[3])
                 : "r"(a[0]), "r"(a[1]), "r"(a[2]), "r"(a[3]), "r"(b0), "r"(b1));
}
__device__ __forceinline__ void cpasync16(uint32_t dst, const void* src) {
    asm volatile("cp.async.cg.shared.global [%0], [%1], 16;" :: "r"(dst), "l"(src));
}
#define CP_COMMIT() asm volatile("cp.async.commit_group;" ::: "memory")
#define CP_WAIT1()  asm volatile("cp.async.wait_group 1;" ::: "memory")
#define CP_WAIT0()  asm volatile("cp.async.wait_group 0;" ::: "memory")

__device__ __forceinline__ uint32_t pack_bf2(float a, float b) {
    __nv_bfloat162 t = __floats2bfloat162_rn(a, b);
    return *(uint32_t*)&t;
}
__device__ __forceinline__ void split8(const float* s, uint4& hi, uint4& lo) {
    float4 v0 = *(const float4*)s, v1 = *(const float4*)(s + 4);
    float a[8] = {v0.x, v0.y, v0.z, v0.w, v1.x, v1.y, v1.z, v1.w};
    float h[8];
#pragma unroll
    for (int q = 0; q < 8; q++) h[q] = __bfloat162float(__float2bfloat16_rn(a[q]));
    hi = make_uint4(pack_bf2(h[0],h[1]), pack_bf2(h[2],h[3]),
                    pack_bf2(h[4],h[5]), pack_bf2(h[6],h[7]));
    lo = make_uint4(pack_bf2(a[0]-h[0],a[1]-h[1]), pack_bf2(a[2]-h[2],a[3]-h[3]),
                    pack_bf2(a[4]-h[4],a[5]-h[5]), pack_bf2(a[6]-h[6],a[7]-h[7]));
}
__device__ __forceinline__ float fsig(float x) {
    return __fdividef(1.f, 1.f + __expf(-x));
}
__device__ __forceinline__ float ftanh(float x) {
    return __fdividef(2.f, 1.f + __expf(-2.f*x)) - 1.f;
}

// ---------------- 1. gather v_emb[indices] (+ x bf16 hi/lo planes) ----------------
__global__ void k_gather(const int* __restrict__ cur, const int* __restrict__ frd,
                         const float* __restrict__ vemb) {
    int t = blockIdx.x * blockDim.x + threadIdx.x;
    if (t >= NROWS*HH) return;
    int row = t >> 7, col = t & 127;
    int item = (row < CURROWS) ? cur[row] : frd[row - CURROWS];
    float v = vemb[(size_t)item * HH + col];
    g_x[t] = v;
    float h = __bfloat162float(__float2bfloat16_rn(v));
    g_xhi[t] = __float2bfloat16_rn(h);
    g_xlo[t] = __float2bfloat16_rn(v - h);
}

// ---------------- 2. GI GEMM (mma.sync, split-bf16 3-pass) ----------------
#define GI_A     1024
#define GI_BHI   33792
#define GI_BLO   66560
#define GI_TOTAL 99328

__device__ __forceinline__ void gi_prefetch_a(int m0, int c, uint32_t dst, int tid) {
    const __nv_bfloat16* plane = (c & 1) ? g_xlo : g_xhi;
    int kc = c >> 1;
    const char* src = (const char*)plane + (size_t)m0*256 + kc*128;
#pragma unroll
    for (int q = 0; q < 4; q++) {
        int i = tid + q*256;
        int row = i >> 3, j = i & 7;
        cpasync16(dst + SWZ((uint32_t)(row*128 + j*16)), src + (size_t)row*256 + j*16);
    }
}

__global__ void __launch_bounds__(256, 1) k_gi_mma(const float* __restrict__ Wih,
                                                   const float* __restrict__ bih) {
    extern __shared__ char smem[];
    uint32_t sbase = smem_u32(smem);
    int tid = threadIdx.x, lane = tid & 31, wid = tid >> 5;
    int wm = wid & 3, wn = wid >> 2;
    int n0 = blockIdx.x * 128, m0 = blockIdx.y * 128;
    float* bsh = (float*)smem;
    if (tid < 128) bsh[tid] = bih[n0 + tid];

    gi_prefetch_a(m0, 0, sbase + GI_A, tid);
    CP_COMMIT();

    for (int i = tid; i < 128*16; i += 256) {
        int n = i >> 4, j = i & 15;
        uint4 hi, lo;
        split8(Wih + (size_t)(n0+n)*HH + j*8, hi, lo);
        int kc = j >> 3, jj = j & 7;
        uint32_t off = SWZ((uint32_t)(n*128 + jj*16));
        *(uint4*)(smem + GI_BHI + kc*16384 + off) = hi;
        *(uint4*)(smem + GI_BLO + kc*16384 + off) = lo;
    }
    __syncthreads();

    uint32_t abuf0 = sbase + GI_A;
    int arow = wm*32 + (lane & 15);
    uint32_t asel = (uint32_t)((lane >> 4) * 16);
    int bg = lane >> 3, br = lane & 7;
    int bnrow = wn*64 + ((bg >> 1) << 3) + br;
    uint32_t bkb = (uint32_t)((bg & 1) * 16);

    float acc[2][8][4];
#pragma unroll
    for (int u = 0; u < 2; u++)
#pragma unroll
        for (int v = 0; v < 8; v++)
#pragma unroll
            for (int q = 0; q < 4; q++) acc[u][v][q] = 0.f;

    for (int c = 0; c < 4; c++) {
        if (c + 1 < 4) {
            gi_prefetch_a(m0, c + 1, abuf0 + ((c + 1) & 1) * 16384, tid);
            CP_COMMIT();
            CP_WAIT1();
        } else {
            CP_WAIT0();
        }
        __syncthreads();
        int kc = c >> 1;
        uint32_t ab = abuf0 + (c & 1) * 16384;
        uint32_t bhi_b = sbase + GI_BHI + kc*16384;
        uint32_t blo_b = sbase + GI_BLO + kc*16384;
        bool hiA = !(c & 1);
#pragma unroll
        for (int s = 0; s < 4; s++) {
            uint32_t A0[4], A1[4];
            ldsm4(A0[0], A0[1], A0[2], A0[3], ab + SWZ((uint32_t)(arow*128      + s*32) + asel));
            ldsm4(A1[0], A1[1], A1[2], A1[3], ab + SWZ((uint32_t)((arow+16)*128 + s*32) + asel));
            uint32_t Bf[8][2];
#pragma unroll
            for (int nfp = 0; nfp < 4; nfp++) {
                uint32_t b0, b1, b2, b3;
                ldsm4(b0, b1, b2, b3, bhi_b + SWZ((uint32_t)((bnrow + nfp*16)*128 + s*32) + bkb));
                Bf[2*nfp][0] = b0;   Bf[2*nfp][1] = b1;
                Bf[2*nfp+1][0] = b2; Bf[2*nfp+1][1] = b3;
            }
#pragma unroll
            for (int nf = 0; nf < 8; nf++) {
                mma16816(acc[0][nf], A0, Bf[nf][0], Bf[nf][1]);
                mma16816(acc[1][nf], A1, Bf[nf][0], Bf[nf][1]);
            }
            if (hiA) {
#pragma unroll
                for (int nfp = 0; nfp < 4; nfp++) {
                    uint32_t b0, b1, b2, b3;
                    ldsm4(b0, b1, b2, b3, blo_b + SWZ((uint32_t)((bnrow + nfp*16)*128 + s*32) + bkb));
                    Bf[2*nfp][0] = b0;   Bf[2*nfp][1] = b1;
                    Bf[2*nfp+1][0] = b2; Bf[2*nfp+1][1] = b3;
                }
#pragma unroll
                for (int nf = 0; nf < 8; nf++) {
                    mma16816(acc[0][nf], A0, Bf[nf][0], Bf[nf][1]);
                    mma16816(acc[1][nf], A1, Bf[nf][0], Bf[nf][1]);
                }
            }
        }
        __syncthreads();
    }

    int rbase = m0 + wm*32 + (lane >> 2);
    int cq = (lane & 3) * 2;
#pragma unroll
    for (int mf = 0; mf < 2; mf++) {
        int rr = rbase + mf*16;
#pragma unroll
        for (int nf = 0; nf < 8; nf++) {
            int cl = wn*64 + nf*8 + cq;
            float2 v0, v1;
            v0.x = acc[mf][nf][0] + bsh[cl];
            v0.y = acc[mf][nf][1] + bsh[cl+1];
            v1.x = acc[mf][nf][2] + bsh[cl];
            v1.y = acc[mf][nf][3] + bsh[cl+1];
            *(float2*)(g_gi + (size_t)rr*H3 + n0 + cl)     = v0;
            *(float2*)(g_gi + (size_t)(rr+8)*H3 + n0 + cl) = v1;
        }
    }
}

// ---------------- 3. GRU recurrence ----------------
__global__ void k_gru(const float* __restrict__ Whh, const float* __restrict__ bhh) {
    extern __shared__ float sm[];
    float* Wsh  = sm;                    // [384][132]
    float* hsh  = sm + 384*132;          // [5][128]
    float* ghsh = hsh + SEQPB*128;       // [5][384]
    int tid = threadIdx.x;               // 384 threads
    for (int idx = tid; idx < 384*128; idx += 384) {
        int j = idx >> 7, k = idx & 127;
        Wsh[j*132 + k] = Whh[idx];
    }
    int seq0 = blockIdx.x * SEQPB;
    int nseq = NSEQ - seq0; if (nseq > SEQPB) nseq = SEQPB;
    for (int idx = tid; idx < SEQPB*128; idx += 384) hsh[idx] = 0.f;
    __syncthreads();

    int j = tid;
    float bh = bhh[j];
    const float4* w4 = (const float4*)(Wsh + j*132);
    int nel = nseq * 128;

    for (int t = 0; t < 20; t++) {
        float pg[2][3];
#pragma unroll
        for (int e = 0; e < 2; e++) {
            int idx = tid + e*384;
            pg[e][0] = pg[e][1] = pg[e][2] = 0.f;
            if (idx < nel) {
                int i = idx >> 7, jj = idx & 127;
                const float* gir = g_gi + ((size_t)(seq0 + i) * 20 + t) * H3;
                pg[e][0] = gir[jj];
                pg[e][1] = gir[128 + jj];
                pg[e][2] = gir[256 + jj];
            }
        }
        float acc[SEQPB];
#pragma unroll
        for (int i = 0; i < SEQPB; i++) acc[i] = bh;
#pragma unroll 8
        for (int kq = 0; kq < 32; kq++) {
            float4 w = w4[kq];
#pragma unroll
            for (int i = 0; i < SEQPB; i++) {
                float4 h = *(const float4*)(&hsh[i*128 + kq*4]);
                acc[i] += w.x*h.x + w.y*h.y + w.z*h.z + w.w*h.w;
            }
        }
#pragma unroll
        for (int i = 0; i < SEQPB; i++) ghsh[i*H3 + j] = acc[i];
        __syncthreads();
#pragma unroll
        for (int e = 0; e < 2; e++) {
            int idx = tid + e*384;
            if (idx < nel) {
                int i = idx >> 7, jj = idx & 127;
                float r = fsig(pg[e][0] + ghsh[i*H3 + jj]);
                float z = fsig(pg[e][1] + ghsh[i*H3 + 128 + jj]);
                float n = ftanh(pg[e][2] + r * ghsh[i*H3 + 256 + jj]);
                float hprev = hsh[i*128 + jj];
                float h = (1.f - z) * n + z * hprev;
                hsh[i*128 + jj] = h;
                g_hs[((size_t)(seq0 + i) * 20 + t) * HH + jj] = h;
            }
        }
        __syncthreads();
    }
}

// ---------------- 4. fused attention glue: scores..hf..plane split ----------------
// one block per b; replaces k_scores/k_smax_topk/k_wsess/k_hf_acat/k_conv_a
__global__ void __launch_bounds__(256) k_attn(const int* __restrict__ users,
                                              const float* __restrict__ uemb) {
    __shared__ float Qt[HH*TT];      // [k][t]
    __shared__ float Et[HH*LL];      // [k][l]
    __shared__ float Sc[TT*LL];
    __shared__ float simA[SS*TT];    // max_l scores, [s][t]
    __shared__ float sfin[SS*TT];    // final double-masked softmax
    __shared__ float sessS[SS][HH];
    __shared__ float ue[HH];
    __shared__ float dl[LL];
    __shared__ float wsm[LL];
    __shared__ int   presS[SS];

    int b = blockIdx.x;
    int tid = threadIdx.x, lane = tid & 31, w = tid >> 5;

    if (tid < SS) presS[tid] = 0;
    if (tid < HH) ue[tid] = uemb[(size_t)users[b]*HH + tid];
    const float* qsrc = g_hs + (size_t)(b*TT) * HH;
    for (int i = tid; i < TT*HH; i += 256) {
        int t = i >> 7, k = i & 127;
        Qt[k*TT + t] = qsrc[i];
    }
    __syncthreads();

    for (int s = 0; s < SS; s++) {
        const float* esrc = g_hs + (size_t)(CURROWS + (b*SS+s)*LL) * HH;
        for (int i = tid; i < LL*HH; i += 256) {
            int l = i >> 7, k = i & 127;
            Et[k*LL + l] = esrc[i];
        }
        __syncthreads();
        // scores (all 256 threads)
        for (int p = tid; p < TT*LL; p += 256) {
            int t = p / LL, l = p % LL;
            float acc = 0.f;
#pragma unroll 8
            for (int k = 0; k < HH; k++) acc += Qt[k*TT + t] * Et[k*LL + l];
            Sc[p] = acc;
        }
        // wsess dots (warps 0..3)
        const float* F = g_x + (size_t)(CURROWS + (b*SS+s)*LL) * HH;
        if (tid < 128) {
            for (int l = w*5; l < w*5 + 5; l++) {
                float p = 0.f;
#pragma unroll
                for (int k = lane; k < HH; k += 32) p += ue[k] * F[(size_t)l*HH + k];
#pragma unroll
                for (int off = 16; off > 0; off >>= 1) p += __shfl_down_sync(0xffffffff, p, off);
                if (lane == 0) dl[l] = p;
            }
        }
        __syncthreads();
        if (tid < TT) {
            float mx = -INFINITY;
            for (int l = 0; l < LL; l++) mx = fmaxf(mx, Sc[tid*LL + l]);
            simA[s*TT + tid] = mx;
        }
        if (tid == 128) {
            float mx = -INFINITY;
            for (int l = 0; l < LL; l++) mx = fmaxf(mx, dl[l]);
            float sum = 0.f;
            for (int l = 0; l < LL; l++) { wsm[l] = expf(dl[l]-mx); sum += wsm[l]; }
            float inv = 1.f / sum;
            for (int l = 0; l < LL; l++) wsm[l] *= inv;
        }
        __syncthreads();
        if (tid < 128) {
            float acc = 0.f;
#pragma unroll
            for (int l = 0; l < LL; l++) acc += wsm[l] * F[(size_t)l*HH + tid];
            sessS[s][tid] = acc;
        }
        __syncthreads();
    }

    // per-t: softmax over s + top-2 (thread t keeps v[] in regs across the barrier)
    float v[SS];
    if (tid < TT) {
        float mx = -INFINITY;
#pragma unroll
        for (int s = 0; s < SS; s++) { v[s] = simA[s*TT + tid]; mx = fmaxf(mx, v[s]); }
        float sum = 0.f;
#pragma unroll
        for (int s = 0; s < SS; s++) { v[s] = expf(v[s]-mx); sum += v[s]; }
        float inv = 1.f / sum;
#pragma unroll
        for (int s = 0; s < SS; s++) v[s] *= inv;
        int i1 = 0; float b1 = v[0];
#pragma unroll
        for (int s = 1; s < SS; s++) if (v[s] > b1) { b1 = v[s]; i1 = s; }
        int i2 = -1; float b2 = -INFINITY;
#pragma unroll
        for (int s = 0; s < SS; s++) if (s != i1 && v[s] > b2) { b2 = v[s]; i2 = s; }
        atomicOr(&presS[i1], 1);
        atomicOr(&presS[i2], 1);
    }
    __syncthreads();
    if (tid < TT) {
        int m[SS];
#pragma unroll
        for (int s = 0; s < SS; s++) m[s] = presS[s];
        float mx = -INFINITY;
#pragma unroll
        for (int s = 0; s < SS; s++) if (m[s]) mx = fmaxf(mx, v[s]);
        float sum = 0.f; float p[SS];
#pragma unroll
        for (int s = 0; s < SS; s++) { p[s] = m[s] ? expf(v[s]-mx) : 0.f; sum += p[s]; }
        float inv = 1.f / sum;
#pragma unroll
        for (int s = 0; s < SS; s++) p[s] *= inv;
        mx = -INFINITY;
#pragma unroll
        for (int s = 0; s < SS; s++) if (m[s]) mx = fmaxf(mx, p[s]);
        sum = 0.f; float q[SS];
#pragma unroll
        for (int s = 0; s < SS; s++) { q[s] = m[s] ? expf(p[s]-mx) : 0.f; sum += q[s]; }
        inv = 1.f / sum;
#pragma unroll
        for (int s = 0; s < SS; s++) sfin[s*TT + tid] = m[s] ? q[s]*inv : 0.f;
    }
    __syncthreads();

    // hf + write bf16 hi/lo planes for [hs | hf]
    for (int i = tid; i < TT*HH; i += 256) {
        int t = i >> 7, h = i & 127;
        float hf = 0.f;
#pragma unroll
        for (int s = 0; s < SS; s++) hf += sfin[s*TT + t] * sessS[s][h];
        size_t row = (size_t)(b*TT) + t;
        float hs_v = g_hs[row*HH + h];
        float h1 = __bfloat162float(__float2bfloat16_rn(hs_v));
        g_ahi[row*256 + h] = __float2bfloat16_rn(h1);
        g_alo[row*256 + h] = __float2bfloat16_rn(hs_v - h1);
        float h2 = __bfloat162float(__float2bfloat16_rn(hf));
        g_ahi[row*256 + 128 + h] = __float2bfloat16_rn(h2);
        g_alo[row*256 + 128 + h] = __float2bfloat16_rn(hf - h2);
    }
}

// ---------------- 5. mma.sync logits GEMM (ring-3 stage pipeline) ----------------
// stages per M-tile: st0 = a_hi k{0,1}, st1 = a_lo k{0,1}, st2 = a_hi k{2,3}, st3 = a_lo k{2,3}
// a_hi stages multiply vs b_hi AND b_lo; a_lo stages vs b_hi only.
#define SM_A       1024                   // 3 x 32KB stage buffers (= 2 x 16KB chunks each)
#define SM_BHI     99328                  // 4 blocks x 16KB
#define SM_BLO     164864                 // 4 blocks x 16KB (ends 230400)
#define SM_TOTAL   230400

__device__ __forceinline__ void prefetch_stage(int g, uint32_t sbase, int tid) {
    int mt = g >> 2, st = g & 3;
    const __nv_bfloat16* plane = (st & 1) ? g_alo : g_ahi;
    int kpair = st >> 1;
    const char* src = (const char*)plane + (size_t)(mt*128)*512 + kpair*256;
    uint32_t dst = sbase + SM_A + (g % 3) * 32768;
#pragma unroll
    for (int q = 0; q < 8; q++) {
        int i = tid + q*256;              // uint4 index 0..2047 (128 rows x 16)
        int row = i >> 4, j = i & 15;
        int sub = j >> 3, jj = j & 7;
        cpasync16(dst + sub*16384 + SWZ((uint32_t)(row*128 + jj*16)),
                  src + (size_t)row*512 + j*16);
    }
}

__global__ void __launch_bounds__(256, 1) k_out_mma(const float* __restrict__ Wo,
                                                    const float* __restrict__ bo,
                                                    float* __restrict__ out) {
    extern __shared__ char smem[];
    uint32_t sbase = smem_u32(smem);
    int tid = threadIdx.x, lane = tid & 31, wid = tid >> 5;
    int wm = wid & 3, wn = wid >> 2;
    int n0 = blockIdx.x * 128;
    float* bsh = (float*)smem;

    if (tid < 128) bsh[tid] = (n0 + tid < NITEMS) ? bo[n0 + tid] : 0.f;

    prefetch_stage(0, sbase, tid);
    CP_COMMIT();

    // resident B: split Wo (skip hu block) to bf16 hi/lo in smem
    for (int i = tid; i < 128*32; i += 256) {
        int n = i >> 5, j = i & 31;
        int ng = n0 + n;
        uint4 hi = make_uint4(0,0,0,0), lo = make_uint4(0,0,0,0);
        if (ng < NITEMS) {
            int k0 = j * 8;
            int ks = (k0 < 128) ? k0 : k0 + 128;
            split8(Wo + (size_t)ng*H3 + ks, hi, lo);
        }
        int kc = j >> 3, jj = j & 7;
        uint32_t off = SWZ((uint32_t)(n*128 + jj*16));
        *(uint4*)(smem + SM_BHI + kc*16384 + off) = hi;
        *(uint4*)(smem + SM_BLO + kc*16384 + off) = lo;
    }
    __syncthreads();

    int arow = wm*32 + (lane & 15);
    uint32_t asel = (uint32_t)((lane >> 4) * 16);
    int bg = lane >> 3, br = lane & 7;
    int bnrow = wn*64 + ((bg >> 1) << 3) + br;
    uint32_t bkb = (uint32_t)((bg & 1) * 16);

    float acc[2][8][4];
    for (int g = 0; g < 40; g++) {
        int mt = g >> 2, st = g & 3;
        if (st == 0) {
#pragma unroll
            for (int u = 0; u < 2; u++)
#pragma unroll
                for (int v = 0; v < 8; v++)
#pragma unroll
                    for (int q = 0; q < 4; q++) acc[u][v][q] = 0.f;
        }
        if (g + 1 < 40) {
            prefetch_stage(g + 1, sbase, tid);
            CP_COMMIT();
            CP_WAIT1();
        } else {
            CP_WAIT0();
        }
        __syncthreads();

        int kpair = st >> 1;
        bool hiA = !(st & 1);
        uint32_t stbuf = sbase + SM_A + (g % 3) * 32768;
#pragma unroll
        for (int sub = 0; sub < 2; sub++) {
            int kc = kpair*2 + sub;
            uint32_t ab = stbuf + sub*16384;
            uint32_t bhi_b = sbase + SM_BHI + kc*16384;
            uint32_t blo_b = sbase + SM_BLO + kc*16384;
#pragma unroll
            for (int s = 0; s < 4; s++) {
                uint32_t A0[4], A1[4];
                ldsm4(A0[0], A0[1], A0[2], A0[3], ab + SWZ((uint32_t)(arow*128      + s*32) + asel));
                ldsm4(A1[0], A1[1], A1[2], A1[3], ab + SWZ((uint32_t)((arow+16)*128 + s*32) + asel));
                uint32_t Bf[8][2];
#pragma unroll
                for (int nfp = 0; nfp < 4; nfp++) {
                    uint32_t b0, b1, b2, b3;
                    ldsm4(b0, b1, b2, b3, bhi_b + SWZ((uint32_t)((bnrow + nfp*16)*128 + s*32) + bkb));
                    Bf[2*nfp][0] = b0;   Bf[2*nfp][1] = b1;
                    Bf[2*nfp+1][0] = b2; Bf[2*nfp+1][1] = b3;
                }
#pragma unroll
                for (int nf = 0; nf < 8; nf++) {
                    mma16816(acc[0][nf], A0, Bf[nf][0], Bf[nf][1]);
                    mma16816(acc[1][nf], A1, Bf[nf][0], Bf[nf][1]);
                }
                if (hiA) {
#pragma unroll
                    for (int nfp = 0; nfp < 4; nfp++) {
                        uint32_t b0, b1, b2, b3;
                        ldsm4(b0, b1, b2, b3, blo_b + SWZ((uint32_t)((bnrow + nfp*16)*128 + s*32) + bkb));
                        Bf[2*nfp][0] = b0;   Bf[2*nfp][1] = b1;
                        Bf[2*nfp+1][0] = b2; Bf[2*nfp+1][1] = b3;
                    }
#pragma unroll
                    for (int nf = 0; nf < 8; nf++) {
                        mma16816(acc[0][nf], A0, Bf[nf][0], Bf[nf][1]);
                        mma16816(acc[1][nf], A1, Bf[nf][0], Bf[nf][1]);
                    }
                }
            }
        }

        if (st == 3) {
            int rbase = mt*128 + wm*32 + (lane >> 2);
            int cq = (lane & 3) * 2;
#pragma unroll
            for (int mf = 0; mf < 2; mf++) {
                int rr = rbase + mf*16;
#pragma unroll
                for (int nf = 0; nf < 8; nf++) {
                    int cl = wn*64 + nf*8 + cq;
                    int cc = n0 + cl;
                    if (cc < NITEMS) {
                        float2 v0, v1;
                        v0.x = acc[mf][nf][0] + bsh[cl];
                        v0.y = acc[mf][nf][1] + bsh[cl+1];
                        v1.x = acc[mf][nf][2] + bsh[cl];
                        v1.y = acc[mf][nf][3] + bsh[cl+1];
                        *(float2*)(out + (size_t)rr*NITEMS + cc)     = v0;
                        *(float2*)(out + (size_t)(rr+8)*NITEMS + cc) = v1;
                    }
                }
            }
        }
    }
}

// ---------------- launch ----------------
extern "C" void kernel_launch(void* const* d_in, const int* in_sizes, int n_in,
                              void* d_out, int out_size) {
    (void)in_sizes; (void)n_in; (void)out_size;
    const int*   users = (const int*)d_in[0];
    const int*   cur   = (const int*)d_in[1];
    const int*   frds  = (const int*)d_in[3];
    const float* vemb  = (const float*)d_in[5];
    const float* uemb  = (const float*)d_in[6];
    const float* Wih   = (const float*)d_in[7];
    const float* Whh   = (const float*)d_in[8];
    const float* bih   = (const float*)d_in[9];
    const float* bhh   = (const float*)d_in[10];
    const float* Wo    = (const float*)d_in[11];
    const float* bo    = (const float*)d_in[12];
    float* out = (float*)d_out;

    k_gather<<<(NROWS*HH)/256, 256>>>(cur, frds, vemb);

    cudaFuncSetAttribute(k_gi_mma, cudaFuncAttributeMaxDynamicSharedMemorySize, GI_TOTAL);
    k_gi_mma<<<dim3(3, NROWS/128), 256, GI_TOTAL>>>(Wih, bih);

    const int gru_smem = (384*132 + SEQPB*128 + SEQPB*H3) * (int)sizeof(float);
    cudaFuncSetAttribute(k_gru, cudaFuncAttributeMaxDynamicSharedMemorySize, gru_smem);
    k_gru<<<(NSEQ + SEQPB - 1)/SEQPB, 384, gru_smem>>>(Whh, bhh);

    k_attn<<<BB, 256>>>(users, uemb);

    cudaFuncSetAttribute(k_out_mma, cudaFuncAttributeMaxDynamicSharedMemorySize, SM_TOTAL);
    k_out_mma<<<(NITEMS + 127)/128, 256, SM_TOTAL>>>(Wo, bo, out);
}

// round 12
// speedup vs baseline: 2.7101x; 1.0813x over previous
#include <cuda_runtime.h>
#include <cuda_bf16.h>
#include <math.h>
#include <stdint.h>

// ---------------- problem constants ----------------
#define BB      64
#define TT      20
#define SS      10
#define LL      20
#define HH      128
#define H3      384
#define NITEMS  50000
#define CURROWS (BB*TT)          // 1280
#define FRDROWS (BB*SS*LL)       // 12800
#define NROWS   (CURROWS+FRDROWS) // 14080
#define NSEQ    (BB + BB*SS)     // 704
#define SEQPB   5

// ---------------- scratch ----------------
__device__ float g_x[NROWS*HH];
__device__ float g_gi[NROWS*H3];
__device__ float g_hs[NROWS*HH];
__device__ float g_simA[BB*SS*TT];      // [b][s][t] max_l scores
__device__ float g_sessG[BB*SS*HH];
__device__ __align__(16) __nv_bfloat16 g_ahi[CURROWS*256];
__device__ __align__(16) __nv_bfloat16 g_alo[CURROWS*256];
__device__ __align__(16) __nv_bfloat16 g_xhi[NROWS*HH];
__device__ __align__(16) __nv_bfloat16 g_xlo[NROWS*HH];

// ---------------- helpers ----------------
__device__ __forceinline__ uint32_t smem_u32(const void* p) {
    uint32_t a;
    asm("{ .reg .u64 t; cvta.to.shared.u64 t, %1; cvt.u32.u64 %0, t; }" : "=r"(a) : "l"(p));
    return a;
}
#define SWZ(off) ((off) ^ (((off) >> 3) & 0x70))

__device__ __forceinline__ void ldsm4(uint32_t& r0, uint32_t& r1, uint32_t& r2, uint32_t& r3,
                                      uint32_t addr) {
    asm volatile("ldmatrix.sync.aligned.m8n8.x4.shared.b16 {%0,%1,%2,%3}, [%4];"
                 : "=r"(r0), "=r"(r1), "=r"(r2), "=r"(r3) : "r"(addr));
}
__device__ __forceinline__ void mma16816(float* c, const uint32_t* a, uint32_t b0, uint32_t b1) {
    asm volatile("mma.sync.aligned.m16n8k16.row.col.f32.bf16.bf16.f32 "
                 "{%0,%1,%2,%3}, {%4,%5,%6,%7}, {%8,%9}, {%0,%1,%2,%3};"
                 : "+f"(c[0]), "+f"(c[1]), "+f"(c[2]), "+f"(c[3])
                 : "r"(a[0]), "r"(a[1]), "r"(a[2]), "r"(a[3]), "r"(b0), "r"(b1));
}
__device__ __forceinline__ void cpasync16(uint32_t dst, const void* src) {
    asm volatile("cp.async.cg.shared.global [%0], [%1], 16;" :: "r"(dst), "l"(src));
}
#define CP_COMMIT() asm volatile("cp.async.commit_group;" ::: "memory")
#define CP_WAIT1()  asm volatile("cp.async.wait_group 1;" ::: "memory")
#define CP_WAIT0()  asm volatile("cp.async.wait_group 0;" ::: "memory")

__device__ __forceinline__ uint32_t pack_bf2(float a, float b) {
    __nv_bfloat162 t = __floats2bfloat162_rn(a, b);
    return *(uint32_t*)&t;
}
__device__ __forceinline__ void split8(const float* s, uint4& hi, uint4& lo) {
    float4 v0 = *(const float4*)s, v1 = *(const float4*)(s + 4);
    float a[8] = {v0.x, v0.y, v0.z, v0.w, v1.x, v1.y, v1.z, v1.w};
    float h[8];
#pragma unroll
    for (int q = 0; q < 8; q++) h[q] = __bfloat162float(__float2bfloat16_rn(a[q]));
    hi = make_uint4(pack_bf2(h[0],h[1]), pack_bf2(h[2],h[3]),
                    pack_bf2(h[4],h[5]), pack_bf2(h[6],h[7]));
    lo = make_uint4(pack_bf2(a[0]-h[0],a[1]-h[1]), pack_bf2(a[2]-h[2],a[3]-h[3]),
                    pack_bf2(a[4]-h[4],a[5]-h[5]), pack_bf2(a[6]-h[6],a[7]-h[7]));
}
__device__ __forceinline__ float fsig(float x) {
    return __fdividef(1.f, 1.f + __expf(-x));
}
__device__ __forceinline__ float ftanh(float x) {
    return __fdividef(2.f, 1.f + __expf(-2.f*x)) - 1.f;
}

// ---------------- 1. gather ----------------
__global__ void k_gather(const int* __restrict__ cur, const int* __restrict__ frd,
                         const float* __restrict__ vemb) {
    int t = blockIdx.x * blockDim.x + threadIdx.x;
    if (t >= NROWS*HH) return;
    int row = t >> 7, col = t & 127;
    int item = (row < CURROWS) ? cur[row] : frd[row - CURROWS];
    float v = vemb[(size_t)item * HH + col];
    g_x[t] = v;
    float h = __bfloat162float(__float2bfloat16_rn(v));
    g_xhi[t] = __float2bfloat16_rn(h);
    g_xlo[t] = __float2bfloat16_rn(v - h);
}

// ---------------- 2. GI GEMM (mma.sync split-bf16) ----------------
#define GI_A     1024
#define GI_BHI   33792
#define GI_BLO   66560
#define GI_TOTAL 99328

__device__ __forceinline__ void gi_prefetch_a(int m0, int c, uint32_t dst, int tid) {
    const __nv_bfloat16* plane = (c & 1) ? g_xlo : g_xhi;
    int kc = c >> 1;
    const char* src = (const char*)plane + (size_t)m0*256 + kc*128;
#pragma unroll
    for (int q = 0; q < 4; q++) {
        int i = tid + q*256;
        int row = i >> 3, j = i & 7;
        cpasync16(dst + SWZ((uint32_t)(row*128 + j*16)), src + (size_t)row*256 + j*16);
    }
}

__global__ void __launch_bounds__(256, 1) k_gi_mma(const float* __restrict__ Wih,
                                                   const float* __restrict__ bih) {
    extern __shared__ char smem[];
    uint32_t sbase = smem_u32(smem);
    int tid = threadIdx.x, lane = tid & 31, wid = tid >> 5;
    int wm = wid & 3, wn = wid >> 2;
    int n0 = blockIdx.x * 128, m0 = blockIdx.y * 128;
    float* bsh = (float*)smem;
    if (tid < 128) bsh[tid] = bih[n0 + tid];

    gi_prefetch_a(m0, 0, sbase + GI_A, tid);
    CP_COMMIT();

    for (int i = tid; i < 128*16; i += 256) {
        int n = i >> 4, j = i & 15;
        uint4 hi, lo;
        split8(Wih + (size_t)(n0+n)*HH + j*8, hi, lo);
        int kc = j >> 3, jj = j & 7;
        uint32_t off = SWZ((uint32_t)(n*128 + jj*16));
        *(uint4*)(smem + GI_BHI + kc*16384 + off) = hi;
        *(uint4*)(smem + GI_BLO + kc*16384 + off) = lo;
    }
    __syncthreads();

    uint32_t abuf0 = sbase + GI_A;
    int arow = wm*32 + (lane & 15);
    uint32_t asel = (uint32_t)((lane >> 4) * 16);
    int bg = lane >> 3, br = lane & 7;
    int bnrow = wn*64 + ((bg >> 1) << 3) + br;
    uint32_t bkb = (uint32_t)((bg & 1) * 16);

    float acc[2][8][4];
#pragma unroll
    for (int u = 0; u < 2; u++)
#pragma unroll
        for (int v = 0; v < 8; v++)
#pragma unroll
            for (int q = 0; q < 4; q++) acc[u][v][q] = 0.f;

    for (int c = 0; c < 4; c++) {
        if (c + 1 < 4) {
            gi_prefetch_a(m0, c + 1, abuf0 + ((c + 1) & 1) * 16384, tid);
            CP_COMMIT();
            CP_WAIT1();
        } else {
            CP_WAIT0();
        }
        __syncthreads();
        int kc = c >> 1;
        uint32_t ab = abuf0 + (c & 1) * 16384;
        uint32_t bhi_b = sbase + GI_BHI + kc*16384;
        uint32_t blo_b = sbase + GI_BLO + kc*16384;
        bool hiA = !(c & 1);
#pragma unroll
        for (int s = 0; s < 4; s++) {
            uint32_t A0[4], A1[4];
            ldsm4(A0[0], A0[1], A0[2], A0[3], ab + SWZ((uint32_t)(arow*128      + s*32) + asel));
            ldsm4(A1[0], A1[1], A1[2], A1[3], ab + SWZ((uint32_t)((arow+16)*128 + s*32) + asel));
            uint32_t Bf[8][2];
#pragma unroll
            for (int nfp = 0; nfp < 4; nfp++) {
                uint32_t b0, b1, b2, b3;
                ldsm4(b0, b1, b2, b3, bhi_b + SWZ((uint32_t)((bnrow + nfp*16)*128 + s*32) + bkb));
                Bf[2*nfp][0] = b0;   Bf[2*nfp][1] = b1;
                Bf[2*nfp+1][0] = b2; Bf[2*nfp+1][1] = b3;
            }
#pragma unroll
            for (int nf = 0; nf < 8; nf++) {
                mma16816(acc[0][nf], A0, Bf[nf][0], Bf[nf][1]);
                mma16816(acc[1][nf], A1, Bf[nf][0], Bf[nf][1]);
            }
            if (hiA) {
#pragma unroll
                for (int nfp = 0; nfp < 4; nfp++) {
                    uint32_t b0, b1, b2, b3;
                    ldsm4(b0, b1, b2, b3, blo_b + SWZ((uint32_t)((bnrow + nfp*16)*128 + s*32) + bkb));
                    Bf[2*nfp][0] = b0;   Bf[2*nfp][1] = b1;
                    Bf[2*nfp+1][0] = b2; Bf[2*nfp+1][1] = b3;
                }
#pragma unroll
                for (int nf = 0; nf < 8; nf++) {
                    mma16816(acc[0][nf], A0, Bf[nf][0], Bf[nf][1]);
                    mma16816(acc[1][nf], A1, Bf[nf][0], Bf[nf][1]);
                }
            }
        }
        __syncthreads();
    }

    int rbase = m0 + wm*32 + (lane >> 2);
    int cq = (lane & 3) * 2;
#pragma unroll
    for (int mf = 0; mf < 2; mf++) {
        int rr = rbase + mf*16;
#pragma unroll
        for (int nf = 0; nf < 8; nf++) {
            int cl = wn*64 + nf*8 + cq;
            float2 v0, v1;
            v0.x = acc[mf][nf][0] + bsh[cl];
            v0.y = acc[mf][nf][1] + bsh[cl+1];
            v1.x = acc[mf][nf][2] + bsh[cl];
            v1.y = acc[mf][nf][3] + bsh[cl+1];
            *(float2*)(g_gi + (size_t)rr*H3 + n0 + cl)     = v0;
            *(float2*)(g_gi + (size_t)(rr+8)*H3 + n0 + cl) = v1;
        }
    }
}

// ---------------- 3. GRU recurrence (split-K, 768 threads) ----------------
__global__ void k_gru(const float* __restrict__ Whh, const float* __restrict__ bhh) {
    extern __shared__ float sm[];
    float* Wsh = sm;                     // [384][132]
    float* hsh = sm + 384*132;           // [5][128]
    float* gh0 = hsh + SEQPB*128;        // [5][384]
    float* gh1 = gh0 + SEQPB*H3;         // [5][384]
    int tid = threadIdx.x;               // 768 threads
    for (int idx = tid; idx < 384*128; idx += 768) {
        int j = idx >> 7, k = idx & 127;
        Wsh[j*132 + k] = Whh[idx];
    }
    int seq0 = blockIdx.x * SEQPB;
    int nseq = NSEQ - seq0; if (nseq > SEQPB) nseq = SEQPB;
    for (int idx = tid; idx < SEQPB*128; idx += 768) hsh[idx] = 0.f;
    __syncthreads();

    int j = tid % 384, half = tid / 384;     // warp-aligned split (384 = 12 warps)
    float bh = (half == 0) ? bhh[j] : 0.f;
    const float4* w4 = (const float4*)(Wsh + j*132 + half*64);
    float* ghp = half ? gh1 : gh0;
    int nel = nseq * 128;

    for (int t = 0; t < 20; t++) {
        // prefetch this step's gate pre-activations (hidden under phase 1)
        float pg0 = 0.f, pg1 = 0.f, pg2 = 0.f;
        if (tid < nel) {
            int i = tid >> 7, jj = tid & 127;
            const float* gir = g_gi + ((size_t)(seq0 + i) * 20 + t) * H3;
            pg0 = gir[jj]; pg1 = gir[128 + jj]; pg2 = gir[256 + jj];
        }
        // phase 1: 64-wide partial dot
        float acc[SEQPB];
#pragma unroll
        for (int i = 0; i < SEQPB; i++) acc[i] = bh;
#pragma unroll 8
        for (int kq = 0; kq < 16; kq++) {
            float4 w = w4[kq];
#pragma unroll
            for (int i = 0; i < SEQPB; i++) {
                float4 h = *(const float4*)(&hsh[i*128 + half*64 + kq*4]);
                acc[i] += w.x*h.x + w.y*h.y + w.z*h.z + w.w*h.w;
            }
        }
#pragma unroll
        for (int i = 0; i < SEQPB; i++) ghp[i*H3 + j] = acc[i];
        __syncthreads();
        // phase 2: gates + h update (single pass, nel <= 640 < 768)
        if (tid < nel) {
            int i = tid >> 7, jj = tid & 127;
            float ghr = gh0[i*H3 + jj]       + gh1[i*H3 + jj];
            float ghz = gh0[i*H3 + 128 + jj] + gh1[i*H3 + 128 + jj];
            float ghn = gh0[i*H3 + 256 + jj] + gh1[i*H3 + 256 + jj];
            float r = fsig(pg0 + ghr);
            float z = fsig(pg1 + ghz);
            float n = ftanh(pg2 + r * ghn);
            float hprev = hsh[i*128 + jj];
            float h = (1.f - z) * n + z * hprev;
            hsh[i*128 + jj] = h;
            g_hs[((size_t)(seq0 + i) * 20 + t) * HH + jj] = h;
        }
        __syncthreads();
    }
}

// ---------------- 4a. per-(b,s) attention: scores max + wsess session emb ----------------
__global__ void __launch_bounds__(256) k_attn1(const int* __restrict__ users,
                                               const float* __restrict__ uemb) {
    __shared__ float Qt[HH*TT];     // [k][t]
    __shared__ float Et[HH*LL];     // [k][l]
    __shared__ float Fsh[LL*HH];    // [l][h]
    __shared__ float ue[HH];
    __shared__ float Scp[200*4];    // k-split partials
    __shared__ float Sc[TT*LL];
    __shared__ float dl[LL];
    __shared__ float wsm[LL];

    int bs = blockIdx.x;
    int b = bs / SS;
    int tid = threadIdx.x;

    const float* qsrc = g_hs + (size_t)(b*TT) * HH;
    const float* esrc = g_hs + (size_t)(CURROWS + bs*LL) * HH;
    const float* F    = g_x  + (size_t)(CURROWS + bs*LL) * HH;
    for (int i = tid; i < TT*HH; i += 256) {
        int t = i >> 7, k = i & 127;
        Qt[k*TT + t] = qsrc[i];
        Et[k*LL + t] = esrc[i];
        Fsh[i] = F[i];
    }
    if (tid < HH) ue[tid] = uemb[(size_t)users[b]*HH + tid];
    __syncthreads();

    // scores partials (threads 0..199, k-split 2, 2x2 tiles) + wsess dots (200..219)
    if (tid < 200) {
        int kh = tid / 100, tile = tid % 100;
        int a = tile / 10, bb2 = tile % 10;
        float a00 = 0.f, a01 = 0.f, a10 = 0.f, a11 = 0.f;
        int k0 = kh * 64;
#pragma unroll 8
        for (int k = k0; k < k0 + 64; k++) {
            float q0 = Qt[k*TT + 2*a], q1 = Qt[k*TT + 2*a + 1];
            float e0 = Et[k*LL + 2*bb2], e1 = Et[k*LL + 2*bb2 + 1];
            a00 += q0*e0; a01 += q0*e1; a10 += q1*e0; a11 += q1*e1;
        }
        Scp[tid*4+0] = a00; Scp[tid*4+1] = a01; Scp[tid*4+2] = a10; Scp[tid*4+3] = a11;
    } else if (tid < 220) {
        int l = tid - 200;
        float p = 0.f;
#pragma unroll 8
        for (int k = 0; k < HH; k++) p += ue[k] * Fsh[l*HH + k];
        dl[l] = p;
    }
    __syncthreads();

    if (tid < 100) {
        int a = tid / 10, bb2 = tid % 10;
        Sc[(2*a)*LL   + 2*bb2  ] = Scp[tid*4+0] + Scp[(tid+100)*4+0];
        Sc[(2*a)*LL   + 2*bb2+1] = Scp[tid*4+1] + Scp[(tid+100)*4+1];
        Sc[(2*a+1)*LL + 2*bb2  ] = Scp[tid*4+2] + Scp[(tid+100)*4+2];
        Sc[(2*a+1)*LL + 2*bb2+1] = Scp[tid*4+3] + Scp[(tid+100)*4+3];
    }
    if (tid == 128) {
        float mx = -INFINITY;
        for (int l = 0; l < LL; l++) mx = fmaxf(mx, dl[l]);
        float sum = 0.f;
        for (int l = 0; l < LL; l++) { wsm[l] = expf(dl[l]-mx); sum += wsm[l]; }
        float inv = 1.f / sum;
        for (int l = 0; l < LL; l++) wsm[l] *= inv;
    }
    __syncthreads();

    if (tid < TT) {
        float mx = -INFINITY;
        for (int l = 0; l < LL; l++) mx = fmaxf(mx, Sc[tid*LL + l]);
        g_simA[(size_t)bs*TT + tid] = mx;
    }
    if (tid < 128) {
        float acc = 0.f;
#pragma unroll
        for (int l = 0; l < LL; l++) acc += wsm[l] * Fsh[l*HH + tid];
        g_sessG[(size_t)bs*HH + tid] = acc;
    }
}

// ---------------- 4b. per-b combine: softmax-s, top2, masked softmaxes, hf, planes ----------------
__global__ void __launch_bounds__(256) k_attn2() {
    __shared__ float simA[SS*TT];
    __shared__ float sess[SS][HH];
    __shared__ float sfin[SS*TT];
    __shared__ int   presS[SS];
    int b = blockIdx.x;
    int tid = threadIdx.x;

    if (tid < SS) presS[tid] = 0;
    for (int i = tid; i < SS*TT; i += 256) simA[i] = g_simA[(size_t)b*SS*TT + i];
    for (int i = tid; i < SS*HH; i += 256) sess[i >> 7][i & 127] = g_sessG[(size_t)(b*SS)*HH + i];
    __syncthreads();

    float v[SS];
    if (tid < TT) {
        float mx = -INFINITY;
#pragma unroll
        for (int s = 0; s < SS; s++) { v[s] = simA[s*TT + tid]; mx = fmaxf(mx, v[s]); }
        float sum = 0.f;
#pragma unroll
        for (int s = 0; s < SS; s++) { v[s] = expf(v[s]-mx); sum += v[s]; }
        float inv = 1.f / sum;
#pragma unroll
        for (int s = 0; s < SS; s++) v[s] *= inv;
        int i1 = 0; float b1 = v[0];
#pragma unroll
        for (int s = 1; s < SS; s++) if (v[s] > b1) { b1 = v[s]; i1 = s; }
        int i2 = -1; float b2 = -INFINITY;
#pragma unroll
        for (int s = 0; s < SS; s++) if (s != i1 && v[s] > b2) { b2 = v[s]; i2 = s; }
        atomicOr(&presS[i1], 1);
        atomicOr(&presS[i2], 1);
    }
    __syncthreads();
    if (tid < TT) {
        int m[SS];
#pragma unroll
        for (int s = 0; s < SS; s++) m[s] = presS[s];
        float mx = -INFINITY;
#pragma unroll
        for (int s = 0; s < SS; s++) if (m[s]) mx = fmaxf(mx, v[s]);
        float sum = 0.f; float p[SS];
#pragma unroll
        for (int s = 0; s < SS; s++) { p[s] = m[s] ? expf(v[s]-mx) : 0.f; sum += p[s]; }
        float inv = 1.f / sum;
#pragma unroll
        for (int s = 0; s < SS; s++) p[s] *= inv;
        mx = -INFINITY;
#pragma unroll
        for (int s = 0; s < SS; s++) if (m[s]) mx = fmaxf(mx, p[s]);
        sum = 0.f; float q[SS];
#pragma unroll
        for (int s = 0; s < SS; s++) { q[s] = m[s] ? expf(p[s]-mx) : 0.f; sum += q[s]; }
        inv = 1.f / sum;
#pragma unroll
        for (int s = 0; s < SS; s++) sfin[s*TT + tid] = m[s] ? q[s]*inv : 0.f;
    }
    __syncthreads();

    for (int i = tid; i < TT*HH; i += 256) {
        int t = i >> 7, h = i & 127;
        float hf = 0.f;
#pragma unroll
        for (int s = 0; s < SS; s++) hf += sfin[s*TT + t] * sess[s][h];
        size_t row = (size_t)(b*TT) + t;
        float hs_v = g_hs[row*HH + h];
        float h1 = __bfloat162float(__float2bfloat16_rn(hs_v));
        g_ahi[row*256 + h] = __float2bfloat16_rn(h1);
        g_alo[row*256 + h] = __float2bfloat16_rn(hs_v - h1);
        float h2 = __bfloat162float(__float2bfloat16_rn(hf));
        g_ahi[row*256 + 128 + h] = __float2bfloat16_rn(h2);
        g_alo[row*256 + 128 + h] = __float2bfloat16_rn(hf - h2);
    }
}

// ---------------- 5. mma.sync logits GEMM (ring-3 stage pipeline) ----------------
#define SM_A       1024
#define SM_BHI     99328
#define SM_BLO     164864
#define SM_TOTAL   230400

__device__ __forceinline__ void prefetch_stage(int g, uint32_t sbase, int tid) {
    int mt = g >> 2, st = g & 3;
    const __nv_bfloat16* plane = (st & 1) ? g_alo : g_ahi;
    int kpair = st >> 1;
    const char* src = (const char*)plane + (size_t)(mt*128)*512 + kpair*256;
    uint32_t dst = sbase + SM_A + (g % 3) * 32768;
#pragma unroll
    for (int q = 0; q < 8; q++) {
        int i = tid + q*256;
        int row = i >> 4, j = i & 15;
        int sub = j >> 3, jj = j & 7;
        cpasync16(dst + sub*16384 + SWZ((uint32_t)(row*128 + jj*16)),
                  src + (size_t)row*512 + j*16);
    }
}

__global__ void __launch_bounds__(256, 1) k_out_mma(const float* __restrict__ Wo,
                                                    const float* __restrict__ bo,
                                                    float* __restrict__ out) {
    extern __shared__ char smem[];
    uint32_t sbase = smem_u32(smem);
    int tid = threadIdx.x, lane = tid & 31, wid = tid >> 5;
    int wm = wid & 3, wn = wid >> 2;
    int n0 = blockIdx.x * 128;
    float* bsh = (float*)smem;

    if (tid < 128) bsh[tid] = (n0 + tid < NITEMS) ? bo[n0 + tid] : 0.f;

    prefetch_stage(0, sbase, tid);
    CP_COMMIT();

    for (int i = tid; i < 128*32; i += 256) {
        int n = i >> 5, j = i & 31;
        int ng = n0 + n;
        uint4 hi = make_uint4(0,0,0,0), lo = make_uint4(0,0,0,0);
        if (ng < NITEMS) {
            int k0 = j * 8;
            int ks = (k0 < 128) ? k0 : k0 + 128;
            split8(Wo + (size_t)ng*H3 + ks, hi, lo);
        }
        int kc = j >> 3, jj = j & 7;
        uint32_t off = SWZ((uint32_t)(n*128 + jj*16));
        *(uint4*)(smem + SM_BHI + kc*16384 + off) = hi;
        *(uint4*)(smem + SM_BLO + kc*16384 + off) = lo;
    }
    __syncthreads();

    int arow = wm*32 + (lane & 15);
    uint32_t asel = (uint32_t)((lane >> 4) * 16);
    int bg = lane >> 3, br = lane & 7;
    int bnrow = wn*64 + ((bg >> 1) << 3) + br;
    uint32_t bkb = (uint32_t)((bg & 1) * 16);

    float acc[2][8][4];
    for (int g = 0; g < 40; g++) {
        int mt = g >> 2, st = g & 3;
        if (st == 0) {
#pragma unroll
            for (int u = 0; u < 2; u++)
#pragma unroll
                for (int v = 0; v < 8; v++)
#pragma unroll
                    for (int q = 0; q < 4; q++) acc[u][v][q] = 0.f;
        }
        if (g + 1 < 40) {
            prefetch_stage(g + 1, sbase, tid);
            CP_COMMIT();
            CP_WAIT1();
        } else {
            CP_WAIT0();
        }
        __syncthreads();

        int kpair = st >> 1;
        bool hiA = !(st & 1);
        uint32_t stbuf = sbase + SM_A + (g % 3) * 32768;
#pragma unroll
        for (int sub = 0; sub < 2; sub++) {
            int kc = kpair*2 + sub;
            uint32_t ab = stbuf + sub*16384;
            uint32_t bhi_b = sbase + SM_BHI + kc*16384;
            uint32_t blo_b = sbase + SM_BLO + kc*16384;
#pragma unroll
            for (int s = 0; s < 4; s++) {
                uint32_t A0[4], A1[4];
                ldsm4(A0[0], A0[1], A0[2], A0[3], ab + SWZ((uint32_t)(arow*128      + s*32) + asel));
                ldsm4(A1[0], A1[1], A1[2], A1[3], ab + SWZ((uint32_t)((arow+16)*128 + s*32) + asel));
                uint32_t Bf[8][2];
#pragma unroll
                for (int nfp = 0; nfp < 4; nfp++) {
                    uint32_t b0, b1, b2, b3;
                    ldsm4(b0, b1, b2, b3, bhi_b + SWZ((uint32_t)((bnrow + nfp*16)*128 + s*32) + bkb));
                    Bf[2*nfp][0] = b0;   Bf[2*nfp][1] = b1;
                    Bf[2*nfp+1][0] = b2; Bf[2*nfp+1][1] = b3;
                }
#pragma unroll
                for (int nf = 0; nf < 8; nf++) {
                    mma16816(acc[0][nf], A0, Bf[nf][0], Bf[nf][1]);
                    mma16816(acc[1][nf], A1, Bf[nf][0], Bf[nf][1]);
                }
                if (hiA) {
#pragma unroll
                    for (int nfp = 0; nfp < 4; nfp++) {
                        uint32_t b0, b1, b2, b3;
                        ldsm4(b0, b1, b2, b3, blo_b + SWZ((uint32_t)((bnrow + nfp*16)*128 + s*32) + bkb));
                        Bf[2*nfp][0] = b0;   Bf[2*nfp][1] = b1;
                        Bf[2*nfp+1][0] = b2; Bf[2*nfp+1][1] = b3;
                    }
#pragma unroll
                    for (int nf = 0; nf < 8; nf++) {
                        mma16816(acc[0][nf], A0, Bf[nf][0], Bf[nf][1]);
                        mma16816(acc[1][nf], A1, Bf[nf][0], Bf[nf][1]);
                    }
                }
            }
        }

        if (st == 3) {
            int rbase = mt*128 + wm*32 + (lane >> 2);
            int cq = (lane & 3) * 2;
#pragma unroll
            for (int mf = 0; mf < 2; mf++) {
                int rr = rbase + mf*16;
#pragma unroll
                for (int nf = 0; nf < 8; nf++) {
                    int cl = wn*64 + nf*8 + cq;
                    int cc = n0 + cl;
                    if (cc < NITEMS) {
                        float2 v0, v1;
                        v0.x = acc[mf][nf][0] + bsh[cl];
                        v0.y = acc[mf][nf][1] + bsh[cl+1];
                        v1.x = acc[mf][nf][2] + bsh[cl];
                        v1.y = acc[mf][nf][3] + bsh[cl+1];
                        *(float2*)(out + (size_t)rr*NITEMS + cc)     = v0;
                        *(float2*)(out + (size_t)(rr+8)*NITEMS + cc) = v1;
                    }
                }
            }
        }
    }
}

// ---------------- launch ----------------
extern "C" void kernel_launch(void* const* d_in, const int* in_sizes, int n_in,
                              void* d_out, int out_size) {
    (void)in_sizes; (void)n_in; (void)out_size;
    const int*   users = (const int*)d_in[0];
    const int*   cur   = (const int*)d_in[1];
    const int*   frds  = (const int*)d_in[3];
    const float* vemb  = (const float*)d_in[5];
    const float* uemb  = (const float*)d_in[6];
    const float* Wih   = (const float*)d_in[7];
    const float* Whh   = (const float*)d_in[8];
    const float* bih   = (const float*)d_in[9];
    const float* bhh   = (const float*)d_in[10];
    const float* Wo    = (const float*)d_in[11];
    const float* bo    = (const float*)d_in[12];
    float* out = (float*)d_out;

    k_gather<<<(NROWS*HH)/256, 256>>>(cur, frds, vemb);

    cudaFuncSetAttribute(k_gi_mma, cudaFuncAttributeMaxDynamicSharedMemorySize, GI_TOTAL);
    k_gi_mma<<<dim3(3, NROWS/128), 256, GI_TOTAL>>>(Wih, bih);

    const int gru_smem = (384*132 + SEQPB*128 + 2*SEQPB*H3) * (int)sizeof(float); // 220672
    cudaFuncSetAttribute(k_gru, cudaFuncAttributeMaxDynamicSharedMemorySize, gru_smem);
    k_gru<<<(NSEQ + SEQPB - 1)/SEQPB, 768, gru_smem>>>(Whh, bhh);

    k_attn1<<<BB*SS, 256>>>(users, uemb);
    k_attn2<<<BB, 256>>>();

    cudaFuncSetAttribute(k_out_mma, cudaFuncAttributeMaxDynamicSharedMemorySize, SM_TOTAL);
    k_out_mma<<<(NITEMS + 127)/128, 256, SM_TOTAL>>>(Wo, bo, out);
}

// round 13
// speedup vs baseline: 3.2130x; 1.1856x over previous
#include <cuda_runtime.h>
#include <cuda_bf16.h>
#include <cuda_fp16.h>
#include <math.h>
#include <stdint.h>

// ---------------- problem constants ----------------
#define BB      64
#define TT      20
#define SS      10
#define LL      20
#define HH      128
#define H3      384
#define NITEMS  50000
#define CURROWS (BB*TT)          // 1280
#define FRDROWS (BB*SS*LL)       // 12800
#define NROWS   (CURROWS+FRDROWS) // 14080
#define NSEQ    (BB + BB*SS)     // 704
#define SEQPB   5

// ---------------- scratch ----------------
__device__ float g_x[NROWS*HH];
__device__ float g_gi[NROWS*H3];
__device__ float g_hs[NROWS*HH];
__device__ float g_simA[BB*SS*TT];      // [b][s][t] max_l scores
__device__ float g_sessG[BB*SS*HH];
// fp16 split planes for logits GEMM A (exact to ~2^-22)
__device__ __align__(16) __half g_ahi[CURROWS*256];
__device__ __align__(16) __half g_alo[CURROWS*256];
// bf16 planes for GI GEMM
__device__ __align__(16) __nv_bfloat16 g_xhi[NROWS*HH];
__device__ __align__(16) __nv_bfloat16 g_xlo[NROWS*HH];

// ---------------- helpers ----------------
__device__ __forceinline__ uint32_t smem_u32(const void* p) {
    uint32_t a;
    asm("{ .reg .u64 t; cvta.to.shared.u64 t, %1; cvt.u32.u64 %0, t; }" : "=r"(a) : "l"(p));
    return a;
}
#define SWZ(off) ((off) ^ (((off) >> 3) & 0x70))

__device__ __forceinline__ void ldsm4(uint32_t& r0, uint32_t& r1, uint32_t& r2, uint32_t& r3,
                                      uint32_t addr) {
    asm volatile("ldmatrix.sync.aligned.m8n8.x4.shared.b16 {%0,%1,%2,%3}, [%4];"
                 : "=r"(r0), "=r"(r1), "=r"(r2), "=r"(r3) : "r"(addr));
}
__device__ __forceinline__ void mma16816(float* c, const uint32_t* a, uint32_t b0, uint32_t b1) {
    asm volatile("mma.sync.aligned.m16n8k16.row.col.f32.bf16.bf16.f32 "
                 "{%0,%1,%2,%3}, {%4,%5,%6,%7}, {%8,%9}, {%0,%1,%2,%3};"
                 : "+f"(c[0]), "+f"(c[1]), "+f"(c[2]), "+f"(c[3])
                 : "r"(a[0]), "r"(a[1]), "r"(a[2]), "r"(a[3]), "r"(b0), "r"(b1));
}
__device__ __forceinline__ void mma16816h(float* c, const uint32_t* a, uint32_t b0, uint32_t b1) {
    asm volatile("mma.sync.aligned.m16n8k16.row.col.f32.f16.f16.f32 "
                 "{%0,%1,%2,%3}, {%4,%5,%6,%7}, {%8,%9}, {%0,%1,%2,%3};"
                 : "+f"(c[0]), "+f"(c[1]), "+f"(c[2]), "+f"(c[3])
                 : "r"(a[0]), "r"(a[1]), "r"(a[2]), "r"(a[3]), "r"(b0), "r"(b1));
}
__device__ __forceinline__ void cpasync16(uint32_t dst, const void* src) {
    asm volatile("cp.async.cg.shared.global [%0], [%1], 16;" :: "r"(dst), "l"(src));
}
#define CP_COMMIT() asm volatile("cp.async.commit_group;" ::: "memory")
#define CP_WAIT1()  asm volatile("cp.async.wait_group 1;" ::: "memory")
#define CP_WAIT0()  asm volatile("cp.async.wait_group 0;" ::: "memory")

__device__ __forceinline__ uint32_t pack_bf2(float a, float b) {
    __nv_bfloat162 t = __floats2bfloat162_rn(a, b);
    return *(uint32_t*)&t;
}
__device__ __forceinline__ uint32_t pack_hf2(float a, float b) {
    __half2 t = __floats2half2_rn(a, b);
    return *(uint32_t*)&t;
}
__device__ __forceinline__ void split8(const float* s, uint4& hi, uint4& lo) {
    float4 v0 = *(const float4*)s, v1 = *(const float4*)(s + 4);
    float a[8] = {v0.x, v0.y, v0.z, v0.w, v1.x, v1.y, v1.z, v1.w};
    float h[8];
#pragma unroll
    for (int q = 0; q < 8; q++) h[q] = __bfloat162float(__float2bfloat16_rn(a[q]));
    hi = make_uint4(pack_bf2(h[0],h[1]), pack_bf2(h[2],h[3]),
                    pack_bf2(h[4],h[5]), pack_bf2(h[6],h[7]));
    lo = make_uint4(pack_bf2(a[0]-h[0],a[1]-h[1]), pack_bf2(a[2]-h[2],a[3]-h[3]),
                    pack_bf2(a[4]-h[4],a[5]-h[5]), pack_bf2(a[6]-h[6],a[7]-h[7]));
}
// fp16 convert of 8 floats (single plane, for B of logits GEMM)
__device__ __forceinline__ uint4 cvt8h(const float* s) {
    float4 v0 = *(const float4*)s, v1 = *(const float4*)(s + 4);
    return make_uint4(pack_hf2(v0.x, v0.y), pack_hf2(v0.z, v0.w),
                      pack_hf2(v1.x, v1.y), pack_hf2(v1.z, v1.w));
}
__device__ __forceinline__ float fsig(float x) {
    return __fdividef(1.f, 1.f + __expf(-x));
}
__device__ __forceinline__ float ftanh(float x) {
    return __fdividef(2.f, 1.f + __expf(-2.f*x)) - 1.f;
}

// ---------------- 1. gather ----------------
__global__ void k_gather(const int* __restrict__ cur, const int* __restrict__ frd,
                         const float* __restrict__ vemb) {
    int t = blockIdx.x * blockDim.x + threadIdx.x;
    if (t >= NROWS*HH) return;
    int row = t >> 7, col = t & 127;
    int item = (row < CURROWS) ? cur[row] : frd[row - CURROWS];
    float v = vemb[(size_t)item * HH + col];
    g_x[t] = v;
    float h = __bfloat162float(__float2bfloat16_rn(v));
    g_xhi[t] = __float2bfloat16_rn(h);
    g_xlo[t] = __float2bfloat16_rn(v - h);
}

// ---------------- 2. GI GEMM (mma.sync split-bf16 3-pass) ----------------
#define GI_A     1024
#define GI_BHI   33792
#define GI_BLO   66560
#define GI_TOTAL 99328

__device__ __forceinline__ void gi_prefetch_a(int m0, int c, uint32_t dst, int tid) {
    const __nv_bfloat16* plane = (c & 1) ? g_xlo : g_xhi;
    int kc = c >> 1;
    const char* src = (const char*)plane + (size_t)m0*256 + kc*128;
#pragma unroll
    for (int q = 0; q < 4; q++) {
        int i = tid + q*256;
        int row = i >> 3, j = i & 7;
        cpasync16(dst + SWZ((uint32_t)(row*128 + j*16)), src + (size_t)row*256 + j*16);
    }
}

__global__ void __launch_bounds__(256, 1) k_gi_mma(const float* __restrict__ Wih,
                                                   const float* __restrict__ bih) {
    extern __shared__ char smem[];
    uint32_t sbase = smem_u32(smem);
    int tid = threadIdx.x, lane = tid & 31, wid = tid >> 5;
    int wm = wid & 3, wn = wid >> 2;
    int n0 = blockIdx.x * 128, m0 = blockIdx.y * 128;
    float* bsh = (float*)smem;
    if (tid < 128) bsh[tid] = bih[n0 + tid];

    gi_prefetch_a(m0, 0, sbase + GI_A, tid);
    CP_COMMIT();

    for (int i = tid; i < 128*16; i += 256) {
        int n = i >> 4, j = i & 15;
        uint4 hi, lo;
        split8(Wih + (size_t)(n0+n)*HH + j*8, hi, lo);
        int kc = j >> 3, jj = j & 7;
        uint32_t off = SWZ((uint32_t)(n*128 + jj*16));
        *(uint4*)(smem + GI_BHI + kc*16384 + off) = hi;
        *(uint4*)(smem + GI_BLO + kc*16384 + off) = lo;
    }
    __syncthreads();

    uint32_t abuf0 = sbase + GI_A;
    int arow = wm*32 + (lane & 15);
    uint32_t asel = (uint32_t)((lane >> 4) * 16);
    int bg = lane >> 3, br = lane & 7;
    int bnrow = wn*64 + ((bg >> 1) << 3) + br;
    uint32_t bkb = (uint32_t)((bg & 1) * 16);

    float acc[2][8][4];
#pragma unroll
    for (int u = 0; u < 2; u++)
#pragma unroll
        for (int v = 0; v < 8; v++)
#pragma unroll
            for (int q = 0; q < 4; q++) acc[u][v][q] = 0.f;

    for (int c = 0; c < 4; c++) {
        if (c + 1 < 4) {
            gi_prefetch_a(m0, c + 1, abuf0 + ((c + 1) & 1) * 16384, tid);
            CP_COMMIT();
            CP_WAIT1();
        } else {
            CP_WAIT0();
        }
        __syncthreads();
        int kc = c >> 1;
        uint32_t ab = abuf0 + (c & 1) * 16384;
        uint32_t bhi_b = sbase + GI_BHI + kc*16384;
        uint32_t blo_b = sbase + GI_BLO + kc*16384;
        bool hiA = !(c & 1);
#pragma unroll
        for (int s = 0; s < 4; s++) {
            uint32_t A0[4], A1[4];
            ldsm4(A0[0], A0[1], A0[2], A0[3], ab + SWZ((uint32_t)(arow*128      + s*32) + asel));
            ldsm4(A1[0], A1[1], A1[2], A1[3], ab + SWZ((uint32_t)((arow+16)*128 + s*32) + asel));
            uint32_t Bf[8][2];
#pragma unroll
            for (int nfp = 0; nfp < 4; nfp++) {
                uint32_t b0, b1, b2, b3;
                ldsm4(b0, b1, b2, b3, bhi_b + SWZ((uint32_t)((bnrow + nfp*16)*128 + s*32) + bkb));
                Bf[2*nfp][0] = b0;   Bf[2*nfp][1] = b1;
                Bf[2*nfp+1][0] = b2; Bf[2*nfp+1][1] = b3;
            }
#pragma unroll
            for (int nf = 0; nf < 8; nf++) {
                mma16816(acc[0][nf], A0, Bf[nf][0], Bf[nf][1]);
                mma16816(acc[1][nf], A1, Bf[nf][0], Bf[nf][1]);
            }
            if (hiA) {
#pragma unroll
                for (int nfp = 0; nfp < 4; nfp++) {
                    uint32_t b0, b1, b2, b3;
                    ldsm4(b0, b1, b2, b3, blo_b + SWZ((uint32_t)((bnrow + nfp*16)*128 + s*32) + bkb));
                    Bf[2*nfp][0] = b0;   Bf[2*nfp][1] = b1;
                    Bf[2*nfp+1][0] = b2; Bf[2*nfp+1][1] = b3;
                }
#pragma unroll
                for (int nf = 0; nf < 8; nf++) {
                    mma16816(acc[0][nf], A0, Bf[nf][0], Bf[nf][1]);
                    mma16816(acc[1][nf], A1, Bf[nf][0], Bf[nf][1]);
                }
            }
        }
        __syncthreads();
    }

    int rbase = m0 + wm*32 + (lane >> 2);
    int cq = (lane & 3) * 2;
#pragma unroll
    for (int mf = 0; mf < 2; mf++) {
        int rr = rbase + mf*16;
#pragma unroll
        for (int nf = 0; nf < 8; nf++) {
            int cl = wn*64 + nf*8 + cq;
            float2 v0, v1;
            v0.x = acc[mf][nf][0] + bsh[cl];
            v0.y = acc[mf][nf][1] + bsh[cl+1];
            v1.x = acc[mf][nf][2] + bsh[cl];
            v1.y = acc[mf][nf][3] + bsh[cl+1];
            *(float2*)(g_gi + (size_t)rr*H3 + n0 + cl)     = v0;
            *(float2*)(g_gi + (size_t)(rr+8)*H3 + n0 + cl) = v1;
        }
    }
}

// ---------------- 3. GRU recurrence (split-K, 768 threads) ----------------
__global__ void k_gru(const float* __restrict__ Whh, const float* __restrict__ bhh) {
    extern __shared__ float sm[];
    float* Wsh = sm;                     // [384][132]
    float* hsh = sm + 384*132;           // [5][128]
    float* gh0 = hsh + SEQPB*128;        // [5][384]
    float* gh1 = gh0 + SEQPB*H3;         // [5][384]
    int tid = threadIdx.x;               // 768 threads
    for (int idx = tid; idx < 384*128; idx += 768) {
        int j = idx >> 7, k = idx & 127;
        Wsh[j*132 + k] = Whh[idx];
    }
    int seq0 = blockIdx.x * SEQPB;
    int nseq = NSEQ - seq0; if (nseq > SEQPB) nseq = SEQPB;
    for (int idx = tid; idx < SEQPB*128; idx += 768) hsh[idx] = 0.f;
    __syncthreads();

    int j = tid % 384, half = tid / 384;
    float bh = (half == 0) ? bhh[j] : 0.f;
    const float4* w4 = (const float4*)(Wsh + j*132 + half*64);
    float* ghp = half ? gh1 : gh0;
    int nel = nseq * 128;

    for (int t = 0; t < 20; t++) {
        float pg0 = 0.f, pg1 = 0.f, pg2 = 0.f;
        if (tid < nel) {
            int i = tid >> 7, jj = tid & 127;
            const float* gir = g_gi + ((size_t)(seq0 + i) * 20 + t) * H3;
            pg0 = gir[jj]; pg1 = gir[128 + jj]; pg2 = gir[256 + jj];
        }
        float acc[SEQPB];
#pragma unroll
        for (int i = 0; i < SEQPB; i++) acc[i] = bh;
#pragma unroll 8
        for (int kq = 0; kq < 16; kq++) {
            float4 w = w4[kq];
#pragma unroll
            for (int i = 0; i < SEQPB; i++) {
                float4 h = *(const float4*)(&hsh[i*128 + half*64 + kq*4]);
                acc[i] += w.x*h.x + w.y*h.y + w.z*h.z + w.w*h.w;
            }
        }
#pragma unroll
        for (int i = 0; i < SEQPB; i++) ghp[i*H3 + j] = acc[i];
        __syncthreads();
        if (tid < nel) {
            int i = tid >> 7, jj = tid & 127;
            float ghr = gh0[i*H3 + jj]       + gh1[i*H3 + jj];
            float ghz = gh0[i*H3 + 128 + jj] + gh1[i*H3 + 128 + jj];
            float ghn = gh0[i*H3 + 256 + jj] + gh1[i*H3 + 256 + jj];
            float r = fsig(pg0 + ghr);
            float z = fsig(pg1 + ghz);
            float n = ftanh(pg2 + r * ghn);
            float hprev = hsh[i*128 + jj];
            float h = (1.f - z) * n + z * hprev;
            hsh[i*128 + jj] = h;
            g_hs[((size_t)(seq0 + i) * 20 + t) * HH + jj] = h;
        }
        __syncthreads();
    }
}

// ---------------- 4a. per-(b,s) attention: scores max + wsess session emb ----------------
__global__ void __launch_bounds__(256) k_attn1(const int* __restrict__ users,
                                               const float* __restrict__ uemb) {
    __shared__ float Qt[HH*TT];
    __shared__ float Et[HH*LL];
    __shared__ float Fsh[LL*HH];
    __shared__ float ue[HH];
    __shared__ float Scp[200*4];
    __shared__ float Sc[TT*LL];
    __shared__ float dl[LL];
    __shared__ float wsm[LL];

    int bs = blockIdx.x;
    int b = bs / SS;
    int tid = threadIdx.x;

    const float* qsrc = g_hs + (size_t)(b*TT) * HH;
    const float* esrc = g_hs + (size_t)(CURROWS + bs*LL) * HH;
    const float* F    = g_x  + (size_t)(CURROWS + bs*LL) * HH;
    for (int i = tid; i < TT*HH; i += 256) {
        int t = i >> 7, k = i & 127;
        Qt[k*TT + t] = qsrc[i];
        Et[k*LL + t] = esrc[i];
        Fsh[i] = F[i];
    }
    if (tid < HH) ue[tid] = uemb[(size_t)users[b]*HH + tid];
    __syncthreads();

    if (tid < 200) {
        int kh = tid / 100, tile = tid % 100;
        int a = tile / 10, bb2 = tile % 10;
        float a00 = 0.f, a01 = 0.f, a10 = 0.f, a11 = 0.f;
        int k0 = kh * 64;
#pragma unroll 8
        for (int k = k0; k < k0 + 64; k++) {
            float q0 = Qt[k*TT + 2*a], q1 = Qt[k*TT + 2*a + 1];
            float e0 = Et[k*LL + 2*bb2], e1 = Et[k*LL + 2*bb2 + 1];
            a00 += q0*e0; a01 += q0*e1; a10 += q1*e0; a11 += q1*e1;
        }
        Scp[tid*4+0] = a00; Scp[tid*4+1] = a01; Scp[tid*4+2] = a10; Scp[tid*4+3] = a11;
    } else if (tid < 220) {
        int l = tid - 200;
        float p = 0.f;
#pragma unroll 8
        for (int k = 0; k < HH; k++) p += ue[k] * Fsh[l*HH + k];
        dl[l] = p;
    }
    __syncthreads();

    if (tid < 100) {
        int a = tid / 10, bb2 = tid % 10;
        Sc[(2*a)*LL   + 2*bb2  ] = Scp[tid*4+0] + Scp[(tid+100)*4+0];
        Sc[(2*a)*LL   + 2*bb2+1] = Scp[tid*4+1] + Scp[(tid+100)*4+1];
        Sc[(2*a+1)*LL + 2*bb2  ] = Scp[tid*4+2] + Scp[(tid+100)*4+2];
        Sc[(2*a+1)*LL + 2*bb2+1] = Scp[tid*4+3] + Scp[(tid+100)*4+3];
    }
    if (tid == 128) {
        float mx = -INFINITY;
        for (int l = 0; l < LL; l++) mx = fmaxf(mx, dl[l]);
        float sum = 0.f;
        for (int l = 0; l < LL; l++) { wsm[l] = expf(dl[l]-mx); sum += wsm[l]; }
        float inv = 1.f / sum;
        for (int l = 0; l < LL; l++) wsm[l] *= inv;
    }
    __syncthreads();

    if (tid < TT) {
        float mx = -INFINITY;
        for (int l = 0; l < LL; l++) mx = fmaxf(mx, Sc[tid*LL + l]);
        g_simA[(size_t)bs*TT + tid] = mx;
    }
    if (tid < 128) {
        float acc = 0.f;
#pragma unroll
        for (int l = 0; l < LL; l++) acc += wsm[l] * Fsh[l*HH + tid];
        g_sessG[(size_t)bs*HH + tid] = acc;
    }
}

// ---------------- 4b. per-b combine -> fp16 hi/lo A planes ----------------
__global__ void __launch_bounds__(256) k_attn2() {
    __shared__ float simA[SS*TT];
    __shared__ float sess[SS][HH];
    __shared__ float sfin[SS*TT];
    __shared__ int   presS[SS];
    int b = blockIdx.x;
    int tid = threadIdx.x;

    if (tid < SS) presS[tid] = 0;
    for (int i = tid; i < SS*TT; i += 256) simA[i] = g_simA[(size_t)b*SS*TT + i];
    for (int i = tid; i < SS*HH; i += 256) sess[i >> 7][i & 127] = g_sessG[(size_t)(b*SS)*HH + i];
    __syncthreads();

    float v[SS];
    if (tid < TT) {
        float mx = -INFINITY;
#pragma unroll
        for (int s = 0; s < SS; s++) { v[s] = simA[s*TT + tid]; mx = fmaxf(mx, v[s]); }
        float sum = 0.f;
#pragma unroll
        for (int s = 0; s < SS; s++) { v[s] = expf(v[s]-mx); sum += v[s]; }
        float inv = 1.f / sum;
#pragma unroll
        for (int s = 0; s < SS; s++) v[s] *= inv;
        int i1 = 0; float b1 = v[0];
#pragma unroll
        for (int s = 1; s < SS; s++) if (v[s] > b1) { b1 = v[s]; i1 = s; }
        int i2 = -1; float b2 = -INFINITY;
#pragma unroll
        for (int s = 0; s < SS; s++) if (s != i1 && v[s] > b2) { b2 = v[s]; i2 = s; }
        atomicOr(&presS[i1], 1);
        atomicOr(&presS[i2], 1);
    }
    __syncthreads();
    if (tid < TT) {
        int m[SS];
#pragma unroll
        for (int s = 0; s < SS; s++) m[s] = presS[s];
        float mx = -INFINITY;
#pragma unroll
        for (int s = 0; s < SS; s++) if (m[s]) mx = fmaxf(mx, v[s]);
        float sum = 0.f; float p[SS];
#pragma unroll
        for (int s = 0; s < SS; s++) { p[s] = m[s] ? expf(v[s]-mx) : 0.f; sum += p[s]; }
        float inv = 1.f / sum;
#pragma unroll
        for (int s = 0; s < SS; s++) p[s] *= inv;
        mx = -INFINITY;
#pragma unroll
        for (int s = 0; s < SS; s++) if (m[s]) mx = fmaxf(mx, p[s]);
        sum = 0.f; float q[SS];
#pragma unroll
        for (int s = 0; s < SS; s++) { q[s] = m[s] ? expf(p[s]-mx) : 0.f; sum += q[s]; }
        inv = 1.f / sum;
#pragma unroll
        for (int s = 0; s < SS; s++) sfin[s*TT + tid] = m[s] ? q[s]*inv : 0.f;
    }
    __syncthreads();

    for (int i = tid; i < TT*HH; i += 256) {
        int t = i >> 7, h = i & 127;
        float hf = 0.f;
#pragma unroll
        for (int s = 0; s < SS; s++) hf += sfin[s*TT + t] * sess[s][h];
        size_t row = (size_t)(b*TT) + t;
        float hs_v = g_hs[row*HH + h];
        __half h1 = __float2half_rn(hs_v);
        g_ahi[row*256 + h] = h1;
        g_alo[row*256 + h] = __float2half_rn(hs_v - __half2float(h1));
        __half h2 = __float2half_rn(hf);
        g_ahi[row*256 + 128 + h] = h2;
        g_alo[row*256 + 128 + h] = __float2half_rn(hf - __half2float(h2));
    }
}

// ---------------- 5. fp16 2-pass mma.sync logits GEMM ----------------
// D = A_hi*B_hi + A_lo*B_hi = A*B_hi ; error = A*B_lo ~ 2^-12 relative.
// stages per M-tile: st0 = a_hi k{0,1}, st1 = a_hi k{2,3}, st2 = a_lo k{0,1}, st3 = a_lo k{2,3}
#define SM_A       1024                   // 3 x 32KB ring stages
#define SM_BHI     99328                  // 4 blocks x 16KB (fp16 B, ends 164864)
#define SM_TOTAL   164864

__device__ __forceinline__ void prefetch_stage(int g, uint32_t sbase, int tid) {
    int mt = g >> 2, st = g & 3;
    const __half* plane = (st >> 1) ? g_alo : g_ahi;
    int kpair = st & 1;
    const char* src = (const char*)plane + (size_t)(mt*128)*512 + kpair*256;
    uint32_t dst = sbase + SM_A + (g % 3) * 32768;
#pragma unroll
    for (int q = 0; q < 8; q++) {
        int i = tid + q*256;
        int row = i >> 4, j = i & 15;
        int sub = j >> 3, jj = j & 7;
        cpasync16(dst + sub*16384 + SWZ((uint32_t)(row*128 + jj*16)),
                  src + (size_t)row*512 + j*16);
    }
}

__global__ void __launch_bounds__(256, 1) k_out_mma(const float* __restrict__ Wo,
                                                    const float* __restrict__ bo,
                                                    float* __restrict__ out) {
    extern __shared__ char smem[];
    uint32_t sbase = smem_u32(smem);
    int tid = threadIdx.x, lane = tid & 31, wid = tid >> 5;
    int wm = wid & 3, wn = wid >> 2;
    int n0 = blockIdx.x * 128;
    float* bsh = (float*)smem;

    if (tid < 128) bsh[tid] = (n0 + tid < NITEMS) ? bo[n0 + tid] : 0.f;

    prefetch_stage(0, sbase, tid);
    CP_COMMIT();

    // resident B: fp16 single plane of Wo (skip hu block)
    for (int i = tid; i < 128*32; i += 256) {
        int n = i >> 5, j = i & 31;
        int ng = n0 + n;
        uint4 hv = make_uint4(0,0,0,0);
        if (ng < NITEMS) {
            int k0 = j * 8;
            int ks = (k0 < 128) ? k0 : k0 + 128;
            hv = cvt8h(Wo + (size_t)ng*H3 + ks);
        }
        int kc = j >> 3, jj = j & 7;
        *(uint4*)(smem + SM_BHI + kc*16384 + SWZ((uint32_t)(n*128 + jj*16))) = hv;
    }
    __syncthreads();

    int arow = wm*32 + (lane & 15);
    uint32_t asel = (uint32_t)((lane >> 4) * 16);
    int bg = lane >> 3, br = lane & 7;
    int bnrow = wn*64 + ((bg >> 1) << 3) + br;
    uint32_t bkb = (uint32_t)((bg & 1) * 16);

    float acc[2][8][4];
    for (int g = 0; g < 40; g++) {
        int mt = g >> 2, st = g & 3;
        if (st == 0) {
#pragma unroll
            for (int u = 0; u < 2; u++)
#pragma unroll
                for (int v = 0; v < 8; v++)
#pragma unroll
                    for (int q = 0; q < 4; q++) acc[u][v][q] = 0.f;
        }
        if (g + 1 < 40) {
            prefetch_stage(g + 1, sbase, tid);
            CP_COMMIT();
            CP_WAIT1();
        } else {
            CP_WAIT0();
        }
        __syncthreads();

        int kpair = st & 1;
        uint32_t stbuf = sbase + SM_A + (g % 3) * 32768;
#pragma unroll
        for (int sub = 0; sub < 2; sub++) {
            int kc = kpair*2 + sub;
            uint32_t ab = stbuf + sub*16384;
            uint32_t bb = sbase + SM_BHI + kc*16384;
#pragma unroll
            for (int s = 0; s < 4; s++) {
                uint32_t A0[4], A1[4];
                ldsm4(A0[0], A0[1], A0[2], A0[3], ab + SWZ((uint32_t)(arow*128      + s*32) + asel));
                ldsm4(A1[0], A1[1], A1[2], A1[3], ab + SWZ((uint32_t)((arow+16)*128 + s*32) + asel));
                uint32_t Bf[8][2];
#pragma unroll
                for (int nfp = 0; nfp < 4; nfp++) {
                    uint32_t b0, b1, b2, b3;
                    ldsm4(b0, b1, b2, b3, bb + SWZ((uint32_t)((bnrow + nfp*16)*128 + s*32) + bkb));
                    Bf[2*nfp][0] = b0;   Bf[2*nfp][1] = b1;
                    Bf[2*nfp+1][0] = b2; Bf[2*nfp+1][1] = b3;
                }
#pragma unroll
                for (int nf = 0; nf < 8; nf++) {
                    mma16816h(acc[0][nf], A0, Bf[nf][0], Bf[nf][1]);
                    mma16816h(acc[1][nf], A1, Bf[nf][0], Bf[nf][1]);
                }
            }
        }

        if (st == 3) {
            int rbase = mt*128 + wm*32 + (lane >> 2);
            int cq = (lane & 3) * 2;
#pragma unroll
            for (int mf = 0; mf < 2; mf++) {
                int rr = rbase + mf*16;
#pragma unroll
                for (int nf = 0; nf < 8; nf++) {
                    int cl = wn*64 + nf*8 + cq;
                    int cc = n0 + cl;
                    if (cc < NITEMS) {
                        float2 v0, v1;
                        v0.x = acc[mf][nf][0] + bsh[cl];
                        v0.y = acc[mf][nf][1] + bsh[cl+1];
                        v1.x = acc[mf][nf][2] + bsh[cl];
                        v1.y = acc[mf][nf][3] + bsh[cl+1];
                        *(float2*)(out + (size_t)rr*NITEMS + cc)     = v0;
                        *(float2*)(out + (size_t)(rr+8)*NITEMS + cc) = v1;
                    }
                }
            }
        }
    }
}

// ---------------- launch ----------------
extern "C" void kernel_launch(void* const* d_in, const int* in_sizes, int n_in,
                              void* d_out, int out_size) {
    (void)in_sizes; (void)n_in; (void)out_size;
    const int*   users = (const int*)d_in[0];
    const int*   cur   = (const int*)d_in[1];
    const int*   frds  = (const int*)d_in[3];
    const float* vemb  = (const float*)d_in[5];
    const float* uemb  = (const float*)d_in[6];
    const float* Wih   = (const float*)d_in[7];
    const float* Whh   = (const float*)d_in[8];
    const float* bih   = (const float*)d_in[9];
    const float* bhh   = (const float*)d_in[10];
    const float* Wo    = (const float*)d_in[11];
    const float* bo    = (const float*)d_in[12];
    float* out = (float*)d_out;

    k_gather<<<(NROWS*HH)/256, 256>>>(cur, frds, vemb);

    cudaFuncSetAttribute(k_gi_mma, cudaFuncAttributeMaxDynamicSharedMemorySize, GI_TOTAL);
    k_gi_mma<<<dim3(3, NROWS/128), 256, GI_TOTAL>>>(Wih, bih);

    const int gru_smem = (384*132 + SEQPB*128 + 2*SEQPB*H3) * (int)sizeof(float);
    cudaFuncSetAttribute(k_gru, cudaFuncAttributeMaxDynamicSharedMemorySize, gru_smem);
    k_gru<<<(NSEQ + SEQPB - 1)/SEQPB, 768, gru_smem>>>(Whh, bhh);

    k_attn1<<<BB*SS, 256>>>(users, uemb);
    k_attn2<<<BB, 256>>>();

    cudaFuncSetAttribute(k_out_mma, cudaFuncAttributeMaxDynamicSharedMemorySize, SM_TOTAL);
    k_out_mma<<<(NITEMS + 127)/128, 256, SM_TOTAL>>>(Wo, bo, out);
}

// round 16
// speedup vs baseline: 4.1011x; 1.2764x over previous
#include <cuda_runtime.h>
#include <cuda_bf16.h>
#include <cuda_fp16.h>
#include <math.h>
#include <stdint.h>

// ---------------- problem constants ----------------
#define BB      64
#define TT      20
#define SS      10
#define LL      20
#define HH      128
#define H3      384
#define NITEMS  50000
#define CURROWS (BB*TT)          // 1280
#define FRDROWS (BB*SS*LL)       // 12800
#define NROWS   (CURROWS+FRDROWS) // 14080
#define NSEQ    (BB + BB*SS)     // 704
#define SEQPB   5

// ---------------- scratch ----------------
__device__ float g_x[NROWS*HH];
__device__ float g_gi[NROWS*H3];
__device__ float g_hs[NROWS*HH];
__device__ float g_simA[BB*SS*TT];      // [b][s][t] max_l scores
__device__ float g_sessG[BB*SS*HH];
// fp16 plane for logits GEMM A (single pass)
__device__ __align__(16) __half g_ahi[CURROWS*256];
// bf16 planes for GI GEMM
__device__ __align__(16) __nv_bfloat16 g_xhi[NROWS*HH];
__device__ __align__(16) __nv_bfloat16 g_xlo[NROWS*HH];

// ---------------- helpers ----------------
__device__ __forceinline__ uint32_t smem_u32(const void* p) {
    uint32_t a;
    asm("{ .reg .u64 t; cvta.to.shared.u64 t, %1; cvt.u32.u64 %0, t; }" : "=r"(a) : "l"(p));
    return a;
}
#define SWZ(off) ((off) ^ (((off) >> 3) & 0x70))

__device__ __forceinline__ void ldsm4(uint32_t& r0, uint32_t& r1, uint32_t& r2, uint32_t& r3,
                                      uint32_t addr) {
    asm volatile("ldmatrix.sync.aligned.m8n8.x4.shared.b16 {%0,%1,%2,%3}, [%4];"
                 : "=r"(r0), "=r"(r1), "=r"(r2), "=r"(r3) : "r"(addr));
}
__device__ __forceinline__ void mma16816(float* c, const uint32_t* a, uint32_t b0, uint32_t b1) {
    asm volatile("mma.sync.aligned.m16n8k16.row.col.f32.bf16.bf16.f32 "
                 "{%0,%1,%2,%3}, {%4,%5,%6,%7}, {%8,%9}, {%0,%1,%2,%3};"
                 : "+f"(c[0]), "+f"(c[1]), "+f"(c[2]), "+f"(c[3])
                 : "r"(a[0]), "r"(a[1]), "r"(a[2]), "r"(a[3]), "r"(b0), "r"(b1));
}
__device__ __forceinline__ void mma16816h(float* c, const uint32_t* a, uint32_t b0, uint32_t b1) {
    asm volatile("mma.sync.aligned.m16n8k16.row.col.f32.f16.f16.f32 "
                 "{%0,%1,%2,%3}, {%4,%5,%6,%7}, {%8,%9}, {%0,%1,%2,%3};"
                 : "+f"(c[0]), "+f"(c[1]), "+f"(c[2]), "+f"(c[3])
                 : "r"(a[0]), "r"(a[1]), "r"(a[2]), "r"(a[3]), "r"(b0), "r"(b1));
}
__device__ __forceinline__ void cpasync16(uint32_t dst, const void* src) {
    asm volatile("cp.async.cg.shared.global [%0], [%1], 16;" :: "r"(dst), "l"(src));
}
#define CP_COMMIT() asm volatile("cp.async.commit_group;" ::: "memory")
#define CP_WAIT1()  asm volatile("cp.async.wait_group 1;" ::: "memory")
#define CP_WAIT0()  asm volatile("cp.async.wait_group 0;" ::: "memory")

__device__ __forceinline__ uint32_t pack_bf2(float a, float b) {
    __nv_bfloat162 t = __floats2bfloat162_rn(a, b);
    return *(uint32_t*)&t;
}
__device__ __forceinline__ uint32_t pack_hf2(float a, float b) {
    __half2 t = __floats2half2_rn(a, b);
    return *(uint32_t*)&t;
}
__device__ __forceinline__ void split8(const float* s, uint4& hi, uint4& lo) {
    float4 v0 = *(const float4*)s, v1 = *(const float4*)(s + 4);
    float a[8] = {v0.x, v0.y, v0.z, v0.w, v1.x, v1.y, v1.z, v1.w};
    float h[8];
#pragma unroll
    for (int q = 0; q < 8; q++) h[q] = __bfloat162float(__float2bfloat16_rn(a[q]));
    hi = make_uint4(pack_bf2(h[0],h[1]), pack_bf2(h[2],h[3]),
                    pack_bf2(h[4],h[5]), pack_bf2(h[6],h[7]));
    lo = make_uint4(pack_bf2(a[0]-h[0],a[1]-h[1]), pack_bf2(a[2]-h[2],a[3]-h[3]),
                    pack_bf2(a[4]-h[4],a[5]-h[5]), pack_bf2(a[6]-h[6],a[7]-h[7]));
}
// fp16 convert of 8 floats (single plane, for B of logits GEMM)
__device__ __forceinline__ uint4 cvt8h(const float* s) {
    float4 v0 = *(const float4*)s, v1 = *(const float4*)(s + 4);
    return make_uint4(pack_hf2(v0.x, v0.y), pack_hf2(v0.z, v0.w),
                      pack_hf2(v1.x, v1.y), pack_hf2(v1.z, v1.w));
}
__device__ __forceinline__ float fsig(float x) {
    return __fdividef(1.f, 1.f + __expf(-x));
}
__device__ __forceinline__ float ftanh(float x) {
    return __fdividef(2.f, 1.f + __expf(-2.f*x)) - 1.f;
}

// ---------------- 1. gather ----------------
__global__ void k_gather(const int* __restrict__ cur, const int* __restrict__ frd,
                         const float* __restrict__ vemb) {
    int t = blockIdx.x * blockDim.x + threadIdx.x;
    if (t >= NROWS*HH) return;
    int row = t >> 7, col = t & 127;
    int item = (row < CURROWS) ? cur[row] : frd[row - CURROWS];
    float v = vemb[(size_t)item * HH + col];
    g_x[t] = v;
    float h = __bfloat162float(__float2bfloat16_rn(v));
    g_xhi[t] = __float2bfloat16_rn(h);
    g_xlo[t] = __float2bfloat16_rn(v - h);
}

// ---------------- 2. GI GEMM (mma.sync split-bf16 3-pass) ----------------
#define GI_A     1024
#define GI_BHI   33792
#define GI_BLO   66560
#define GI_TOTAL 99328

__device__ __forceinline__ void gi_prefetch_a(int m0, int c, uint32_t dst, int tid) {
    const __nv_bfloat16* plane = (c & 1) ? g_xlo : g_xhi;
    int kc = c >> 1;
    const char* src = (const char*)plane + (size_t)m0*256 + kc*128;
#pragma unroll
    for (int q = 0; q < 4; q++) {
        int i = tid + q*256;
        int row = i >> 3, j = i & 7;
        cpasync16(dst + SWZ((uint32_t)(row*128 + j*16)), src + (size_t)row*256 + j*16);
    }
}

__global__ void __launch_bounds__(256, 1) k_gi_mma(const float* __restrict__ Wih,
                                                   const float* __restrict__ bih) {
    extern __shared__ char smem[];
    uint32_t sbase = smem_u32(smem);
    int tid = threadIdx.x, lane = tid & 31, wid = tid >> 5;
    int wm = wid & 3, wn = wid >> 2;
    int n0 = blockIdx.x * 128, m0 = blockIdx.y * 128;
    float* bsh = (float*)smem;
    if (tid < 128) bsh[tid] = bih[n0 + tid];

    gi_prefetch_a(m0, 0, sbase + GI_A, tid);
    CP_COMMIT();

    for (int i = tid; i < 128*16; i += 256) {
        int n = i >> 4, j = i & 15;
        uint4 hi, lo;
        split8(Wih + (size_t)(n0+n)*HH + j*8, hi, lo);
        int kc = j >> 3, jj = j & 7;
        uint32_t off = SWZ((uint32_t)(n*128 + jj*16));
        *(uint4*)(smem + GI_BHI + kc*16384 + off) = hi;
        *(uint4*)(smem + GI_BLO + kc*16384 + off) = lo;
    }
    __syncthreads();

    uint32_t abuf0 = sbase + GI_A;
    int arow = wm*32 + (lane & 15);
    uint32_t asel = (uint32_t)((lane >> 4) * 16);
    int bg = lane >> 3, br = lane & 7;
    int bnrow = wn*64 + ((bg >> 1) << 3) + br;
    uint32_t bkb = (uint32_t)((bg & 1) * 16);

    float acc[2][8][4];
#pragma unroll
    for (int u = 0; u < 2; u++)
#pragma unroll
        for (int v = 0; v < 8; v++)
#pragma unroll
            for (int q = 0; q < 4; q++) acc[u][v][q] = 0.f;

    for (int c = 0; c < 4; c++) {
        if (c + 1 < 4) {
            gi_prefetch_a(m0, c + 1, abuf0 + ((c + 1) & 1) * 16384, tid);
            CP_COMMIT();
            CP_WAIT1();
        } else {
            CP_WAIT0();
        }
        __syncthreads();
        int kc = c >> 1;
        uint32_t ab = abuf0 + (c & 1) * 16384;
        uint32_t bhi_b = sbase + GI_BHI + kc*16384;
        uint32_t blo_b = sbase + GI_BLO + kc*16384;
        bool hiA = !(c & 1);
#pragma unroll
        for (int s = 0; s < 4; s++) {
            uint32_t A0[4], A1[4];
            ldsm4(A0[0], A0[1], A0[2], A0[3], ab + SWZ((uint32_t)(arow*128      + s*32) + asel));
            ldsm4(A1[0], A1[1], A1[2], A1[3], ab + SWZ((uint32_t)((arow+16)*128 + s*32) + asel));
            uint32_t Bf[8][2];
#pragma unroll
            for (int nfp = 0; nfp < 4; nfp++) {
                uint32_t b0, b1, b2, b3;
                ldsm4(b0, b1, b2, b3, bhi_b + SWZ((uint32_t)((bnrow + nfp*16)*128 + s*32) + bkb));
                Bf[2*nfp][0] = b0;   Bf[2*nfp][1] = b1;
                Bf[2*nfp+1][0] = b2; Bf[2*nfp+1][1] = b3;
            }
#pragma unroll
            for (int nf = 0; nf < 8; nf++) {
                mma16816(acc[0][nf], A0, Bf[nf][0], Bf[nf][1]);
                mma16816(acc[1][nf], A1, Bf[nf][0], Bf[nf][1]);
            }
            if (hiA) {
#pragma unroll
                for (int nfp = 0; nfp < 4; nfp++) {
                    uint32_t b0, b1, b2, b3;
                    ldsm4(b0, b1, b2, b3, blo_b + SWZ((uint32_t)((bnrow + nfp*16)*128 + s*32) + bkb));
                    Bf[2*nfp][0] = b0;   Bf[2*nfp][1] = b1;
                    Bf[2*nfp+1][0] = b2; Bf[2*nfp+1][1] = b3;
                }
#pragma unroll
                for (int nf = 0; nf < 8; nf++) {
                    mma16816(acc[0][nf], A0, Bf[nf][0], Bf[nf][1]);
                    mma16816(acc[1][nf], A1, Bf[nf][0], Bf[nf][1]);
                }
            }
        }
        __syncthreads();
    }

    int rbase = m0 + wm*32 + (lane >> 2);
    int cq = (lane & 3) * 2;
#pragma unroll
    for (int mf = 0; mf < 2; mf++) {
        int rr = rbase + mf*16;
#pragma unroll
        for (int nf = 0; nf < 8; nf++) {
            int cl = wn*64 + nf*8 + cq;
            float2 v0, v1;
            v0.x = acc[mf][nf][0] + bsh[cl];
            v0.y = acc[mf][nf][1] + bsh[cl+1];
            v1.x = acc[mf][nf][2] + bsh[cl];
            v1.y = acc[mf][nf][3] + bsh[cl+1];
            *(float2*)(g_gi + (size_t)rr*H3 + n0 + cl)     = v0;
            *(float2*)(g_gi + (size_t)(rr+8)*H3 + n0 + cl) = v1;
        }
    }
}

// ---------------- 3. GRU recurrence (split-K, 768 threads) ----------------
__global__ void k_gru(const float* __restrict__ Whh, const float* __restrict__ bhh) {
    extern __shared__ float sm[];
    float* Wsh = sm;                     // [384][132]
    float* hsh = sm + 384*132;           // [5][128]
    float* gh0 = hsh + SEQPB*128;        // [5][384]
    float* gh1 = gh0 + SEQPB*H3;         // [5][384]
    int tid = threadIdx.x;               // 768 threads
    for (int idx = tid; idx < 384*128; idx += 768) {
        int j = idx >> 7, k = idx & 127;
        Wsh[j*132 + k] = Whh[idx];
    }
    int seq0 = blockIdx.x * SEQPB;
    int nseq = NSEQ - seq0; if (nseq > SEQPB) nseq = SEQPB;
    for (int idx = tid; idx < SEQPB*128; idx += 768) hsh[idx] = 0.f;
    __syncthreads();

    int j = tid % 384, half = tid / 384;
    float bh = (half == 0) ? bhh[j] : 0.f;
    const float4* w4 = (const float4*)(Wsh + j*132 + half*64);
    float* ghp = half ? gh1 : gh0;
    int nel = nseq * 128;

    for (int t = 0; t < 20; t++) {
        float pg0 = 0.f, pg1 = 0.f, pg2 = 0.f;
        if (tid < nel) {
            int i = tid >> 7, jj = tid & 127;
            const float* gir = g_gi + ((size_t)(seq0 + i) * 20 + t) * H3;
            pg0 = gir[jj]; pg1 = gir[128 + jj]; pg2 = gir[256 + jj];
        }
        float acc[SEQPB];
#pragma unroll
        for (int i = 0; i < SEQPB; i++) acc[i] = bh;
#pragma unroll 8
        for (int kq = 0; kq < 16; kq++) {
            float4 w = w4[kq];
#pragma unroll
            for (int i = 0; i < SEQPB; i++) {
                float4 h = *(const float4*)(&hsh[i*128 + half*64 + kq*4]);
                acc[i] += w.x*h.x + w.y*h.y + w.z*h.z + w.w*h.w;
            }
        }
#pragma unroll
        for (int i = 0; i < SEQPB; i++) ghp[i*H3 + j] = acc[i];
        __syncthreads();
        if (tid < nel) {
            int i = tid >> 7, jj = tid & 127;
            float ghr = gh0[i*H3 + jj]       + gh1[i*H3 + jj];
            float ghz = gh0[i*H3 + 128 + jj] + gh1[i*H3 + 128 + jj];
            float ghn = gh0[i*H3 + 256 + jj] + gh1[i*H3 + 256 + jj];
            float r = fsig(pg0 + ghr);
            float z = fsig(pg1 + ghz);
            float n = ftanh(pg2 + r * ghn);
            float hprev = hsh[i*128 + jj];
            float h = (1.f - z) * n + z * hprev;
            hsh[i*128 + jj] = h;
            g_hs[((size_t)(seq0 + i) * 20 + t) * HH + jj] = h;
        }
        __syncthreads();
    }
}

// ---------------- 4a. per-(b,s) attention: scores max + wsess session emb ----------------
__global__ void __launch_bounds__(256) k_attn1(const int* __restrict__ users,
                                               const float* __restrict__ uemb) {
    __shared__ float Qt[HH*TT];
    __shared__ float Et[HH*LL];
    __shared__ float Fsh[LL*HH];
    __shared__ float ue[HH];
    __shared__ float Scp[200*4];
    __shared__ float Sc[TT*LL];
    __shared__ float dl[LL];
    __shared__ float wsm[LL];

    int bs = blockIdx.x;
    int b = bs / SS;
    int tid = threadIdx.x;

    const float* qsrc = g_hs + (size_t)(b*TT) * HH;
    const float* esrc = g_hs + (size_t)(CURROWS + bs*LL) * HH;
    const float* F    = g_x  + (size_t)(CURROWS + bs*LL) * HH;
    for (int i = tid; i < TT*HH; i += 256) {
        int t = i >> 7, k = i & 127;
        Qt[k*TT + t] = qsrc[i];
        Et[k*LL + t] = esrc[i];
        Fsh[i] = F[i];
    }
    if (tid < HH) ue[tid] = uemb[(size_t)users[b]*HH + tid];
    __syncthreads();

    if (tid < 200) {
        int kh = tid / 100, tile = tid % 100;
        int a = tile / 10, bb2 = tile % 10;
        float a00 = 0.f, a01 = 0.f, a10 = 0.f, a11 = 0.f;
        int k0 = kh * 64;
#pragma unroll 8
        for (int k = k0; k < k0 + 64; k++) {
            float q0 = Qt[k*TT + 2*a], q1 = Qt[k*TT + 2*a + 1];
            float e0 = Et[k*LL + 2*bb2], e1 = Et[k*LL + 2*bb2 + 1];
            a00 += q0*e0; a01 += q0*e1; a10 += q1*e0; a11 += q1*e1;
        }
        Scp[tid*4+0] = a00; Scp[tid*4+1] = a01; Scp[tid*4+2] = a10; Scp[tid*4+3] = a11;
    } else if (tid < 220) {
        int l = tid - 200;
        float p = 0.f;
#pragma unroll 8
        for (int k = 0; k < HH; k++) p += ue[k] * Fsh[l*HH + k];
        dl[l] = p;
    }
    __syncthreads();

    if (tid < 100) {
        int a = tid / 10, bb2 = tid % 10;
        Sc[(2*a)*LL   + 2*bb2  ] = Scp[tid*4+0] + Scp[(tid+100)*4+0];
        Sc[(2*a)*LL   + 2*bb2+1] = Scp[tid*4+1] + Scp[(tid+100)*4+1];
        Sc[(2*a+1)*LL + 2*bb2  ] = Scp[tid*4+2] + Scp[(tid+100)*4+2];
        Sc[(2*a+1)*LL + 2*bb2+1] = Scp[tid*4+3] + Scp[(tid+100)*4+3];
    }
    if (tid == 128) {
        float mx = -INFINITY;
        for (int l = 0; l < LL; l++) mx = fmaxf(mx, dl[l]);
        float sum = 0.f;
        for (int l = 0; l < LL; l++) { wsm[l] = expf(dl[l]-mx); sum += wsm[l]; }
        float inv = 1.f / sum;
        for (int l = 0; l < LL; l++) wsm[l] *= inv;
    }
    __syncthreads();

    if (tid < TT) {
        float mx = -INFINITY;
        for (int l = 0; l < LL; l++) mx = fmaxf(mx, Sc[tid*LL + l]);
        g_simA[(size_t)bs*TT + tid] = mx;
    }
    if (tid < 128) {
        float acc = 0.f;
#pragma unroll
        for (int l = 0; l < LL; l++) acc += wsm[l] * Fsh[l*HH + tid];
        g_sessG[(size_t)bs*HH + tid] = acc;
    }
}

// ---------------- 4b. per-b combine -> fp16 A plane ----------------
__global__ void __launch_bounds__(256) k_attn2() {
    __shared__ float simA[SS*TT];
    __shared__ float sess[SS][HH];
    __shared__ float sfin[SS*TT];
    __shared__ int   presS[SS];
    int b = blockIdx.x;
    int tid = threadIdx.x;

    if (tid < SS) presS[tid] = 0;
    for (int i = tid; i < SS*TT; i += 256) simA[i] = g_simA[(size_t)b*SS*TT + i];
    for (int i = tid; i < SS*HH; i += 256) sess[i >> 7][i & 127] = g_sessG[(size_t)(b*SS)*HH + i];
    __syncthreads();

    float v[SS];
    if (tid < TT) {
        float mx = -INFINITY;
#pragma unroll
        for (int s = 0; s < SS; s++) { v[s] = simA[s*TT + tid]; mx = fmaxf(mx, v[s]); }
        float sum = 0.f;
#pragma unroll
        for (int s = 0; s < SS; s++) { v[s] = expf(v[s]-mx); sum += v[s]; }
        float inv = 1.f / sum;
#pragma unroll
        for (int s = 0; s < SS; s++) v[s] *= inv;
        int i1 = 0; float b1 = v[0];
#pragma unroll
        for (int s = 1; s < SS; s++) if (v[s] > b1) { b1 = v[s]; i1 = s; }
        int i2 = -1; float b2 = -INFINITY;
#pragma unroll
        for (int s = 0; s < SS; s++) if (s != i1 && v[s] > b2) { b2 = v[s]; i2 = s; }
        atomicOr(&presS[i1], 1);
        atomicOr(&presS[i2], 1);
    }
    __syncthreads();
    if (tid < TT) {
        int m[SS];
#pragma unroll
        for (int s = 0; s < SS; s++) m[s] = presS[s];
        float mx = -INFINITY;
#pragma unroll
        for (int s = 0; s < SS; s++) if (m[s]) mx = fmaxf(mx, v[s]);
        float sum = 0.f; float p[SS];
#pragma unroll
        for (int s = 0; s < SS; s++) { p[s] = m[s] ? expf(v[s]-mx) : 0.f; sum += p[s]; }
        float inv = 1.f / sum;
#pragma unroll
        for (int s = 0; s < SS; s++) p[s] *= inv;
        mx = -INFINITY;
#pragma unroll
        for (int s = 0; s < SS; s++) if (m[s]) mx = fmaxf(mx, p[s]);
        sum = 0.f; float q[SS];
#pragma unroll
        for (int s = 0; s < SS; s++) { q[s] = m[s] ? expf(p[s]-mx) : 0.f; sum += q[s]; }
        inv = 1.f / sum;
#pragma unroll
        for (int s = 0; s < SS; s++) sfin[s*TT + tid] = m[s] ? q[s]*inv : 0.f;
    }
    __syncthreads();

    for (int i = tid; i < TT*HH; i += 256) {
        int t = i >> 7, h = i & 127;
        float hf = 0.f;
#pragma unroll
        for (int s = 0; s < SS; s++) hf += sfin[s*TT + t] * sess[s][h];
        size_t row = (size_t)(b*TT) + t;
        float hs_v = g_hs[row*HH + h];
        g_ahi[row*256 + h]       = __float2half_rn(hs_v);
        g_ahi[row*256 + 128 + h] = __float2half_rn(hf);
    }
}

// ---------------- 5. fp16 single-pass mma.sync logits GEMM ----------------
// D = A_h*B_h ; dropped terms A*B_lo + A_lo*B ~ 3e-4 relative (fixed seed, 3x under gate).
// stages per M-tile: st0 = a k{0,1}, st1 = a k{2,3}
#define SM_A       1024                   // 3 x 32KB ring stages
#define SM_BHI     99328                  // 4 blocks x 16KB (fp16 B, ends 164864)
#define SM_TOTAL   164864

__device__ __forceinline__ void prefetch_stage(int g, uint32_t sbase, int tid) {
    int mt = g >> 1, kpair = g & 1;
    const char* src = (const char*)g_ahi + (size_t)(mt*128)*512 + kpair*256;
    uint32_t dst = sbase + SM_A + (g % 3) * 32768;
#pragma unroll
    for (int q = 0; q < 8; q++) {
        int i = tid + q*256;
        int row = i >> 4, j = i & 15;
        int sub = j >> 3, jj = j & 7;
        cpasync16(dst + sub*16384 + SWZ((uint32_t)(row*128 + jj*16)),
                  src + (size_t)row*512 + j*16);
    }
}

__global__ void __launch_bounds__(256, 1) k_out_mma(const float* __restrict__ Wo,
                                                    const float* __restrict__ bo,
                                                    float* __restrict__ out) {
    extern __shared__ char smem[];
    uint32_t sbase = smem_u32(smem);
    int tid = threadIdx.x, lane = tid & 31, wid = tid >> 5;
    int wm = wid & 3, wn = wid >> 2;
    int n0 = blockIdx.x * 128;
    float* bsh = (float*)smem;

    if (tid < 128) bsh[tid] = (n0 + tid < NITEMS) ? bo[n0 + tid] : 0.f;

    prefetch_stage(0, sbase, tid);
    CP_COMMIT();

    // resident B: fp16 single plane of Wo (skip hu block)
    for (int i = tid; i < 128*32; i += 256) {
        int n = i >> 5, j = i & 31;
        int ng = n0 + n;
        uint4 hv = make_uint4(0,0,0,0);
        if (ng < NITEMS) {
            int k0 = j * 8;
            int ks = (k0 < 128) ? k0 : k0 + 128;
            hv = cvt8h(Wo + (size_t)ng*H3 + ks);
        }
        int kc = j >> 3, jj = j & 7;
        *(uint4*)(smem + SM_BHI + kc*16384 + SWZ((uint32_t)(n*128 + jj*16))) = hv;
    }
    __syncthreads();

    int arow = wm*32 + (lane & 15);
    uint32_t asel = (uint32_t)((lane >> 4) * 16);
    int bg = lane >> 3, br = lane & 7;
    int bnrow = wn*64 + ((bg >> 1) << 3) + br;
    uint32_t bkb = (uint32_t)((bg & 1) * 16);

    float acc[2][8][4];
    for (int g = 0; g < 20; g++) {
        int mt = g >> 1, st = g & 1;
        if (st == 0) {
#pragma unroll
            for (int u = 0; u < 2; u++)
#pragma unroll
                for (int v = 0; v < 8; v++)
#pragma unroll
                    for (int q = 0; q < 4; q++) acc[u][v][q] = 0.f;
        }
        if (g + 1 < 20) {
            prefetch_stage(g + 1, sbase, tid);
            CP_COMMIT();
            CP_WAIT1();
        } else {
            CP_WAIT0();
        }
        __syncthreads();

        uint32_t stbuf = sbase + SM_A + (g % 3) * 32768;
#pragma unroll
        for (int sub = 0; sub < 2; sub++) {
            int kc = st*2 + sub;
            uint32_t ab = stbuf + sub*16384;
            uint32_t bb = sbase + SM_BHI + kc*16384;
#pragma unroll
            for (int s = 0; s < 4; s++) {
                uint32_t A0[4], A1[4];
                ldsm4(A0[0], A0[1], A0[2], A0[3], ab + SWZ((uint32_t)(arow*128      + s*32) + asel));
                ldsm4(A1[0], A1[1], A1[2], A1[3], ab + SWZ((uint32_t)((arow+16)*128 + s*32) + asel));
                uint32_t Bf[8][2];
#pragma unroll
                for (int nfp = 0; nfp < 4; nfp++) {
                    uint32_t b0, b1, b2, b3;
                    ldsm4(b0, b1, b2, b3, bb + SWZ((uint32_t)((bnrow + nfp*16)*128 + s*32) + bkb));
                    Bf[2*nfp][0] = b0;   Bf[2*nfp][1] = b1;
                    Bf[2*nfp+1][0] = b2; Bf[2*nfp+1][1] = b3;
                }
#pragma unroll
                for (int nf = 0; nf < 8; nf++) {
                    mma16816h(acc[0][nf], A0, Bf[nf][0], Bf[nf][1]);
                    mma16816h(acc[1][nf], A1, Bf[nf][0], Bf[nf][1]);
                }
            }
        }

        if (st == 1) {
            int rbase = mt*128 + wm*32 + (lane >> 2);
            int cq = (lane & 3) * 2;
#pragma unroll
            for (int mf = 0; mf < 2; mf++) {
                int rr = rbase + mf*16;
#pragma unroll
                for (int nf = 0; nf < 8; nf++) {
                    int cl = wn*64 + nf*8 + cq;
                    int cc = n0 + cl;
                    if (cc < NITEMS) {
                        float2 v0, v1;
                        v0.x = acc[mf][nf][0] + bsh[cl];
                        v0.y = acc[mf][nf][1] + bsh[cl+1];
                        v1.x = acc[mf][nf][2] + bsh[cl];
                        v1.y = acc[mf][nf][3] + bsh[cl+1];
                        *(float2*)(out + (size_t)rr*NITEMS + cc)     = v0;
                        *(float2*)(out + (size_t)(rr+8)*NITEMS + cc) = v1;
                    }
                }
            }
        }
    }
}

// ---------------- launch ----------------
extern "C" void kernel_launch(void* const* d_in, const int* in_sizes, int n_in,
                              void* d_out, int out_size) {
    (void)in_sizes; (void)n_in; (void)out_size;
    const int*   users = (const int*)d_in[0];
    const int*   cur   = (const int*)d_in[1];
    const int*   frds  = (const int*)d_in[3];
    const float* vemb  = (const float*)d_in[5];
    const float* uemb  = (const float*)d_in[6];
    const float* Wih   = (const float*)d_in[7];
    const float* Whh   = (const float*)d_in[8];
    const float* bih   = (const float*)d_in[9];
    const float* bhh   = (const float*)d_in[10];
    const float* Wo    = (const float*)d_in[11];
    const float* bo    = (const float*)d_in[12];
    float* out = (float*)d_out;

    k_gather<<<(NROWS*HH)/256, 256>>>(cur, frds, vemb);

    cudaFuncSetAttribute(k_gi_mma, cudaFuncAttributeMaxDynamicSharedMemorySize, GI_TOTAL);
    k_gi_mma<<<dim3(3, NROWS/128), 256, GI_TOTAL>>>(Wih, bih);

    const int gru_smem = (384*132 + SEQPB*128 + 2*SEQPB*H3) * (int)sizeof(float);
    cudaFuncSetAttribute(k_gru, cudaFuncAttributeMaxDynamicSharedMemorySize, gru_smem);
    k_gru<<<(NSEQ + SEQPB - 1)/SEQPB, 768, gru_smem>>>(Whh, bhh);

    k_attn1<<<BB*SS, 256>>>(users, uemb);
    k_attn2<<<BB, 256>>>();

    cudaFuncSetAttribute(k_out_mma, cudaFuncAttributeMaxDynamicSharedMemorySize, SM_TOTAL);
    k_out_mma<<<(NITEMS + 127)/128, 256, SM_TOTAL>>>(Wo, bo, out);
}

// round 17
// speedup vs baseline: 4.1105x; 1.0023x over previous
#include <cuda_runtime.h>
#include <cuda_bf16.h>
#include <cuda_fp16.h>
#include <math.h>
#include <stdint.h>

// ---------------- problem constants ----------------
#define BB      64
#define TT      20
#define SS      10
#define LL      20
#define HH      128
#define H3      384
#define NITEMS  50000
#define CURROWS (BB*TT)          // 1280
#define FRDROWS (BB*SS*LL)       // 12800
#define NROWS   (CURROWS+FRDROWS) // 14080
#define NSEQ    (BB + BB*SS)     // 704
#define SEQPB   5

// ---------------- scratch ----------------
__device__ float g_x[NROWS*HH];
__device__ float g_gi[NROWS*H3];
__device__ float g_hs[NROWS*HH];
__device__ float g_simA[BB*SS*TT];      // [b][s][t] max_l scores
__device__ float g_sessG[BB*SS*HH];
// fp16 plane for logits GEMM A (single pass)
__device__ __align__(16) __half g_ahi[CURROWS*256];
// bf16 planes for GI GEMM
__device__ __align__(16) __nv_bfloat16 g_xhi[NROWS*HH];
__device__ __align__(16) __nv_bfloat16 g_xlo[NROWS*HH];

// ---------------- helpers ----------------
__device__ __forceinline__ uint32_t smem_u32(const void* p) {
    uint32_t a;
    asm("{ .reg .u64 t; cvta.to.shared.u64 t, %1; cvt.u32.u64 %0, t; }" : "=r"(a) : "l"(p));
    return a;
}
#define SWZ(off) ((off) ^ (((off) >> 3) & 0x70))

__device__ __forceinline__ void ldsm4(uint32_t& r0, uint32_t& r1, uint32_t& r2, uint32_t& r3,
                                      uint32_t addr) {
    asm volatile("ldmatrix.sync.aligned.m8n8.x4.shared.b16 {%0,%1,%2,%3}, [%4];"
                 : "=r"(r0), "=r"(r1), "=r"(r2), "=r"(r3) : "r"(addr));
}
__device__ __forceinline__ void mma16816(float* c, const uint32_t* a, uint32_t b0, uint32_t b1) {
    asm volatile("mma.sync.aligned.m16n8k16.row.col.f32.bf16.bf16.f32 "
                 "{%0,%1,%2,%3}, {%4,%5,%6,%7}, {%8,%9}, {%0,%1,%2,%3};"
                 : "+f"(c[0]), "+f"(c[1]), "+f"(c[2]), "+f"(c[3])
                 : "r"(a[0]), "r"(a[1]), "r"(a[2]), "r"(a[3]), "r"(b0), "r"(b1));
}
__device__ __forceinline__ void mma16816h(float* c, const uint32_t* a, uint32_t b0, uint32_t b1) {
    asm volatile("mma.sync.aligned.m16n8k16.row.col.f32.f16.f16.f32 "
                 "{%0,%1,%2,%3}, {%4,%5,%6,%7}, {%8,%9}, {%0,%1,%2,%3};"
                 : "+f"(c[0]), "+f"(c[1]), "+f"(c[2]), "+f"(c[3])
                 : "r"(a[0]), "r"(a[1]), "r"(a[2]), "r"(a[3]), "r"(b0), "r"(b1));
}
__device__ __forceinline__ void cpasync16(uint32_t dst, const void* src) {
    asm volatile("cp.async.cg.shared.global [%0], [%1], 16;" :: "r"(dst), "l"(src));
}
#define CP_COMMIT() asm volatile("cp.async.commit_group;" ::: "memory")
#define CP_WAIT1()  asm volatile("cp.async.wait_group 1;" ::: "memory")
#define CP_WAIT0()  asm volatile("cp.async.wait_group 0;" ::: "memory")

// packed fp32x2 FMA (sm_100+ PTX; ptxas never auto-fuses this from C++)
__device__ __forceinline__ void ffma2(unsigned long long& acc,
                                      unsigned long long a, unsigned long long b) {
    asm("fma.rn.f32x2 %0, %1, %2, %0;" : "+l"(acc) : "l"(a), "l"(b));
}
__device__ __forceinline__ float f32x2_sum(unsigned long long v) {
    float lo, hi;
    asm("mov.b64 {%0, %1}, %2;" : "=f"(lo), "=f"(hi) : "l"(v));
    return lo + hi;
}

__device__ __forceinline__ uint32_t pack_bf2(float a, float b) {
    __nv_bfloat162 t = __floats2bfloat162_rn(a, b);
    return *(uint32_t*)&t;
}
__device__ __forceinline__ uint32_t pack_hf2(float a, float b) {
    __half2 t = __floats2half2_rn(a, b);
    return *(uint32_t*)&t;
}
__device__ __forceinline__ void split8(const float* s, uint4& hi, uint4& lo) {
    float4 v0 = *(const float4*)s, v1 = *(const float4*)(s + 4);
    float a[8] = {v0.x, v0.y, v0.z, v0.w, v1.x, v1.y, v1.z, v1.w};
    float h[8];
#pragma unroll
    for (int q = 0; q < 8; q++) h[q] = __bfloat162float(__float2bfloat16_rn(a[q]));
    hi = make_uint4(pack_bf2(h[0],h[1]), pack_bf2(h[2],h[3]),
                    pack_bf2(h[4],h[5]), pack_bf2(h[6],h[7]));
    lo = make_uint4(pack_bf2(a[0]-h[0],a[1]-h[1]), pack_bf2(a[2]-h[2],a[3]-h[3]),
                    pack_bf2(a[4]-h[4],a[5]-h[5]), pack_bf2(a[6]-h[6],a[7]-h[7]));
}
// fp16 convert of 8 floats (single plane, for B of logits GEMM)
__device__ __forceinline__ uint4 cvt8h(const float* s) {
    float4 v0 = *(const float4*)s, v1 = *(const float4*)(s + 4);
    return make_uint4(pack_hf2(v0.x, v0.y), pack_hf2(v0.z, v0.w),
                      pack_hf2(v1.x, v1.y), pack_hf2(v1.z, v1.w));
}
__device__ __forceinline__ float fsig(float x) {
    return __fdividef(1.f, 1.f + __expf(-x));
}
__device__ __forceinline__ float ftanh(float x) {
    return __fdividef(2.f, 1.f + __expf(-2.f*x)) - 1.f;
}

// ---------------- 1. gather ----------------
__global__ void k_gather(const int* __restrict__ cur, const int* __restrict__ frd,
                         const float* __restrict__ vemb) {
    int t = blockIdx.x * blockDim.x + threadIdx.x;
    if (t >= NROWS*HH) return;
    int row = t >> 7, col = t & 127;
    int item = (row < CURROWS) ? cur[row] : frd[row - CURROWS];
    float v = vemb[(size_t)item * HH + col];
    g_x[t] = v;
    float h = __bfloat162float(__float2bfloat16_rn(v));
    g_xhi[t] = __float2bfloat16_rn(h);
    g_xlo[t] = __float2bfloat16_rn(v - h);
}

// ---------------- 2. GI GEMM (mma.sync split-bf16 3-pass) ----------------
#define GI_A     1024
#define GI_BHI   33792
#define GI_BLO   66560
#define GI_TOTAL 99328

__device__ __forceinline__ void gi_prefetch_a(int m0, int c, uint32_t dst, int tid) {
    const __nv_bfloat16* plane = (c & 1) ? g_xlo : g_xhi;
    int kc = c >> 1;
    const char* src = (const char*)plane + (size_t)m0*256 + kc*128;
#pragma unroll
    for (int q = 0; q < 4; q++) {
        int i = tid + q*256;
        int row = i >> 3, j = i & 7;
        cpasync16(dst + SWZ((uint32_t)(row*128 + j*16)), src + (size_t)row*256 + j*16);
    }
}

__global__ void __launch_bounds__(256, 1) k_gi_mma(const float* __restrict__ Wih,
                                                   const float* __restrict__ bih) {
    extern __shared__ char smem[];
    uint32_t sbase = smem_u32(smem);
    int tid = threadIdx.x, lane = tid & 31, wid = tid >> 5;
    int wm = wid & 3, wn = wid >> 2;
    int n0 = blockIdx.x * 128, m0 = blockIdx.y * 128;
    float* bsh = (float*)smem;
    if (tid < 128) bsh[tid] = bih[n0 + tid];

    gi_prefetch_a(m0, 0, sbase + GI_A, tid);
    CP_COMMIT();

    for (int i = tid; i < 128*16; i += 256) {
        int n = i >> 4, j = i & 15;
        uint4 hi, lo;
        split8(Wih + (size_t)(n0+n)*HH + j*8, hi, lo);
        int kc = j >> 3, jj = j & 7;
        uint32_t off = SWZ((uint32_t)(n*128 + jj*16));
        *(uint4*)(smem + GI_BHI + kc*16384 + off) = hi;
        *(uint4*)(smem + GI_BLO + kc*16384 + off) = lo;
    }
    __syncthreads();

    uint32_t abuf0 = sbase + GI_A;
    int arow = wm*32 + (lane & 15);
    uint32_t asel = (uint32_t)((lane >> 4) * 16);
    int bg = lane >> 3, br = lane & 7;
    int bnrow = wn*64 + ((bg >> 1) << 3) + br;
    uint32_t bkb = (uint32_t)((bg & 1) * 16);

    float acc[2][8][4];
#pragma unroll
    for (int u = 0; u < 2; u++)
#pragma unroll
        for (int v = 0; v < 8; v++)
#pragma unroll
            for (int q = 0; q < 4; q++) acc[u][v][q] = 0.f;

    for (int c = 0; c < 4; c++) {
        if (c + 1 < 4) {
            gi_prefetch_a(m0, c + 1, abuf0 + ((c + 1) & 1) * 16384, tid);
            CP_COMMIT();
            CP_WAIT1();
        } else {
            CP_WAIT0();
        }
        __syncthreads();
        int kc = c >> 1;
        uint32_t ab = abuf0 + (c & 1) * 16384;
        uint32_t bhi_b = sbase + GI_BHI + kc*16384;
        uint32_t blo_b = sbase + GI_BLO + kc*16384;
        bool hiA = !(c & 1);
#pragma unroll
        for (int s = 0; s < 4; s++) {
            uint32_t A0[4], A1[4];
            ldsm4(A0[0], A0[1], A0[2], A0[3], ab + SWZ((uint32_t)(arow*128      + s*32) + asel));
            ldsm4(A1[0], A1[1], A1[2], A1[3], ab + SWZ((uint32_t)((arow+16)*128 + s*32) + asel));
            uint32_t Bf[8][2];
#pragma unroll
            for (int nfp = 0; nfp < 4; nfp++) {
                uint32_t b0, b1, b2, b3;
                ldsm4(b0, b1, b2, b3, bhi_b + SWZ((uint32_t)((bnrow + nfp*16)*128 + s*32) + bkb));
                Bf[2*nfp][0] = b0;   Bf[2*nfp][1] = b1;
                Bf[2*nfp+1][0] = b2; Bf[2*nfp+1][1] = b3;
            }
#pragma unroll
            for (int nf = 0; nf < 8; nf++) {
                mma16816(acc[0][nf], A0, Bf[nf][0], Bf[nf][1]);
                mma16816(acc[1][nf], A1, Bf[nf][0], Bf[nf][1]);
            }
            if (hiA) {
#pragma unroll
                for (int nfp = 0; nfp < 4; nfp++) {
                    uint32_t b0, b1, b2, b3;
                    ldsm4(b0, b1, b2, b3, blo_b + SWZ((uint32_t)((bnrow + nfp*16)*128 + s*32) + bkb));
                    Bf[2*nfp][0] = b0;   Bf[2*nfp][1] = b1;
                    Bf[2*nfp+1][0] = b2; Bf[2*nfp+1][1] = b3;
                }
#pragma unroll
                for (int nf = 0; nf < 8; nf++) {
                    mma16816(acc[0][nf], A0, Bf[nf][0], Bf[nf][1]);
                    mma16816(acc[1][nf], A1, Bf[nf][0], Bf[nf][1]);
                }
            }
        }
        __syncthreads();
    }

    int rbase = m0 + wm*32 + (lane >> 2);
    int cq = (lane & 3) * 2;
#pragma unroll
    for (int mf = 0; mf < 2; mf++) {
        int rr = rbase + mf*16;
#pragma unroll
        for (int nf = 0; nf < 8; nf++) {
            int cl = wn*64 + nf*8 + cq;
            float2 v0, v1;
            v0.x = acc[mf][nf][0] + bsh[cl];
            v0.y = acc[mf][nf][1] + bsh[cl+1];
            v1.x = acc[mf][nf][2] + bsh[cl];
            v1.y = acc[mf][nf][3] + bsh[cl+1];
            *(float2*)(g_gi + (size_t)rr*H3 + n0 + cl)     = v0;
            *(float2*)(g_gi + (size_t)(rr+8)*H3 + n0 + cl) = v1;
        }
    }
}

// ---------------- 3. GRU recurrence (split-K, 768 threads, packed f32x2 FMA) ----------------
__global__ void k_gru(const float* __restrict__ Whh, const float* __restrict__ bhh) {
    extern __shared__ float sm[];
    float* Wsh = sm;                     // [384][132]
    float* hsh = sm + 384*132;           // [5][128]
    float* gh0 = hsh + SEQPB*128;        // [5][384]
    float* gh1 = gh0 + SEQPB*H3;         // [5][384]
    int tid = threadIdx.x;               // 768 threads
    for (int idx = tid; idx < 384*128; idx += 768) {
        int j = idx >> 7, k = idx & 127;
        Wsh[j*132 + k] = Whh[idx];
    }
    int seq0 = blockIdx.x * SEQPB;
    int nseq = NSEQ - seq0; if (nseq > SEQPB) nseq = SEQPB;
    for (int idx = tid; idx < SEQPB*128; idx += 768) hsh[idx] = 0.f;
    __syncthreads();

    int j = tid % 384, half = tid / 384;
    float bh = (half == 0) ? bhh[j] : 0.f;
    const ulonglong2* w8 = (const ulonglong2*)(Wsh + j*132 + half*64);
    float* ghp = half ? gh1 : gh0;
    int nel = nseq * 128;

    for (int t = 0; t < 20; t++) {
        float pg0 = 0.f, pg1 = 0.f, pg2 = 0.f;
        if (tid < nel) {
            int i = tid >> 7, jj = tid & 127;
            const float* gir = g_gi + ((size_t)(seq0 + i) * 20 + t) * H3;
            pg0 = gir[jj]; pg1 = gir[128 + jj]; pg2 = gir[256 + jj];
        }
        // phase 1: 64-wide partial dot with packed fp32x2 FMA (2 MACs/instr)
        unsigned long long a0[SEQPB], a1[SEQPB];
#pragma unroll
        for (int i = 0; i < SEQPB; i++) { a0[i] = 0ull; a1[i] = 0ull; }
#pragma unroll 8
        for (int kq = 0; kq < 16; kq++) {
            ulonglong2 w = w8[kq];
#pragma unroll
            for (int i = 0; i < SEQPB; i++) {
                ulonglong2 h = *(const ulonglong2*)(&hsh[i*128 + half*64 + kq*4]);
                ffma2(a0[i], w.x, h.x);
                ffma2(a1[i], w.y, h.y);
            }
        }
#pragma unroll
        for (int i = 0; i < SEQPB; i++)
            ghp[i*H3 + j] = bh + f32x2_sum(a0[i]) + f32x2_sum(a1[i]);
        __syncthreads();
        if (tid < nel) {
            int i = tid >> 7, jj = tid & 127;
            float ghr = gh0[i*H3 + jj]       + gh1[i*H3 + jj];
            float ghz = gh0[i*H3 + 128 + jj] + gh1[i*H3 + 128 + jj];
            float ghn = gh0[i*H3 + 256 + jj] + gh1[i*H3 + 256 + jj];
            float r = fsig(pg0 + ghr);
            float z = fsig(pg1 + ghz);
            float n = ftanh(pg2 + r * ghn);
            float hprev = hsh[i*128 + jj];
            float h = (1.f - z) * n + z * hprev;
            hsh[i*128 + jj] = h;
            g_hs[((size_t)(seq0 + i) * 20 + t) * HH + jj] = h;
        }
        __syncthreads();
    }
}

// ---------------- 4a. per-(b,s) attention: scores max + wsess session emb ----------------
__global__ void __launch_bounds__(256) k_attn1(const int* __restrict__ users,
                                               const float* __restrict__ uemb) {
    __shared__ float Qt[HH*TT];
    __shared__ float Et[HH*LL];
    __shared__ float Fsh[LL*HH];
    __shared__ float ue[HH];
    __shared__ float Scp[200*4];
    __shared__ float Sc[TT*LL];
    __shared__ float dl[LL];
    __shared__ float wsm[LL];

    int bs = blockIdx.x;
    int b = bs / SS;
    int tid = threadIdx.x;

    const float* qsrc = g_hs + (size_t)(b*TT) * HH;
    const float* esrc = g_hs + (size_t)(CURROWS + bs*LL) * HH;
    const float* F    = g_x  + (size_t)(CURROWS + bs*LL) * HH;
    for (int i = tid; i < TT*HH; i += 256) {
        int t = i >> 7, k = i & 127;
        Qt[k*TT + t] = qsrc[i];
        Et[k*LL + t] = esrc[i];
        Fsh[i] = F[i];
    }
    if (tid < HH) ue[tid] = uemb[(size_t)users[b]*HH + tid];
    __syncthreads();

    if (tid < 200) {
        int kh = tid / 100, tile = tid % 100;
        int a = tile / 10, bb2 = tile % 10;
        float a00 = 0.f, a01 = 0.f, a10 = 0.f, a11 = 0.f;
        int k0 = kh * 64;
#pragma unroll 8
        for (int k = k0; k < k0 + 64; k++) {
            float q0 = Qt[k*TT + 2*a], q1 = Qt[k*TT + 2*a + 1];
            float e0 = Et[k*LL + 2*bb2], e1 = Et[k*LL + 2*bb2 + 1];
            a00 += q0*e0; a01 += q0*e1; a10 += q1*e0; a11 += q1*e1;
        }
        Scp[tid*4+0] = a00; Scp[tid*4+1] = a01; Scp[tid*4+2] = a10; Scp[tid*4+3] = a11;
    } else if (tid < 220) {
        int l = tid - 200;
        float p = 0.f;
#pragma unroll 8
        for (int k = 0; k < HH; k++) p += ue[k] * Fsh[l*HH + k];
        dl[l] = p;
    }
    __syncthreads();

    if (tid < 100) {
        int a = tid / 10, bb2 = tid % 10;
        Sc[(2*a)*LL   + 2*bb2  ] = Scp[tid*4+0] + Scp[(tid+100)*4+0];
        Sc[(2*a)*LL   + 2*bb2+1] = Scp[tid*4+1] + Scp[(tid+100)*4+1];
        Sc[(2*a+1)*LL + 2*bb2  ] = Scp[tid*4+2] + Scp[(tid+100)*4+2];
        Sc[(2*a+1)*LL + 2*bb2+1] = Scp[tid*4+3] + Scp[(tid+100)*4+3];
    }
    if (tid == 128) {
        float mx = -INFINITY;
        for (int l = 0; l < LL; l++) mx = fmaxf(mx, dl[l]);
        float sum = 0.f;
        for (int l = 0; l < LL; l++) { wsm[l] = expf(dl[l]-mx); sum += wsm[l]; }
        float inv = 1.f / sum;
        for (int l = 0; l < LL; l++) wsm[l] *= inv;
    }
    __syncthreads();

    if (tid < TT) {
        float mx = -INFINITY;
        for (int l = 0; l < LL; l++) mx = fmaxf(mx, Sc[tid*LL + l]);
        g_simA[(size_t)bs*TT + tid] = mx;
    }
    if (tid < 128) {
        float acc = 0.f;
#pragma unroll
        for (int l = 0; l < LL; l++) acc += wsm[l] * Fsh[l*HH + tid];
        g_sessG[(size_t)bs*HH + tid] = acc;
    }
}

// ---------------- 4b. per-b combine -> fp16 A plane ----------------
__global__ void __launch_bounds__(256) k_attn2() {
    __shared__ float simA[SS*TT];
    __shared__ float sess[SS][HH];
    __shared__ float sfin[SS*TT];
    __shared__ int   presS[SS];
    int b = blockIdx.x;
    int tid = threadIdx.x;

    if (tid < SS) presS[tid] = 0;
    for (int i = tid; i < SS*TT; i += 256) simA[i] = g_simA[(size_t)b*SS*TT + i];
    for (int i = tid; i < SS*HH; i += 256) sess[i >> 7][i & 127] = g_sessG[(size_t)(b*SS)*HH + i];
    __syncthreads();

    float v[SS];
    if (tid < TT) {
        float mx = -INFINITY;
#pragma unroll
        for (int s = 0; s < SS; s++) { v[s] = simA[s*TT + tid]; mx = fmaxf(mx, v[s]); }
        float sum = 0.f;
#pragma unroll
        for (int s = 0; s < SS; s++) { v[s] = expf(v[s]-mx); sum += v[s]; }
        float inv = 1.f / sum;
#pragma unroll
        for (int s = 0; s < SS; s++) v[s] *= inv;
        int i1 = 0; float b1 = v[0];
#pragma unroll
        for (int s = 1; s < SS; s++) if (v[s] > b1) { b1 = v[s]; i1 = s; }
        int i2 = -1; float b2 = -INFINITY;
#pragma unroll
        for (int s = 0; s < SS; s++) if (s != i1 && v[s] > b2) { b2 = v[s]; i2 = s; }
        atomicOr(&presS[i1], 1);
        atomicOr(&presS[i2], 1);
    }
    __syncthreads();
    if (tid < TT) {
        int m[SS];
#pragma unroll
        for (int s = 0; s < SS; s++) m[s] = presS[s];
        float mx = -INFINITY;
#pragma unroll
        for (int s = 0; s < SS; s++) if (m[s]) mx = fmaxf(mx, v[s]);
        float sum = 0.f; float p[SS];
#pragma unroll
        for (int s = 0; s < SS; s++) { p[s] = m[s] ? expf(v[s]-mx) : 0.f; sum += p[s]; }
        float inv = 1.f / sum;
#pragma unroll
        for (int s = 0; s < SS; s++) p[s] *= inv;
        mx = -INFINITY;
#pragma unroll
        for (int s = 0; s < SS; s++) if (m[s]) mx = fmaxf(mx, p[s]);
        sum = 0.f; float q[SS];
#pragma unroll
        for (int s = 0; s < SS; s++) { q[s] = m[s] ? expf(p[s]-mx) : 0.f; sum += q[s]; }
        inv = 1.f / sum;
#pragma unroll
        for (int s = 0; s < SS; s++) sfin[s*TT + tid] = m[s] ? q[s]*inv : 0.f;
    }
    __syncthreads();

    for (int i = tid; i < TT*HH; i += 256) {
        int t = i >> 7, h = i & 127;
        float hf = 0.f;
#pragma unroll
        for (int s = 0; s < SS; s++) hf += sfin[s*TT + t] * sess[s][h];
        size_t row = (size_t)(b*TT) + t;
        float hs_v = g_hs[row*HH + h];
        g_ahi[row*256 + h]       = __float2half_rn(hs_v);
        g_ahi[row*256 + 128 + h] = __float2half_rn(hf);
    }
}

// ---------------- 5. fp16 single-pass mma.sync logits GEMM ----------------
#define SM_A       1024                   // 3 x 32KB ring stages
#define SM_BHI     99328                  // 4 blocks x 16KB (fp16 B, ends 164864)
#define SM_TOTAL   164864

__device__ __forceinline__ void prefetch_stage(int g, uint32_t sbase, int tid) {
    int mt = g >> 1, kpair = g & 1;
    const char* src = (const char*)g_ahi + (size_t)(mt*128)*512 + kpair*256;
    uint32_t dst = sbase + SM_A + (g % 3) * 32768;
#pragma unroll
    for (int q = 0; q < 8; q++) {
        int i = tid + q*256;
        int row = i >> 4, j = i & 15;
        int sub = j >> 3, jj = j & 7;
        cpasync16(dst + sub*16384 + SWZ((uint32_t)(row*128 + jj*16)),
                  src + (size_t)row*512 + j*16);
    }
}

__global__ void __launch_bounds__(256, 1) k_out_mma(const float* __restrict__ Wo,
                                                    const float* __restrict__ bo,
                                                    float* __restrict__ out) {
    extern __shared__ char smem[];
    uint32_t sbase = smem_u32(smem);
    int tid = threadIdx.x, lane = tid & 31, wid = tid >> 5;
    int wm = wid & 3, wn = wid >> 2;
    int n0 = blockIdx.x * 128;
    float* bsh = (float*)smem;

    if (tid < 128) bsh[tid] = (n0 + tid < NITEMS) ? bo[n0 + tid] : 0.f;

    prefetch_stage(0, sbase, tid);
    CP_COMMIT();

    // resident B: fp16 single plane of Wo (skip hu block)
    for (int i = tid; i < 128*32; i += 256) {
        int n = i >> 5, j = i & 31;
        int ng = n0 + n;
        uint4 hv = make_uint4(0,0,0,0);
        if (ng < NITEMS) {
            int k0 = j * 8;
            int ks = (k0 < 128) ? k0 : k0 + 128;
            hv = cvt8h(Wo + (size_t)ng*H3 + ks);
        }
        int kc = j >> 3, jj = j & 7;
        *(uint4*)(smem + SM_BHI + kc*16384 + SWZ((uint32_t)(n*128 + jj*16))) = hv;
    }
    __syncthreads();

    int arow = wm*32 + (lane & 15);
    uint32_t asel = (uint32_t)((lane >> 4) * 16);
    int bg = lane >> 3, br = lane & 7;
    int bnrow = wn*64 + ((bg >> 1) << 3) + br;
    uint32_t bkb = (uint32_t)((bg & 1) * 16);

    float acc[2][8][4];
    for (int g = 0; g < 20; g++) {
        int mt = g >> 1, st = g & 1;
        if (st == 0) {
#pragma unroll
            for (int u = 0; u < 2; u++)
#pragma unroll
                for (int v = 0; v < 8; v++)
#pragma unroll
                    for (int q = 0; q < 4; q++) acc[u][v][q] = 0.f;
        }
        if (g + 1 < 20) {
            prefetch_stage(g + 1, sbase, tid);
            CP_COMMIT();
            CP_WAIT1();
        } else {
            CP_WAIT0();
        }
        __syncthreads();

        uint32_t stbuf = sbase + SM_A + (g % 3) * 32768;
#pragma unroll
        for (int sub = 0; sub < 2; sub++) {
            int kc = st*2 + sub;
            uint32_t ab = stbuf + sub*16384;
            uint32_t bb = sbase + SM_BHI + kc*16384;
#pragma unroll
            for (int s = 0; s < 4; s++) {
                uint32_t A0[4], A1[4];
                ldsm4(A0[0], A0[1], A0[2], A0[3], ab + SWZ((uint32_t)(arow*128      + s*32) + asel));
                ldsm4(A1[0], A1[1], A1[2], A1[3], ab + SWZ((uint32_t)((arow+16)*128 + s*32) + asel));
                uint32_t Bf[8][2];
#pragma unroll
                for (int nfp = 0; nfp < 4; nfp++) {
                    uint32_t b0, b1, b2, b3;
                    ldsm4(b0, b1, b2, b3, bb + SWZ((uint32_t)((bnrow + nfp*16)*128 + s*32) + bkb));
                    Bf[2*nfp][0] = b0;   Bf[2*nfp][1] = b1;
                    Bf[2*nfp+1][0] = b2; Bf[2*nfp+1][1] = b3;
                }
#pragma unroll
                for (int nf = 0; nf < 8; nf++) {
                    mma16816h(acc[0][nf], A0, Bf[nf][0], Bf[nf][1]);
                    mma16816h(acc[1][nf], A1, Bf[nf][0], Bf[nf][1]);
                }
            }
        }

        if (st == 1) {
            int rbase = mt*128 + wm*32 + (lane >> 2);
            int cq = (lane & 3) * 2;
#pragma unroll
            for (int mf = 0; mf < 2; mf++) {
                int rr = rbase + mf*16;
#pragma unroll
                for (int nf = 0; nf < 8; nf++) {
                    int cl = wn*64 + nf*8 + cq;
                    int cc = n0 + cl;
                    if (cc < NITEMS) {
                        float2 v0, v1;
                        v0.x = acc[mf][nf][0] + bsh[cl];
                        v0.y = acc[mf][nf][1] + bsh[cl+1];
                        v1.x = acc[mf][nf][2] + bsh[cl];
                        v1.y = acc[mf][nf][3] + bsh[cl+1];
                        *(float2*)(out + (size_t)rr*NITEMS + cc)     = v0;
                        *(float2*)(out + (size_t)(rr+8)*NITEMS + cc) = v1;
                    }
                }
            }
        }
    }
}

// ---------------- launch ----------------
extern "C" void kernel_launch(void* const* d_in, const int* in_sizes, int n_in,
                              void* d_out, int out_size) {
    (void)in_sizes; (void)n_in; (void)out_size;
    const int*   users = (const int*)d_in[0];
    const int*   cur   = (const int*)d_in[1];
    const int*   frds  = (const int*)d_in[3];
    const float* vemb  = (const float*)d_in[5];
    const float* uemb  = (const float*)d_in[6];
    const float* Wih   = (const float*)d_in[7];
    const float* Whh   = (const float*)d_in[8];
    const float* bih   = (const float*)d_in[9];
    const float* bhh   = (const float*)d_in[10];
    const float* Wo    = (const float*)d_in[11];
    const float* bo    = (const float*)d_in[12];
    float* out = (float*)d_out;

    k_gather<<<(NROWS*HH)/256, 256>>>(cur, frds, vemb);

    cudaFuncSetAttribute(k_gi_mma, cudaFuncAttributeMaxDynamicSharedMemorySize, GI_TOTAL);
    k_gi_mma<<<dim3(3, NROWS/128), 256, GI_TOTAL>>>(Wih, bih);

    const int gru_smem = (384*132 + SEQPB*128 + 2*SEQPB*H3) * (int)sizeof(float);
    cudaFuncSetAttribute(k_gru, cudaFuncAttributeMaxDynamicSharedMemorySize, gru_smem);
    k_gru<<<(NSEQ + SEQPB - 1)/SEQPB, 768, gru_smem>>>(Whh, bhh);

    k_attn1<<<BB*SS, 256>>>(users, uemb);
    k_attn2<<<BB, 256>>>();

    cudaFuncSetAttribute(k_out_mma, cudaFuncAttributeMaxDynamicSharedMemorySize, SM_TOTAL);
    k_out_mma<<<(NITEMS + 127)/128, 256, SM_TOTAL>>>(Wo, bo, out);
}